// round 9
// baseline (speedup 1.0000x reference)
#include <cuda_runtime.h>
#include <cuda_bf16.h>
#include <cstdint>

// ---------------------------------------------------------------------------
// Problem constants
// ---------------------------------------------------------------------------
#define BSZ  32
#define CC   1536
#define CI   768
#define HH   14
#define WW   14
#define HJ   28
#define WJ   28
#define NN   784
#define MM   196
#define MMP  224          // MM padded to multiple of 32
#define CTPG 2304

// ---------------------------------------------------------------------------
// Scratch (device globals)
// ---------------------------------------------------------------------------
__device__ __align__(16) __nv_bfloat16 g_xhT[(size_t)BSZ * NN * CC];
__device__ __align__(16) __nv_bfloat16 g_xlT[(size_t)BSZ * NN * CC];
__device__ float g_tpg [(size_t)BSZ * CTPG * NN];   // only phi/g rows written now
__device__ __align__(16) __nv_bfloat16 g_thh[(size_t)BSZ * NN * CI];
__device__ __align__(16) __nv_bfloat16 g_thl[(size_t)BSZ * NN * CI];
__device__ float g_phi [(size_t)BSZ * CI * MM];
__device__ __align__(16) __nv_bfloat16 g_phh[(size_t)BSZ * MM * CI];
__device__ __align__(16) __nv_bfloat16 g_phl[(size_t)BSZ * MM * CI];
__device__ __align__(16) __nv_bfloat16 g_gph[(size_t)BSZ * CI * MMP];
__device__ __align__(16) __nv_bfloat16 g_gpl[(size_t)BSZ * CI * MMP];
__device__ float g_f   [(size_t)BSZ * NN * MM];
__device__ __align__(16) __nv_bfloat16 g_ath[(size_t)BSZ * NN * MMP];
__device__ __align__(16) __nv_bfloat16 g_atl[(size_t)BSZ * NN * MMP];
__device__ __align__(16) __nv_bfloat16 g_yhT[(size_t)BSZ * NN * CI];
__device__ __align__(16) __nv_bfloat16 g_ylT[(size_t)BSZ * NN * CI];
__device__ __align__(16) __nv_bfloat16 g_whi[(size_t)CTPG * CC];
__device__ __align__(16) __nv_bfloat16 g_wlo[(size_t)CTPG * CC];
__device__ __align__(16) __nv_bfloat16 g_wWhi[(size_t)CC * CI];
__device__ __align__(16) __nv_bfloat16 g_wWlo[(size_t)CC * CI];
__device__ float g_bstk[CTPG];
__device__ float g_escale[CC];
__device__ float g_eshift[CC];

// ---------------------------------------------------------------------------
// PTX helpers (base ISA only — harness's ptxas targets plain sm_103)
// ---------------------------------------------------------------------------
__device__ __forceinline__ uint32_t smem_u32(const void* p) {
    uint32_t a;
    asm("{ .reg .u64 t; cvta.to.shared.u64 t, %1; cvt.u32.u64 %0, t; }" : "=r"(a) : "l"(p));
    return a;
}
__device__ __forceinline__ void ldm_x4(uint32_t* r, uint32_t addr) {
    asm volatile("ldmatrix.sync.aligned.m8n8.x4.shared.b16 {%0,%1,%2,%3}, [%4];"
                 : "=r"(r[0]), "=r"(r[1]), "=r"(r[2]), "=r"(r[3]) : "r"(addr));
}
__device__ __forceinline__ void mma16816(float* d, const uint32_t* a, uint32_t b0, uint32_t b1) {
    asm volatile("mma.sync.aligned.m16n8k16.row.col.f32.bf16.bf16.f32 "
                 "{%0,%1,%2,%3}, {%4,%5,%6,%7}, {%8,%9}, {%0,%1,%2,%3};"
                 : "+f"(d[0]), "+f"(d[1]), "+f"(d[2]), "+f"(d[3])
                 : "r"(a[0]), "r"(a[1]), "r"(a[2]), "r"(a[3]), "r"(b0), "r"(b1));
}
__device__ __forceinline__ void cpa16(uint32_t dst, const void* src, int srcsz) {
    asm volatile("cp.async.cg.shared.global [%0], [%1], 16, %2;"
                 :: "r"(dst), "l"(src), "r"(srcsz));
}
#define CPA_COMMIT()  asm volatile("cp.async.commit_group;" ::: "memory")
#define CPA_WAIT(n)   asm volatile("cp.async.wait_group %0;" :: "n"(n) : "memory")

// ---------------------------------------------------------------------------
// fused joint-gather + transpose + bf16 hi/lo split: x -> xjT [b][n][c]
// ---------------------------------------------------------------------------
__global__ void tsplitX_kernel(const float* __restrict__ x) {
    __shared__ float t[32][33];
    int b = blockIdx.z;
    int c0 = blockIdx.y * 32, n0 = blockIdx.x * 32;
    int tx = threadIdx.x, ty = threadIdx.y;
#pragma unroll
    for (int s = 0; s < 32; s += 8) {
        int c = c0 + ty + s, n = n0 + tx;
        float v = 0.f;
        if (n < NN) {
            int hj = n / WJ, wj = n % WJ;
            int vv = ((hj >= HH) ? 2 : 0) + ((wj >= WW) ? 1 : 0);
            int hl = (hj >= HH) ? hj - HH : hj;
            int wl = (wj >= WW) ? wj - WW : wj;
            v = x[(((long)(b * 4 + vv) * CC + c) * HH + hl) * WW + wl];
        }
        t[ty + s][tx] = v;
    }
    __syncthreads();
    long ob = (long)b * NN * CC;
#pragma unroll
    for (int s = 0; s < 32; s += 8) {
        int n = n0 + ty + s, c = c0 + tx;
        if (n < NN) {
            float v = t[tx][ty + s];
            __nv_bfloat16 h = __float2bfloat16(v);
            g_xhT[ob + (long)n * CC + c] = h;
            g_xlT[ob + (long)n * CC + c] = __float2bfloat16(v - __bfloat162float(h));
        }
    }
}

// ---------------------------------------------------------------------------
// generic tiled transpose + bf16 hi/lo split (phi only now)
// ---------------------------------------------------------------------------
__global__ void tsplit_kernel(const float* __restrict__ in,
                              __nv_bfloat16* __restrict__ hi,
                              __nv_bfloat16* __restrict__ lo,
                              int R, int Cn, long inStride) {
    __shared__ float t[32][33];
    int b = blockIdx.z;
    int r0 = blockIdx.y * 32, c0 = blockIdx.x * 32;
    const float* ib = in + (long)b * inStride;
    int tx = threadIdx.x, ty = threadIdx.y;
#pragma unroll
    for (int s = 0; s < 32; s += 8) {
        int r = r0 + ty + s, c = c0 + tx;
        t[ty + s][tx] = (r < R && c < Cn) ? ib[(long)r * Cn + c] : 0.f;
    }
    __syncthreads();
    long ob = (long)b * Cn * R;
#pragma unroll
    for (int s = 0; s < 32; s += 8) {
        int c = c0 + ty + s, r = r0 + tx;
        if (c < Cn && r < R) {
            float v = t[tx][ty + s];
            __nv_bfloat16 h = __float2bfloat16(v);
            hi[ob + (long)c * R + r] = h;
            lo[ob + (long)c * R + r] = __float2bfloat16(v - __bfloat162float(h));
        }
    }
}

// ---------------------------------------------------------------------------
// weight prep
// ---------------------------------------------------------------------------
__global__ void wsplit_stack_kernel(const float* __restrict__ wt, const float* __restrict__ wp,
                                    const float* __restrict__ wg, const float* __restrict__ bt,
                                    const float* __restrict__ bp, const float* __restrict__ bg) {
    long idx = (long)blockIdx.x * blockDim.x + threadIdx.x;
    if (idx < (long)CTPG * CC) {
        int r = (int)(idx / CC), c = (int)(idx % CC);
        const float* src = (r < CI) ? wt : ((r < 2 * CI) ? wp : wg);
        int rr = (r < CI) ? r : ((r < 2 * CI) ? r - CI : r - 2 * CI);
        float v = src[(long)rr * CC + c];
        __nv_bfloat16 h = __float2bfloat16(v);
        g_whi[idx] = h;
        g_wlo[idx] = __float2bfloat16(v - __bfloat162float(h));
    }
    if (idx < CTPG) {
        int r = (int)idx;
        g_bstk[r] = (r < CI) ? bt[r] : ((r < 2 * CI) ? bp[r - CI] : bg[r - 2 * CI]);
    }
}

__global__ void wsplitW_kernel(const float* __restrict__ wW) {
    long idx = (long)blockIdx.x * blockDim.x + threadIdx.x;
    if (idx >= (long)CC * CI) return;
    float v = wW[idx];
    __nv_bfloat16 h = __float2bfloat16(v);
    g_wWhi[idx] = h;
    g_wWlo[idx] = __float2bfloat16(v - __bfloat162float(h));
}

__global__ void bnprep_kernel(const float* __restrict__ gamma, const float* __restrict__ beta,
                              const float* __restrict__ mean, const float* __restrict__ var,
                              const float* __restrict__ bW) {
    int m = blockIdx.x * blockDim.x + threadIdx.x;
    if (m < CC) {
        float s = gamma[m] * rsqrtf(var[m] + 1e-5f);
        g_escale[m] = s;
        g_eshift[m] = beta[m] - mean[m] * s + bW[m] * s;
    }
}

// ---------------------------------------------------------------------------
// 2x2 maxpool: phi -> fp32 [c][196]; g -> bf16 hi/lo [c][224] padded
// ---------------------------------------------------------------------------
__global__ void pool_kernel() {
    int idx = blockIdx.x * blockDim.x + threadIdx.x;
    const int totPhi = BSZ * CI * MM;
    const int totG = BSZ * CI * MMP;
    if (idx < totPhi) {
        int m = idx % MM;
        int c = (idx / MM) % CI;
        int b = idx / (MM * CI);
        int hm = m / 14, wm = m % 14;
        const float* src = g_tpg + ((long)b * CTPG + CI + c) * NN;
        int base = (2 * hm) * WJ + 2 * wm;
        g_phi[idx] = fmaxf(fmaxf(src[base], src[base + 1]),
                           fmaxf(src[base + WJ], src[base + WJ + 1]));
    } else if (idx < totPhi + totG) {
        int r = idx - totPhi;
        int j = r % MMP;
        int c = (r / MMP) % CI;
        int b = r / (MMP * CI);
        float v = 0.f;
        if (j < MM) {
            int hm = j / 14, wm = j % 14;
            const float* src = g_tpg + ((long)b * CTPG + 2 * CI + c) * NN;
            int base = (2 * hm) * WJ + 2 * wm;
            v = fmaxf(fmaxf(src[base], src[base + 1]),
                      fmaxf(src[base + WJ], src[base + WJ + 1]));
        }
        __nv_bfloat16 h = __float2bfloat16(v);
        g_gph[r] = h;
        g_gpl[r] = (j < MM) ? __float2bfloat16(v - __bfloat162float(h)) : __nv_bfloat16(0.f);
    }
}

// ---------------------------------------------------------------------------
// row softmax over MM=196 -> attn hi/lo bf16 padded [n][224]
// ---------------------------------------------------------------------------
__global__ void softmax_kernel() {
    int warp = (blockIdx.x * blockDim.x + threadIdx.x) >> 5;
    int lane = threadIdx.x & 31;
    if (warp >= BSZ * NN) return;
    const float* row = g_f + (long)warp * MM;
    __nv_bfloat16* oh = g_ath + (long)warp * MMP;
    __nv_bfloat16* ol = g_atl + (long)warp * MMP;
    float vals[7];
    float mx = -1e30f;
#pragma unroll
    for (int s = 0; s < 7; s++) {
        int i = lane + s * 32;
        vals[s] = (i < MM) ? row[i] : -1e30f;
        mx = fmaxf(mx, vals[s]);
    }
#pragma unroll
    for (int o = 16; o; o >>= 1) mx = fmaxf(mx, __shfl_xor_sync(0xffffffffu, mx, o));
    float sum = 0.f;
#pragma unroll
    for (int s = 0; s < 7; s++) {
        int i = lane + s * 32;
        vals[s] = (i < MM) ? __expf(vals[s] - mx) : 0.f;
        sum += vals[s];
    }
#pragma unroll
    for (int o = 16; o; o >>= 1) sum += __shfl_xor_sync(0xffffffffu, sum, o);
    float inv = 1.f / sum;
#pragma unroll
    for (int s = 0; s < 7; s++) {
        int i = lane + s * 32;   // 0..223 == MMP
        float v = vals[s] * inv;
        __nv_bfloat16 h = __float2bfloat16(v);
        oh[i] = h;
        ol[i] = __float2bfloat16(v - __bfloat162float(h));
    }
}

// ---------------------------------------------------------------------------
// fused-pass bf16-split tensor GEMM (mma.sync m16n8k16).
//   128x128 CTA tile, 256 threads, 2 CTAs/SM, 3-stage cp.async pipeline,
//   swizzled 64B-row smem tiles, single __syncthreads per K-chunk.
//   Per K-chunk: load Ahi/Alo/Bhi/Blo once; mma hi*hi + hi*lo + lo*hi.
//   EPI 0: plain fp32
//   EPI 1: GEMM1 — theta tiles (m0<CI): transposed bf16 hi/lo +bias;
//                  phi/g tiles: fp32 +bias
//   EPI 2: BN-fold + residual joint(x)
//   EPI 3: transposed bf16 hi/lo (no bias)
// ---------------------------------------------------------------------------
#define GTILE (128 * 32)            // bf16 elems per tile (128 rows x 64B)
#define ST    (4 * GTILE)           // per-stage: [Ahi | Bhi | Alo | Blo]
#define SMEM3 (3 * ST * 2)          // 98304 B

// swizzled element offset within a tile: row-major 64B rows, 16B segs XORed
__device__ __forceinline__ int swz(int row, int seg) {
    return row * 32 + ((seg ^ ((row >> 1) & 3)) << 3);
}

template <int EPI>
__global__ void __launch_bounds__(256, 2)
mma128_kernel(const __nv_bfloat16* __restrict__ Ahi, const __nv_bfloat16* __restrict__ Alo,
              const __nv_bfloat16* __restrict__ Bhi, const __nv_bfloat16* __restrict__ Blo,
              float* __restrict__ Cp, int K, int MV, int NB,
              long strideA, long strideB, int ldC, long sC,
              const float* __restrict__ xres,
              __nv_bfloat16* __restrict__ Thi, __nv_bfloat16* __restrict__ Tlo, int ldT) {
    extern __shared__ __align__(16) __nv_bfloat16 smem[];

    const int tid = threadIdx.x;
    const int lane = tid & 31;
    const int wid = tid >> 5;
    const int wm = wid & 1;          // 2 M-warps -> 64 rows
    const int wn = wid >> 1;         // 4 N-warps -> 32 cols
    const int m0 = blockIdx.y * 128;
    const int n0 = blockIdx.x * 128;
    const int b  = blockIdx.z;

    const int NK = K / 32;
    const __nv_bfloat16* A0 = Ahi + (long)b * strideA + (long)m0 * K;
    const __nv_bfloat16* A1 = Alo + (long)b * strideA + (long)m0 * K;
    const __nv_bfloat16* B0 = Bhi + (long)b * strideB;
    const __nv_bfloat16* B1 = Blo + (long)b * strideB;

    float acc[4][4][4];
#pragma unroll
    for (int i = 0; i < 4; i++)
#pragma unroll
        for (int j = 0; j < 4; j++)
#pragma unroll
            for (int r = 0; r < 4; r++) acc[i][j][r] = 0.f;

    auto loadChunk = [&](int g, int stage) {
        long kc = (long)g * 32;
        __nv_bfloat16* st = smem + stage * ST;
#pragma unroll
        for (int i = 0; i < 2; i++) {
            int idx = tid + i * 256;
            int row = idx >> 2, seg = idx & 3;
            int off = swz(row, seg);
            long ga = (long)row * K + kc + seg * 8;
            int okA = (m0 + row) < MV;
            int okB = (n0 + row) < NB;
            long gb = (long)(okB ? (n0 + row) : 0) * K + kc + seg * 8;
            cpa16(smem_u32(st + off), A0 + ga, okA ? 16 : 0);
            cpa16(smem_u32(st + GTILE + off), B0 + gb, okB ? 16 : 0);
            cpa16(smem_u32(st + 2 * GTILE + off), A1 + ga, okA ? 16 : 0);
            cpa16(smem_u32(st + 3 * GTILE + off), B1 + gb, okB ? 16 : 0);
        }
    };

    loadChunk(0, 0); CPA_COMMIT();
    loadChunk(1, 1); CPA_COMMIT();

    int cs = 0;   // compute stage
    int ls = 2;   // next load stage
    for (int g = 0; g < NK; g++) {
        if (g + 1 < NK) { CPA_WAIT(1); } else { CPA_WAIT(0); }
        __syncthreads();
        if (g + 2 < NK) {
            loadChunk(g + 2, ls);
            CPA_COMMIT();
            ls = (ls == 2) ? 0 : ls + 1;
        }
        const __nv_bfloat16* st = smem + cs * ST;
        cs = (cs == 2) ? 0 : cs + 1;

#pragma unroll
        for (int ks = 0; ks < 2; ks++) {
            const int aRow = wm * 64 + ((lane >> 3) & 1) * 8 + (lane & 7);
            const int aSeg = ks * 2 + (lane >> 4);
            const int bRow = wn * 32 + (lane >> 4) * 8 + (lane & 7);
            const int bSeg = ks * 2 + ((lane >> 3) & 1);

            uint32_t bh[2][4];
#pragma unroll
            for (int ni = 0; ni < 2; ni++)
                ldm_x4(bh[ni], smem_u32(st + GTILE + swz(bRow + ni * 16, bSeg)));

            uint32_t a[4][4];
#pragma unroll
            for (int mi = 0; mi < 4; mi++)
                ldm_x4(a[mi], smem_u32(st + swz(aRow + mi * 16, aSeg)));

            // hi * hi
#pragma unroll
            for (int mi = 0; mi < 4; mi++)
#pragma unroll
                for (int nj = 0; nj < 4; nj++)
                    mma16816(acc[mi][nj], a[mi],
                             bh[nj >> 1][(nj & 1) * 2], bh[nj >> 1][(nj & 1) * 2 + 1]);

            // hi * lo
            uint32_t bl[2][4];
#pragma unroll
            for (int ni = 0; ni < 2; ni++)
                ldm_x4(bl[ni], smem_u32(st + 3 * GTILE + swz(bRow + ni * 16, bSeg)));
#pragma unroll
            for (int mi = 0; mi < 4; mi++)
#pragma unroll
                for (int nj = 0; nj < 4; nj++)
                    mma16816(acc[mi][nj], a[mi],
                             bl[nj >> 1][(nj & 1) * 2], bl[nj >> 1][(nj & 1) * 2 + 1]);

            // lo * hi (reuse a regs)
#pragma unroll
            for (int mi = 0; mi < 4; mi++)
                ldm_x4(a[mi], smem_u32(st + 2 * GTILE + swz(aRow + mi * 16, aSeg)));
#pragma unroll
            for (int mi = 0; mi < 4; mi++)
#pragma unroll
                for (int nj = 0; nj < 4; nj++)
                    mma16816(acc[mi][nj], a[mi],
                             bh[nj >> 1][(nj & 1) * 2], bh[nj >> 1][(nj & 1) * 2 + 1]);
        }
    }

    const bool transposed = (EPI == 3) || (EPI == 1 && m0 < CI);

    if (!transposed) {
        // ---- direct fp32 epilogue ----
        const int mbase = m0 + wm * 64;
        const int nbase = n0 + wn * 32;
        float* Cb = Cp + (long)b * sC;
#pragma unroll
        for (int mi = 0; mi < 4; mi++) {
            int mr0 = mbase + mi * 16 + (lane >> 2);
            int mr1 = mr0 + 8;
            bool ok0 = mr0 < MV, ok1 = mr1 < MV;
            float es0 = 1.f, eh0 = 0.f, es1 = 1.f, eh1 = 0.f;
            if (EPI == 1) { if (ok0) eh0 = g_bstk[mr0]; if (ok1) eh1 = g_bstk[mr1]; }
            if (EPI == 2) {
                if (ok0) { es0 = g_escale[mr0]; eh0 = g_eshift[mr0]; }
                if (ok1) { es1 = g_escale[mr1]; eh1 = g_eshift[mr1]; }
            }
#pragma unroll
            for (int nj = 0; nj < 4; nj++) {
                int n = nbase + nj * 8 + (lane & 3) * 2;
                if (n >= NB) continue;
                float2 v0 = make_float2(acc[mi][nj][0], acc[mi][nj][1]);
                float2 v1 = make_float2(acc[mi][nj][2], acc[mi][nj][3]);
                if (EPI == 2) {
                    int hj = n / WJ, wj0 = n - hj * WJ;
#pragma unroll
                    for (int e = 0; e < 2; e++) {
                        int wj = wj0 + e;
                        int vv = ((hj >= HH) ? 2 : 0) + ((wj >= WW) ? 1 : 0);
                        int hl = (hj >= HH) ? hj - HH : hj;
                        int wl = (wj >= WW) ? wj - WW : wj;
                        long base = (((long)(b * 4 + vv) * CC) * HH + hl) * WW + wl;
                        float r0 = ok0 ? xres[base + (long)mr0 * HH * WW] : 0.f;
                        float r1 = ok1 ? xres[base + (long)mr1 * HH * WW] : 0.f;
                        if (e == 0) { v0.x = v0.x * es0 + eh0 + r0; v1.x = v1.x * es1 + eh1 + r1; }
                        else        { v0.y = v0.y * es0 + eh0 + r0; v1.y = v1.y * es1 + eh1 + r1; }
                    }
                } else {
                    v0.x = v0.x * es0 + eh0; v0.y = v0.y * es0 + eh0;
                    v1.x = v1.x * es1 + eh1; v1.y = v1.y * es1 + eh1;
                }
                if (ok0) *(float2*)(Cb + (long)mr0 * ldC + n) = v0;
                if (ok1) *(float2*)(Cb + (long)mr1 * ldC + n) = v1;
            }
        }
    } else {
        // ---- transposed bf16 hi/lo epilogue via smem staging ----
        float* smf = reinterpret_cast<float*>(smem);   // [128][133] fp32
        __syncthreads();   // all warps done reading pipeline stages
#pragma unroll
        for (int mi = 0; mi < 4; mi++) {
            int ml0 = wm * 64 + mi * 16 + (lane >> 2);
            int ml1 = ml0 + 8;
            float eh0 = (EPI == 1) ? g_bstk[m0 + ml0] : 0.f;
            float eh1 = (EPI == 1) ? g_bstk[m0 + ml1] : 0.f;
#pragma unroll
            for (int nj = 0; nj < 4; nj++) {
                int nl = wn * 32 + nj * 8 + (lane & 3) * 2;
                smf[ml0 * 133 + nl]     = acc[mi][nj][0] + eh0;
                smf[ml0 * 133 + nl + 1] = acc[mi][nj][1] + eh0;
                smf[ml1 * 133 + nl]     = acc[mi][nj][2] + eh1;
                smf[ml1 * 133 + nl + 1] = acc[mi][nj][3] + eh1;
            }
        }
        __syncthreads();
        int nrow = tid >> 1;
        int mh = tid & 1;
        int ng = n0 + nrow;
        if (ng < NB) {
            long obase = ((long)b * NN + ng) * ldT + m0 + mh * 64;
            uint32_t* oh = (uint32_t*)(Thi + obase);
            uint32_t* ol = (uint32_t*)(Tlo + obase);
#pragma unroll
            for (int j = 0; j < 64; j += 2) {
                float v0 = smf[(mh * 64 + j) * 133 + nrow];
                float v1 = smf[(mh * 64 + j + 1) * 133 + nrow];
                __nv_bfloat16 h0 = __float2bfloat16(v0);
                __nv_bfloat16 h1 = __float2bfloat16(v1);
                __nv_bfloat16 l0 = __float2bfloat16(v0 - __bfloat162float(h0));
                __nv_bfloat16 l1 = __float2bfloat16(v1 - __bfloat162float(h1));
                uint16_t h0b = *(uint16_t*)&h0, h1b = *(uint16_t*)&h1;
                uint16_t l0b = *(uint16_t*)&l0, l1b = *(uint16_t*)&l1;
                oh[j >> 1] = (uint32_t)h0b | ((uint32_t)h1b << 16);
                ol[j >> 1] = (uint32_t)l0b | ((uint32_t)l1b << 16);
            }
        }
    }
}

// ---------------------------------------------------------------------------
// Launch
// ---------------------------------------------------------------------------
extern "C" void kernel_launch(void* const* d_in, const int* in_sizes, int n_in,
                              void* d_out, int out_size) {
    const float* x     = (const float*)d_in[0];
    const float* wt    = (const float*)d_in[1];
    const float* bt    = (const float*)d_in[2];
    const float* wp    = (const float*)d_in[3];
    const float* bp    = (const float*)d_in[4];
    const float* wg    = (const float*)d_in[5];
    const float* bg    = (const float*)d_in[6];
    const float* wW    = (const float*)d_in[7];
    const float* bW    = (const float*)d_in[8];
    const float* gamma = (const float*)d_in[9];
    const float* beta  = (const float*)d_in[10];
    const float* mean  = (const float*)d_in[11];
    const float* var   = (const float*)d_in[12];
    float* out = (float*)d_out;

    float *p_tpg, *p_phi, *p_f;
    __nv_bfloat16 *p_xhT, *p_xlT, *p_thh, *p_thl, *p_phh, *p_phl;
    __nv_bfloat16 *p_gph, *p_gpl, *p_ath, *p_atl, *p_yhT, *p_ylT;
    __nv_bfloat16 *p_whi, *p_wlo, *p_wWhi, *p_wWlo;
    cudaGetSymbolAddress((void**)&p_tpg, g_tpg);
    cudaGetSymbolAddress((void**)&p_phi, g_phi);
    cudaGetSymbolAddress((void**)&p_f, g_f);
    cudaGetSymbolAddress((void**)&p_xhT, g_xhT);
    cudaGetSymbolAddress((void**)&p_xlT, g_xlT);
    cudaGetSymbolAddress((void**)&p_thh, g_thh);
    cudaGetSymbolAddress((void**)&p_thl, g_thl);
    cudaGetSymbolAddress((void**)&p_phh, g_phh);
    cudaGetSymbolAddress((void**)&p_phl, g_phl);
    cudaGetSymbolAddress((void**)&p_gph, g_gph);
    cudaGetSymbolAddress((void**)&p_gpl, g_gpl);
    cudaGetSymbolAddress((void**)&p_ath, g_ath);
    cudaGetSymbolAddress((void**)&p_atl, g_atl);
    cudaGetSymbolAddress((void**)&p_yhT, g_yhT);
    cudaGetSymbolAddress((void**)&p_ylT, g_ylT);
    cudaGetSymbolAddress((void**)&p_whi, g_whi);
    cudaGetSymbolAddress((void**)&p_wlo, g_wlo);
    cudaGetSymbolAddress((void**)&p_wWhi, g_wWhi);
    cudaGetSymbolAddress((void**)&p_wWlo, g_wWlo);

    cudaFuncSetAttribute((const void*)mma128_kernel<0>,
                         cudaFuncAttributeMaxDynamicSharedMemorySize, SMEM3);
    cudaFuncSetAttribute((const void*)mma128_kernel<1>,
                         cudaFuncAttributeMaxDynamicSharedMemorySize, SMEM3);
    cudaFuncSetAttribute((const void*)mma128_kernel<2>,
                         cudaFuncAttributeMaxDynamicSharedMemorySize, SMEM3);
    cudaFuncSetAttribute((const void*)mma128_kernel<3>,
                         cudaFuncAttributeMaxDynamicSharedMemorySize, SMEM3);

    // #1 weight stack+split
    {
        long total = (long)CTPG * CC;
        wsplit_stack_kernel<<<(unsigned)((total + 255) / 256), 256>>>(wt, wp, wg, bt, bp, bg);
    }
    // #2 fused joint + transpose + split
    {
        dim3 grid((NN + 31) / 32, CC / 32, BSZ);
        tsplitX_kernel<<<grid, dim3(32, 8)>>>(x);
    }
    // #3 BN prep (keeps GEMM1 at launch #4 for ncu)
    bnprep_kernel<<<(CC + 255) / 256, 256>>>(gamma, beta, mean, var, bW);
    // #4 stacked theta|phi|g conv; theta tiles write theta^T hi/lo directly
    {
        mma128_kernel<1><<<dim3((NN + 127) / 128, CTPG / 128, BSZ), 256, SMEM3>>>(
            p_whi, p_wlo, p_xhT, p_xlT, p_tpg, CC, CTPG, NN,
            0L, (long)NN * CC, NN, (long)CTPG * NN, nullptr,
            p_thh, p_thl, CI);
    }
    // #5 W-conv weight split
    wsplitW_kernel<<<(unsigned)(((long)CC * CI + 255) / 256), 256>>>(wW);
    // #6 pool
    {
        int total = BSZ * CI * (MM + MMP);
        pool_kernel<<<(total + 255) / 256, 256>>>();
    }
    // #7 phi -> phi^T hi/lo
    {
        dim3 grid((MM + 31) / 32, CI / 32, BSZ);
        tsplit_kernel<<<grid, dim3(32, 8)>>>(p_phi, p_phh, p_phl, CI, MM, (long)CI * MM);
    }
    // #8 f = thetaT @ phiT^T
    {
        mma128_kernel<0><<<dim3((MM + 127) / 128, (NN + 127) / 128, BSZ), 256, SMEM3>>>(
            p_thh, p_thl, p_phh, p_phl, p_f, CI, NN, MM,
            (long)NN * CI, (long)MM * CI, MM, (long)NN * MM, nullptr,
            nullptr, nullptr, 0);
    }
    // #9 softmax -> attn hi/lo padded
    {
        int rows = BSZ * NN;
        softmax_kernel<<<(rows * 32 + 255) / 256, 256>>>();
    }
    // #10 y = g @ attn^T; writes y^T hi/lo directly (transposed epilogue)
    {
        mma128_kernel<3><<<dim3((NN + 127) / 128, CI / 128, BSZ), 256, SMEM3>>>(
            p_gph, p_gpl, p_ath, p_atl, nullptr, MMP, CI, NN,
            (long)CI * MMP, (long)NN * MMP, 0, 0L, nullptr,
            p_yhT, p_ylT, CI);
    }
    // #11 W conv (3-pass split) + BN + residual -> out
    {
        mma128_kernel<2><<<dim3((NN + 127) / 128, CC / 128, BSZ), 256, SMEM3>>>(
            p_wWhi, p_wWlo, p_yhT, p_ylT, out, CI, CC, NN,
            0L, (long)NN * CI, NN, (long)CC * NN, x,
            nullptr, nullptr, 0);
    }
}

// round 10
// speedup vs baseline: 1.0255x; 1.0255x over previous
#include <cuda_runtime.h>
#include <cuda_bf16.h>
#include <cstdint>

// ---------------------------------------------------------------------------
// Problem constants
// ---------------------------------------------------------------------------
#define BSZ  32
#define CC   1536
#define CI   768
#define HH   14
#define WW   14
#define HJ   28
#define WJ   28
#define NN   784
#define MM   196
#define MMP  224          // MM padded to multiple of 32
#define CTPG 2304

// ---------------------------------------------------------------------------
// Scratch (device globals)
// ---------------------------------------------------------------------------
__device__ __align__(16) __nv_bfloat16 g_xhT[(size_t)BSZ * NN * CC];
__device__ __align__(16) __nv_bfloat16 g_xlT[(size_t)BSZ * NN * CC];
__device__ float g_tpg [(size_t)BSZ * CTPG * NN];
__device__ __align__(16) __nv_bfloat16 g_thh[(size_t)BSZ * NN * CI];
__device__ __align__(16) __nv_bfloat16 g_thl[(size_t)BSZ * NN * CI];
__device__ float g_phi [(size_t)BSZ * CI * MM];
__device__ __align__(16) __nv_bfloat16 g_phh[(size_t)BSZ * MM * CI];
__device__ __align__(16) __nv_bfloat16 g_phl[(size_t)BSZ * MM * CI];
__device__ __align__(16) __nv_bfloat16 g_gph[(size_t)BSZ * CI * MMP];
__device__ __align__(16) __nv_bfloat16 g_gpl[(size_t)BSZ * CI * MMP];
__device__ float g_f   [(size_t)BSZ * NN * MM];
__device__ __align__(16) __nv_bfloat16 g_ath[(size_t)BSZ * NN * MMP];
__device__ __align__(16) __nv_bfloat16 g_atl[(size_t)BSZ * NN * MMP];
__device__ __align__(16) __nv_bfloat16 g_yhT[(size_t)BSZ * NN * CI];
__device__ __align__(16) __nv_bfloat16 g_ylT[(size_t)BSZ * NN * CI];
__device__ __align__(16) __nv_bfloat16 g_whi[(size_t)CTPG * CC];
__device__ __align__(16) __nv_bfloat16 g_wlo[(size_t)CTPG * CC];
__device__ __align__(16) __nv_bfloat16 g_wWhi[(size_t)CC * CI];
__device__ __align__(16) __nv_bfloat16 g_wWlo[(size_t)CC * CI];
__device__ float g_bstk[CTPG];
__device__ float g_escale[CC];
__device__ float g_eshift[CC];

// ---------------------------------------------------------------------------
// PTX helpers (base ISA only — harness's ptxas targets plain sm_103)
// ---------------------------------------------------------------------------
__device__ __forceinline__ uint32_t smem_u32(const void* p) {
    uint32_t a;
    asm("{ .reg .u64 t; cvta.to.shared.u64 t, %1; cvt.u32.u64 %0, t; }" : "=r"(a) : "l"(p));
    return a;
}
__device__ __forceinline__ void ldm_x4(uint32_t* r, uint32_t addr) {
    asm volatile("ldmatrix.sync.aligned.m8n8.x4.shared.b16 {%0,%1,%2,%3}, [%4];"
                 : "=r"(r[0]), "=r"(r[1]), "=r"(r[2]), "=r"(r[3]) : "r"(addr));
}
__device__ __forceinline__ void mma16816(float* d, const uint32_t* a, uint32_t b0, uint32_t b1) {
    asm volatile("mma.sync.aligned.m16n8k16.row.col.f32.bf16.bf16.f32 "
                 "{%0,%1,%2,%3}, {%4,%5,%6,%7}, {%8,%9}, {%0,%1,%2,%3};"
                 : "+f"(d[0]), "+f"(d[1]), "+f"(d[2]), "+f"(d[3])
                 : "r"(a[0]), "r"(a[1]), "r"(a[2]), "r"(a[3]), "r"(b0), "r"(b1));
}
__device__ __forceinline__ void cpa16(uint32_t dst, const void* src, int srcsz) {
    asm volatile("cp.async.cg.shared.global [%0], [%1], 16, %2;"
                 :: "r"(dst), "l"(src), "r"(srcsz));
}
#define CPA_COMMIT()  asm volatile("cp.async.commit_group;" ::: "memory")
#define CPA_WAIT(n)   asm volatile("cp.async.wait_group %0;" :: "n"(n) : "memory")

// ---------------------------------------------------------------------------
// fused joint-gather + transpose + bf16 hi/lo split: x -> xjT [b][n][c]
// ---------------------------------------------------------------------------
__global__ void tsplitX_kernel(const float* __restrict__ x) {
    __shared__ float t[32][33];
    int b = blockIdx.z;
    int c0 = blockIdx.y * 32, n0 = blockIdx.x * 32;
    int tx = threadIdx.x, ty = threadIdx.y;
#pragma unroll
    for (int s = 0; s < 32; s += 8) {
        int c = c0 + ty + s, n = n0 + tx;
        float v = 0.f;
        if (n < NN) {
            int hj = n / WJ, wj = n % WJ;
            int vv = ((hj >= HH) ? 2 : 0) + ((wj >= WW) ? 1 : 0);
            int hl = (hj >= HH) ? hj - HH : hj;
            int wl = (wj >= WW) ? wj - WW : wj;
            v = x[(((long)(b * 4 + vv) * CC + c) * HH + hl) * WW + wl];
        }
        t[ty + s][tx] = v;
    }
    __syncthreads();
    long ob = (long)b * NN * CC;
#pragma unroll
    for (int s = 0; s < 32; s += 8) {
        int n = n0 + ty + s, c = c0 + tx;
        if (n < NN) {
            float v = t[tx][ty + s];
            __nv_bfloat16 h = __float2bfloat16(v);
            g_xhT[ob + (long)n * CC + c] = h;
            g_xlT[ob + (long)n * CC + c] = __float2bfloat16(v - __bfloat162float(h));
        }
    }
}

// ---------------------------------------------------------------------------
// generic tiled transpose + bf16 hi/lo split
// ---------------------------------------------------------------------------
__global__ void tsplit_kernel(const float* __restrict__ in,
                              __nv_bfloat16* __restrict__ hi,
                              __nv_bfloat16* __restrict__ lo,
                              int R, int Cn, long inStride) {
    __shared__ float t[32][33];
    int b = blockIdx.z;
    int r0 = blockIdx.y * 32, c0 = blockIdx.x * 32;
    const float* ib = in + (long)b * inStride;
    int tx = threadIdx.x, ty = threadIdx.y;
#pragma unroll
    for (int s = 0; s < 32; s += 8) {
        int r = r0 + ty + s, c = c0 + tx;
        t[ty + s][tx] = (r < R && c < Cn) ? ib[(long)r * Cn + c] : 0.f;
    }
    __syncthreads();
    long ob = (long)b * Cn * R;
#pragma unroll
    for (int s = 0; s < 32; s += 8) {
        int c = c0 + ty + s, r = r0 + tx;
        if (c < Cn && r < R) {
            float v = t[tx][ty + s];
            __nv_bfloat16 h = __float2bfloat16(v);
            hi[ob + (long)c * R + r] = h;
            lo[ob + (long)c * R + r] = __float2bfloat16(v - __bfloat162float(h));
        }
    }
}

// ---------------------------------------------------------------------------
// weight prep
// ---------------------------------------------------------------------------
__global__ void wsplit_stack_kernel(const float* __restrict__ wt, const float* __restrict__ wp,
                                    const float* __restrict__ wg, const float* __restrict__ bt,
                                    const float* __restrict__ bp, const float* __restrict__ bg) {
    long idx = (long)blockIdx.x * blockDim.x + threadIdx.x;
    if (idx < (long)CTPG * CC) {
        int r = (int)(idx / CC), c = (int)(idx % CC);
        const float* src = (r < CI) ? wt : ((r < 2 * CI) ? wp : wg);
        int rr = (r < CI) ? r : ((r < 2 * CI) ? r - CI : r - 2 * CI);
        float v = src[(long)rr * CC + c];
        __nv_bfloat16 h = __float2bfloat16(v);
        g_whi[idx] = h;
        g_wlo[idx] = __float2bfloat16(v - __bfloat162float(h));
    }
    if (idx < CTPG) {
        int r = (int)idx;
        g_bstk[r] = (r < CI) ? bt[r] : ((r < 2 * CI) ? bp[r - CI] : bg[r - 2 * CI]);
    }
}

__global__ void wsplitW_kernel(const float* __restrict__ wW) {
    long idx = (long)blockIdx.x * blockDim.x + threadIdx.x;
    if (idx >= (long)CC * CI) return;
    float v = wW[idx];
    __nv_bfloat16 h = __float2bfloat16(v);
    g_wWhi[idx] = h;
    g_wWlo[idx] = __float2bfloat16(v - __bfloat162float(h));
}

__global__ void bnprep_kernel(const float* __restrict__ gamma, const float* __restrict__ beta,
                              const float* __restrict__ mean, const float* __restrict__ var,
                              const float* __restrict__ bW) {
    int m = blockIdx.x * blockDim.x + threadIdx.x;
    if (m < CC) {
        float s = gamma[m] * rsqrtf(var[m] + 1e-5f);
        g_escale[m] = s;
        g_eshift[m] = beta[m] - mean[m] * s + bW[m] * s;
    }
}

// ---------------------------------------------------------------------------
// 2x2 maxpool: phi -> fp32 [c][196]; g -> bf16 hi/lo [c][224] padded
// ---------------------------------------------------------------------------
__global__ void pool_kernel() {
    int idx = blockIdx.x * blockDim.x + threadIdx.x;
    const int totPhi = BSZ * CI * MM;
    const int totG = BSZ * CI * MMP;
    if (idx < totPhi) {
        int m = idx % MM;
        int c = (idx / MM) % CI;
        int b = idx / (MM * CI);
        int hm = m / 14, wm = m % 14;
        const float* src = g_tpg + ((long)b * CTPG + CI + c) * NN;
        int base = (2 * hm) * WJ + 2 * wm;
        g_phi[idx] = fmaxf(fmaxf(src[base], src[base + 1]),
                           fmaxf(src[base + WJ], src[base + WJ + 1]));
    } else if (idx < totPhi + totG) {
        int r = idx - totPhi;
        int j = r % MMP;
        int c = (r / MMP) % CI;
        int b = r / (MMP * CI);
        float v = 0.f;
        if (j < MM) {
            int hm = j / 14, wm = j % 14;
            const float* src = g_tpg + ((long)b * CTPG + 2 * CI + c) * NN;
            int base = (2 * hm) * WJ + 2 * wm;
            v = fmaxf(fmaxf(src[base], src[base + 1]),
                      fmaxf(src[base + WJ], src[base + WJ + 1]));
        }
        __nv_bfloat16 h = __float2bfloat16(v);
        g_gph[r] = h;
        g_gpl[r] = (j < MM) ? __float2bfloat16(v - __bfloat162float(h)) : __nv_bfloat16(0.f);
    }
}

// ---------------------------------------------------------------------------
// row softmax over MM=196 -> attn hi/lo bf16 padded [n][224]
// ---------------------------------------------------------------------------
__global__ void softmax_kernel() {
    int warp = (blockIdx.x * blockDim.x + threadIdx.x) >> 5;
    int lane = threadIdx.x & 31;
    if (warp >= BSZ * NN) return;
    const float* row = g_f + (long)warp * MM;
    __nv_bfloat16* oh = g_ath + (long)warp * MMP;
    __nv_bfloat16* ol = g_atl + (long)warp * MMP;
    float vals[7];
    float mx = -1e30f;
#pragma unroll
    for (int s = 0; s < 7; s++) {
        int i = lane + s * 32;
        vals[s] = (i < MM) ? row[i] : -1e30f;
        mx = fmaxf(mx, vals[s]);
    }
#pragma unroll
    for (int o = 16; o; o >>= 1) mx = fmaxf(mx, __shfl_xor_sync(0xffffffffu, mx, o));
    float sum = 0.f;
#pragma unroll
    for (int s = 0; s < 7; s++) {
        int i = lane + s * 32;
        vals[s] = (i < MM) ? __expf(vals[s] - mx) : 0.f;
        sum += vals[s];
    }
#pragma unroll
    for (int o = 16; o; o >>= 1) sum += __shfl_xor_sync(0xffffffffu, sum, o);
    float inv = 1.f / sum;
#pragma unroll
    for (int s = 0; s < 7; s++) {
        int i = lane + s * 32;   // 0..223 == MMP
        float v = vals[s] * inv;
        __nv_bfloat16 h = __float2bfloat16(v);
        oh[i] = h;
        ol[i] = __float2bfloat16(v - __bfloat162float(h));
    }
}

// ---------------------------------------------------------------------------
// fused-pass bf16-split tensor GEMM (mma.sync m16n8k16).
//   128x128 CTA tile, 256 threads, 2 CTAs/SM, 3-stage cp.async pipeline,
//   swizzled 64B-row smem tiles, single __syncthreads per K-chunk.
//   Per K-chunk: load Ahi/Alo/Bhi/Blo once; mma hi*hi + hi*lo + lo*hi.
//   EPI 0: plain fp32
//   EPI 1: fp32 + g_bstk[m]
//   EPI 2: BN-fold + residual joint(x)
//   EPI 3: transposed bf16 hi/lo (compile-time; no other instance carries it)
// ---------------------------------------------------------------------------
#define GTILE (128 * 32)            // bf16 elems per tile (128 rows x 64B)
#define ST    (4 * GTILE)           // per-stage: [Ahi | Bhi | Alo | Blo]
#define SMEM3 (3 * ST * 2)          // 98304 B

// swizzled element offset within a tile: row-major 64B rows, 16B segs XORed
__device__ __forceinline__ int swz(int row, int seg) {
    return row * 32 + ((seg ^ ((row >> 1) & 3)) << 3);
}

template <int EPI>
__global__ void __launch_bounds__(256, 2)
mma128_kernel(const __nv_bfloat16* __restrict__ Ahi, const __nv_bfloat16* __restrict__ Alo,
              const __nv_bfloat16* __restrict__ Bhi, const __nv_bfloat16* __restrict__ Blo,
              float* __restrict__ Cp, int K, int MV, int NB,
              long strideA, long strideB, int ldC, long sC,
              const float* __restrict__ xres,
              __nv_bfloat16* __restrict__ Thi, __nv_bfloat16* __restrict__ Tlo, int ldT) {
    extern __shared__ __align__(16) __nv_bfloat16 smem[];

    const int tid = threadIdx.x;
    const int lane = tid & 31;
    const int wid = tid >> 5;
    const int wm = wid & 1;          // 2 M-warps -> 64 rows
    const int wn = wid >> 1;         // 4 N-warps -> 32 cols
    const int m0 = blockIdx.y * 128;
    const int n0 = blockIdx.x * 128;
    const int b  = blockIdx.z;

    const int NK = K / 32;
    const __nv_bfloat16* A0 = Ahi + (long)b * strideA + (long)m0 * K;
    const __nv_bfloat16* A1 = Alo + (long)b * strideA + (long)m0 * K;
    const __nv_bfloat16* B0 = Bhi + (long)b * strideB;
    const __nv_bfloat16* B1 = Blo + (long)b * strideB;

    float acc[4][4][4];
#pragma unroll
    for (int i = 0; i < 4; i++)
#pragma unroll
        for (int j = 0; j < 4; j++)
#pragma unroll
            for (int r = 0; r < 4; r++) acc[i][j][r] = 0.f;

    auto loadChunk = [&](int g, int stage) {
        long kc = (long)g * 32;
        __nv_bfloat16* st = smem + stage * ST;
#pragma unroll
        for (int i = 0; i < 2; i++) {
            int idx = tid + i * 256;
            int row = idx >> 2, seg = idx & 3;
            int off = swz(row, seg);
            long ga = (long)row * K + kc + seg * 8;
            int okA = (m0 + row) < MV;
            int okB = (n0 + row) < NB;
            long gb = (long)(okB ? (n0 + row) : 0) * K + kc + seg * 8;
            cpa16(smem_u32(st + off), A0 + ga, okA ? 16 : 0);
            cpa16(smem_u32(st + GTILE + off), B0 + gb, okB ? 16 : 0);
            cpa16(smem_u32(st + 2 * GTILE + off), A1 + ga, okA ? 16 : 0);
            cpa16(smem_u32(st + 3 * GTILE + off), B1 + gb, okB ? 16 : 0);
        }
    };

    loadChunk(0, 0); CPA_COMMIT();
    loadChunk(1, 1); CPA_COMMIT();

    int cs = 0;   // compute stage
    int ls = 2;   // next load stage
    for (int g = 0; g < NK; g++) {
        if (g + 1 < NK) { CPA_WAIT(1); } else { CPA_WAIT(0); }
        __syncthreads();
        if (g + 2 < NK) {
            loadChunk(g + 2, ls);
            CPA_COMMIT();
            ls = (ls == 2) ? 0 : ls + 1;
        }
        const __nv_bfloat16* st = smem + cs * ST;
        cs = (cs == 2) ? 0 : cs + 1;

#pragma unroll
        for (int ks = 0; ks < 2; ks++) {
            const int aRow = wm * 64 + ((lane >> 3) & 1) * 8 + (lane & 7);
            const int aSeg = ks * 2 + (lane >> 4);
            const int bRow = wn * 32 + (lane >> 4) * 8 + (lane & 7);
            const int bSeg = ks * 2 + ((lane >> 3) & 1);

            uint32_t bh[2][4];
#pragma unroll
            for (int ni = 0; ni < 2; ni++)
                ldm_x4(bh[ni], smem_u32(st + GTILE + swz(bRow + ni * 16, bSeg)));

            uint32_t a[4][4];
#pragma unroll
            for (int mi = 0; mi < 4; mi++)
                ldm_x4(a[mi], smem_u32(st + swz(aRow + mi * 16, aSeg)));

            // hi * hi
#pragma unroll
            for (int mi = 0; mi < 4; mi++)
#pragma unroll
                for (int nj = 0; nj < 4; nj++)
                    mma16816(acc[mi][nj], a[mi],
                             bh[nj >> 1][(nj & 1) * 2], bh[nj >> 1][(nj & 1) * 2 + 1]);

            // hi * lo
            uint32_t bl[2][4];
#pragma unroll
            for (int ni = 0; ni < 2; ni++)
                ldm_x4(bl[ni], smem_u32(st + 3 * GTILE + swz(bRow + ni * 16, bSeg)));
#pragma unroll
            for (int mi = 0; mi < 4; mi++)
#pragma unroll
                for (int nj = 0; nj < 4; nj++)
                    mma16816(acc[mi][nj], a[mi],
                             bl[nj >> 1][(nj & 1) * 2], bl[nj >> 1][(nj & 1) * 2 + 1]);

            // lo * hi (reuse a regs)
#pragma unroll
            for (int mi = 0; mi < 4; mi++)
                ldm_x4(a[mi], smem_u32(st + 2 * GTILE + swz(aRow + mi * 16, aSeg)));
#pragma unroll
            for (int mi = 0; mi < 4; mi++)
#pragma unroll
                for (int nj = 0; nj < 4; nj++)
                    mma16816(acc[mi][nj], a[mi],
                             bh[nj >> 1][(nj & 1) * 2], bh[nj >> 1][(nj & 1) * 2 + 1]);
        }
    }

    if (EPI != 3) {
        // ---- direct fp32 epilogue (identical codegen to R8 for EPI 0/1/2) ----
        const int mbase = m0 + wm * 64;
        const int nbase = n0 + wn * 32;
        float* Cb = Cp + (long)b * sC;
#pragma unroll
        for (int mi = 0; mi < 4; mi++) {
            int mr0 = mbase + mi * 16 + (lane >> 2);
            int mr1 = mr0 + 8;
            bool ok0 = mr0 < MV, ok1 = mr1 < MV;
            float es0 = 1.f, eh0 = 0.f, es1 = 1.f, eh1 = 0.f;
            if (EPI == 1) { if (ok0) eh0 = g_bstk[mr0]; if (ok1) eh1 = g_bstk[mr1]; }
            if (EPI == 2) {
                if (ok0) { es0 = g_escale[mr0]; eh0 = g_eshift[mr0]; }
                if (ok1) { es1 = g_escale[mr1]; eh1 = g_eshift[mr1]; }
            }
#pragma unroll
            for (int nj = 0; nj < 4; nj++) {
                int n = nbase + nj * 8 + (lane & 3) * 2;
                if (n >= NB) continue;
                float2 v0 = make_float2(acc[mi][nj][0], acc[mi][nj][1]);
                float2 v1 = make_float2(acc[mi][nj][2], acc[mi][nj][3]);
                if (EPI == 2) {
                    int hj = n / WJ, wj0 = n - hj * WJ;
#pragma unroll
                    for (int e = 0; e < 2; e++) {
                        int wj = wj0 + e;
                        int vv = ((hj >= HH) ? 2 : 0) + ((wj >= WW) ? 1 : 0);
                        int hl = (hj >= HH) ? hj - HH : hj;
                        int wl = (wj >= WW) ? wj - WW : wj;
                        long base = (((long)(b * 4 + vv) * CC) * HH + hl) * WW + wl;
                        float r0 = ok0 ? xres[base + (long)mr0 * HH * WW] : 0.f;
                        float r1 = ok1 ? xres[base + (long)mr1 * HH * WW] : 0.f;
                        if (e == 0) { v0.x = v0.x * es0 + eh0 + r0; v1.x = v1.x * es1 + eh1 + r1; }
                        else        { v0.y = v0.y * es0 + eh0 + r0; v1.y = v1.y * es1 + eh1 + r1; }
                    }
                } else {
                    v0.x = v0.x * es0 + eh0; v0.y = v0.y * es0 + eh0;
                    v1.x = v1.x * es1 + eh1; v1.y = v1.y * es1 + eh1;
                }
                if (ok0) *(float2*)(Cb + (long)mr0 * ldC + n) = v0;
                if (ok1) *(float2*)(Cb + (long)mr1 * ldC + n) = v1;
            }
        }
    } else {
        // ---- transposed bf16 hi/lo epilogue via smem staging (EPI 3 only) ----
        float* smf = reinterpret_cast<float*>(smem);   // [128][133] fp32
        __syncthreads();   // all warps done reading pipeline stages
#pragma unroll
        for (int mi = 0; mi < 4; mi++) {
            int ml0 = wm * 64 + mi * 16 + (lane >> 2);
            int ml1 = ml0 + 8;
#pragma unroll
            for (int nj = 0; nj < 4; nj++) {
                int nl = wn * 32 + nj * 8 + (lane & 3) * 2;
                smf[ml0 * 133 + nl]     = acc[mi][nj][0];
                smf[ml0 * 133 + nl + 1] = acc[mi][nj][1];
                smf[ml1 * 133 + nl]     = acc[mi][nj][2];
                smf[ml1 * 133 + nl + 1] = acc[mi][nj][3];
            }
        }
        __syncthreads();
        int nrow = tid >> 1;
        int mh = tid & 1;
        int ng = n0 + nrow;
        if (ng < NB) {
            long obase = ((long)b * NN + ng) * ldT + m0 + mh * 64;
            uint32_t* oh = (uint32_t*)(Thi + obase);
            uint32_t* ol = (uint32_t*)(Tlo + obase);
#pragma unroll
            for (int j = 0; j < 64; j += 2) {
                float v0 = smf[(mh * 64 + j) * 133 + nrow];
                float v1 = smf[(mh * 64 + j + 1) * 133 + nrow];
                __nv_bfloat16 h0 = __float2bfloat16(v0);
                __nv_bfloat16 h1 = __float2bfloat16(v1);
                __nv_bfloat16 l0 = __float2bfloat16(v0 - __bfloat162float(h0));
                __nv_bfloat16 l1 = __float2bfloat16(v1 - __bfloat162float(h1));
                uint16_t h0b = *(uint16_t*)&h0, h1b = *(uint16_t*)&h1;
                uint16_t l0b = *(uint16_t*)&l0, l1b = *(uint16_t*)&l1;
                oh[j >> 1] = (uint32_t)h0b | ((uint32_t)h1b << 16);
                ol[j >> 1] = (uint32_t)l0b | ((uint32_t)l1b << 16);
            }
        }
    }
}

// ---------------------------------------------------------------------------
// Launch
// ---------------------------------------------------------------------------
extern "C" void kernel_launch(void* const* d_in, const int* in_sizes, int n_in,
                              void* d_out, int out_size) {
    const float* x     = (const float*)d_in[0];
    const float* wt    = (const float*)d_in[1];
    const float* bt    = (const float*)d_in[2];
    const float* wp    = (const float*)d_in[3];
    const float* bp    = (const float*)d_in[4];
    const float* wg    = (const float*)d_in[5];
    const float* bg    = (const float*)d_in[6];
    const float* wW    = (const float*)d_in[7];
    const float* bW    = (const float*)d_in[8];
    const float* gamma = (const float*)d_in[9];
    const float* beta  = (const float*)d_in[10];
    const float* mean  = (const float*)d_in[11];
    const float* var   = (const float*)d_in[12];
    float* out = (float*)d_out;

    float *p_tpg, *p_phi, *p_f;
    __nv_bfloat16 *p_xhT, *p_xlT, *p_thh, *p_thl, *p_phh, *p_phl;
    __nv_bfloat16 *p_gph, *p_gpl, *p_ath, *p_atl, *p_yhT, *p_ylT;
    __nv_bfloat16 *p_whi, *p_wlo, *p_wWhi, *p_wWlo;
    cudaGetSymbolAddress((void**)&p_tpg, g_tpg);
    cudaGetSymbolAddress((void**)&p_phi, g_phi);
    cudaGetSymbolAddress((void**)&p_f, g_f);
    cudaGetSymbolAddress((void**)&p_xhT, g_xhT);
    cudaGetSymbolAddress((void**)&p_xlT, g_xlT);
    cudaGetSymbolAddress((void**)&p_thh, g_thh);
    cudaGetSymbolAddress((void**)&p_thl, g_thl);
    cudaGetSymbolAddress((void**)&p_phh, g_phh);
    cudaGetSymbolAddress((void**)&p_phl, g_phl);
    cudaGetSymbolAddress((void**)&p_gph, g_gph);
    cudaGetSymbolAddress((void**)&p_gpl, g_gpl);
    cudaGetSymbolAddress((void**)&p_ath, g_ath);
    cudaGetSymbolAddress((void**)&p_atl, g_atl);
    cudaGetSymbolAddress((void**)&p_yhT, g_yhT);
    cudaGetSymbolAddress((void**)&p_ylT, g_ylT);
    cudaGetSymbolAddress((void**)&p_whi, g_whi);
    cudaGetSymbolAddress((void**)&p_wlo, g_wlo);
    cudaGetSymbolAddress((void**)&p_wWhi, g_wWhi);
    cudaGetSymbolAddress((void**)&p_wWlo, g_wWlo);

    cudaFuncSetAttribute((const void*)mma128_kernel<0>,
                         cudaFuncAttributeMaxDynamicSharedMemorySize, SMEM3);
    cudaFuncSetAttribute((const void*)mma128_kernel<1>,
                         cudaFuncAttributeMaxDynamicSharedMemorySize, SMEM3);
    cudaFuncSetAttribute((const void*)mma128_kernel<2>,
                         cudaFuncAttributeMaxDynamicSharedMemorySize, SMEM3);
    cudaFuncSetAttribute((const void*)mma128_kernel<3>,
                         cudaFuncAttributeMaxDynamicSharedMemorySize, SMEM3);

    // #1 weight stack+split
    {
        long total = (long)CTPG * CC;
        wsplit_stack_kernel<<<(unsigned)((total + 255) / 256), 256>>>(wt, wp, wg, bt, bp, bg);
    }
    // #2 fused joint + transpose + split
    {
        dim3 grid((NN + 31) / 32, CC / 32, BSZ);
        tsplitX_kernel<<<grid, dim3(32, 8)>>>(x);
    }
    // #3 BN prep (keeps GEMM1 at launch #4 for ncu)
    bnprep_kernel<<<(CC + 255) / 256, 256>>>(gamma, beta, mean, var, bW);
    // #4 stacked theta|phi|g conv -> tpg (fp32 + bias)
    {
        mma128_kernel<1><<<dim3((NN + 127) / 128, CTPG / 128, BSZ), 256, SMEM3>>>(
            p_whi, p_wlo, p_xhT, p_xlT, p_tpg, CC, CTPG, NN,
            0L, (long)NN * CC, NN, (long)CTPG * NN, nullptr,
            nullptr, nullptr, 0);
    }
    // #5 W-conv weight split
    wsplitW_kernel<<<(unsigned)(((long)CC * CI + 255) / 256), 256>>>(wW);
    // #6 pool
    {
        int total = BSZ * CI * (MM + MMP);
        pool_kernel<<<(total + 255) / 256, 256>>>();
    }
    // #7 theta slice -> theta^T hi/lo
    {
        dim3 grid((NN + 31) / 32, CI / 32, BSZ);
        tsplit_kernel<<<grid, dim3(32, 8)>>>(p_tpg, p_thh, p_thl, CI, NN, (long)CTPG * NN);
    }
    // #8 phi -> phi^T hi/lo
    {
        dim3 grid((MM + 31) / 32, CI / 32, BSZ);
        tsplit_kernel<<<grid, dim3(32, 8)>>>(p_phi, p_phh, p_phl, CI, MM, (long)CI * MM);
    }
    // #9 f = thetaT @ phiT^T
    {
        mma128_kernel<0><<<dim3((MM + 127) / 128, (NN + 127) / 128, BSZ), 256, SMEM3>>>(
            p_thh, p_thl, p_phh, p_phl, p_f, CI, NN, MM,
            (long)NN * CI, (long)MM * CI, MM, (long)NN * MM, nullptr,
            nullptr, nullptr, 0);
    }
    // #10 softmax -> attn hi/lo padded
    {
        int rows = BSZ * NN;
        softmax_kernel<<<(rows * 32 + 255) / 256, 256>>>();
    }
    // #11 y = g @ attn^T; writes y^T hi/lo directly (EPI 3, compile-time)
    {
        mma128_kernel<3><<<dim3((NN + 127) / 128, CI / 128, BSZ), 256, SMEM3>>>(
            p_gph, p_gpl, p_ath, p_atl, nullptr, MMP, CI, NN,
            (long)CI * MMP, (long)NN * MMP, 0, 0L, nullptr,
            p_yhT, p_ylT, CI);
    }
    // #12 W conv (3-pass split) + BN + residual -> out
    {
        mma128_kernel<2><<<dim3((NN + 127) / 128, CC / 128, BSZ), 256, SMEM3>>>(
            p_wWhi, p_wWlo, p_yhT, p_ylT, out, CI, CC, NN,
            0L, (long)NN * CI, NN, (long)CC * NN, x,
            nullptr, nullptr, 0);
    }
}

// round 11
// speedup vs baseline: 1.1507x; 1.1220x over previous
#include <cuda_runtime.h>
#include <cuda_bf16.h>
#include <cstdint>

// ---------------------------------------------------------------------------
// Problem constants
// ---------------------------------------------------------------------------
#define BSZ  32
#define CC   1536
#define CI   768
#define HH   14
#define WW   14
#define HJ   28
#define WJ   28
#define NN   784
#define MM   196
#define MMP  224          // MM padded to multiple of 32
#define CTPG 2304
#define GNTOT (BSZ * NN)  // 25088 = 196 * 128 exactly

// ---------------------------------------------------------------------------
// Scratch (device globals)
// ---------------------------------------------------------------------------
__device__ __align__(16) __nv_bfloat16 g_xhT[(size_t)BSZ * NN * CC];
__device__ __align__(16) __nv_bfloat16 g_xlT[(size_t)BSZ * NN * CC];
__device__ float g_tpg [(size_t)BSZ * CTPG * NN];
__device__ __align__(16) __nv_bfloat16 g_thh[(size_t)BSZ * NN * CI];
__device__ __align__(16) __nv_bfloat16 g_thl[(size_t)BSZ * NN * CI];
__device__ float g_phi [(size_t)BSZ * CI * MM];
__device__ __align__(16) __nv_bfloat16 g_phh[(size_t)BSZ * MM * CI];
__device__ __align__(16) __nv_bfloat16 g_phl[(size_t)BSZ * MM * CI];
__device__ __align__(16) __nv_bfloat16 g_gph[(size_t)BSZ * CI * MMP];
__device__ __align__(16) __nv_bfloat16 g_gpl[(size_t)BSZ * CI * MMP];
__device__ float g_f   [(size_t)BSZ * NN * MM];
__device__ __align__(16) __nv_bfloat16 g_ath[(size_t)BSZ * NN * MMP];
__device__ __align__(16) __nv_bfloat16 g_atl[(size_t)BSZ * NN * MMP];
__device__ float g_y   [(size_t)BSZ * CI * NN];
__device__ __align__(16) __nv_bfloat16 g_yhT[(size_t)BSZ * NN * CI];
__device__ __align__(16) __nv_bfloat16 g_ylT[(size_t)BSZ * NN * CI];
__device__ __align__(16) __nv_bfloat16 g_whi[(size_t)CTPG * CC];
__device__ __align__(16) __nv_bfloat16 g_wlo[(size_t)CTPG * CC];
__device__ __align__(16) __nv_bfloat16 g_wWhi[(size_t)CC * CI];
__device__ __align__(16) __nv_bfloat16 g_wWlo[(size_t)CC * CI];
__device__ float g_bstk[CTPG];
__device__ float g_escale[CC];
__device__ float g_eshift[CC];

// ---------------------------------------------------------------------------
// PTX helpers (base ISA only — harness's ptxas targets plain sm_103)
// ---------------------------------------------------------------------------
__device__ __forceinline__ uint32_t smem_u32(const void* p) {
    uint32_t a;
    asm("{ .reg .u64 t; cvta.to.shared.u64 t, %1; cvt.u32.u64 %0, t; }" : "=r"(a) : "l"(p));
    return a;
}
__device__ __forceinline__ void ldm_x4(uint32_t* r, uint32_t addr) {
    asm volatile("ldmatrix.sync.aligned.m8n8.x4.shared.b16 {%0,%1,%2,%3}, [%4];"
                 : "=r"(r[0]), "=r"(r[1]), "=r"(r[2]), "=r"(r[3]) : "r"(addr));
}
__device__ __forceinline__ void mma16816(float* d, const uint32_t* a, uint32_t b0, uint32_t b1) {
    asm volatile("mma.sync.aligned.m16n8k16.row.col.f32.bf16.bf16.f32 "
                 "{%0,%1,%2,%3}, {%4,%5,%6,%7}, {%8,%9}, {%0,%1,%2,%3};"
                 : "+f"(d[0]), "+f"(d[1]), "+f"(d[2]), "+f"(d[3])
                 : "r"(a[0]), "r"(a[1]), "r"(a[2]), "r"(a[3]), "r"(b0), "r"(b1));
}
__device__ __forceinline__ void cpa16(uint32_t dst, const void* src, int srcsz) {
    asm volatile("cp.async.cg.shared.global [%0], [%1], 16, %2;"
                 :: "r"(dst), "l"(src), "r"(srcsz));
}
__device__ __forceinline__ void cpa16u(uint32_t dst, const void* src) {
    asm volatile("cp.async.cg.shared.global [%0], [%1], 16;"
                 :: "r"(dst), "l"(src));
}
#define CPA_COMMIT()  asm volatile("cp.async.commit_group;" ::: "memory")
#define CPA_WAIT(n)   asm volatile("cp.async.wait_group %0;" :: "n"(n) : "memory")

// ---------------------------------------------------------------------------
// fused joint-gather + transpose + bf16 hi/lo split: x -> xjT [b][n][c]
// ---------------------------------------------------------------------------
__global__ void tsplitX_kernel(const float* __restrict__ x) {
    __shared__ float t[32][33];
    int b = blockIdx.z;
    int c0 = blockIdx.y * 32, n0 = blockIdx.x * 32;
    int tx = threadIdx.x, ty = threadIdx.y;
#pragma unroll
    for (int s = 0; s < 32; s += 8) {
        int c = c0 + ty + s, n = n0 + tx;
        float v = 0.f;
        if (n < NN) {
            int hj = n / WJ, wj = n % WJ;
            int vv = ((hj >= HH) ? 2 : 0) + ((wj >= WW) ? 1 : 0);
            int hl = (hj >= HH) ? hj - HH : hj;
            int wl = (wj >= WW) ? wj - WW : wj;
            v = x[(((long)(b * 4 + vv) * CC + c) * HH + hl) * WW + wl];
        }
        t[ty + s][tx] = v;
    }
    __syncthreads();
    long ob = (long)b * NN * CC;
#pragma unroll
    for (int s = 0; s < 32; s += 8) {
        int n = n0 + ty + s, c = c0 + tx;
        if (n < NN) {
            float v = t[tx][ty + s];
            __nv_bfloat16 h = __float2bfloat16(v);
            g_xhT[ob + (long)n * CC + c] = h;
            g_xlT[ob + (long)n * CC + c] = __float2bfloat16(v - __bfloat162float(h));
        }
    }
}

// ---------------------------------------------------------------------------
// generic tiled transpose + bf16 hi/lo split
// ---------------------------------------------------------------------------
__global__ void tsplit_kernel(const float* __restrict__ in,
                              __nv_bfloat16* __restrict__ hi,
                              __nv_bfloat16* __restrict__ lo,
                              int R, int Cn, long inStride) {
    __shared__ float t[32][33];
    int b = blockIdx.z;
    int r0 = blockIdx.y * 32, c0 = blockIdx.x * 32;
    const float* ib = in + (long)b * inStride;
    int tx = threadIdx.x, ty = threadIdx.y;
#pragma unroll
    for (int s = 0; s < 32; s += 8) {
        int r = r0 + ty + s, c = c0 + tx;
        t[ty + s][tx] = (r < R && c < Cn) ? ib[(long)r * Cn + c] : 0.f;
    }
    __syncthreads();
    long ob = (long)b * Cn * R;
#pragma unroll
    for (int s = 0; s < 32; s += 8) {
        int c = c0 + ty + s, r = r0 + tx;
        if (c < Cn && r < R) {
            float v = t[tx][ty + s];
            __nv_bfloat16 h = __float2bfloat16(v);
            hi[ob + (long)c * R + r] = h;
            lo[ob + (long)c * R + r] = __float2bfloat16(v - __bfloat162float(h));
        }
    }
}

// ---------------------------------------------------------------------------
// weight prep
// ---------------------------------------------------------------------------
__global__ void wsplit_stack_kernel(const float* __restrict__ wt, const float* __restrict__ wp,
                                    const float* __restrict__ wg, const float* __restrict__ bt,
                                    const float* __restrict__ bp, const float* __restrict__ bg) {
    long idx = (long)blockIdx.x * blockDim.x + threadIdx.x;
    if (idx < (long)CTPG * CC) {
        int r = (int)(idx / CC), c = (int)(idx % CC);
        const float* src = (r < CI) ? wt : ((r < 2 * CI) ? wp : wg);
        int rr = (r < CI) ? r : ((r < 2 * CI) ? r - CI : r - 2 * CI);
        float v = src[(long)rr * CC + c];
        __nv_bfloat16 h = __float2bfloat16(v);
        g_whi[idx] = h;
        g_wlo[idx] = __float2bfloat16(v - __bfloat162float(h));
    }
    if (idx < CTPG) {
        int r = (int)idx;
        g_bstk[r] = (r < CI) ? bt[r] : ((r < 2 * CI) ? bp[r - CI] : bg[r - 2 * CI]);
    }
}

__global__ void wsplitW_kernel(const float* __restrict__ wW) {
    long idx = (long)blockIdx.x * blockDim.x + threadIdx.x;
    if (idx >= (long)CC * CI) return;
    float v = wW[idx];
    __nv_bfloat16 h = __float2bfloat16(v);
    g_wWhi[idx] = h;
    g_wWlo[idx] = __float2bfloat16(v - __bfloat162float(h));
}

__global__ void bnprep_kernel(const float* __restrict__ gamma, const float* __restrict__ beta,
                              const float* __restrict__ mean, const float* __restrict__ var,
                              const float* __restrict__ bW) {
    int m = blockIdx.x * blockDim.x + threadIdx.x;
    if (m < CC) {
        float s = gamma[m] * rsqrtf(var[m] + 1e-5f);
        g_escale[m] = s;
        g_eshift[m] = beta[m] - mean[m] * s + bW[m] * s;
    }
}

// ---------------------------------------------------------------------------
// 2x2 maxpool: phi -> fp32 [c][196]; g -> bf16 hi/lo [c][224] padded
// ---------------------------------------------------------------------------
__global__ void pool_kernel() {
    int idx = blockIdx.x * blockDim.x + threadIdx.x;
    const int totPhi = BSZ * CI * MM;
    const int totG = BSZ * CI * MMP;
    if (idx < totPhi) {
        int m = idx % MM;
        int c = (idx / MM) % CI;
        int b = idx / (MM * CI);
        int hm = m / 14, wm = m % 14;
        const float* src = g_tpg + ((long)b * CTPG + CI + c) * NN;
        int base = (2 * hm) * WJ + 2 * wm;
        g_phi[idx] = fmaxf(fmaxf(src[base], src[base + 1]),
                           fmaxf(src[base + WJ], src[base + WJ + 1]));
    } else if (idx < totPhi + totG) {
        int r = idx - totPhi;
        int j = r % MMP;
        int c = (r / MMP) % CI;
        int b = r / (MMP * CI);
        float v = 0.f;
        if (j < MM) {
            int hm = j / 14, wm = j % 14;
            const float* src = g_tpg + ((long)b * CTPG + 2 * CI + c) * NN;
            int base = (2 * hm) * WJ + 2 * wm;
            v = fmaxf(fmaxf(src[base], src[base + 1]),
                      fmaxf(src[base + WJ], src[base + WJ + 1]));
        }
        __nv_bfloat16 h = __float2bfloat16(v);
        g_gph[r] = h;
        g_gpl[r] = (j < MM) ? __float2bfloat16(v - __bfloat162float(h)) : __nv_bfloat16(0.f);
    }
}

// ---------------------------------------------------------------------------
// row softmax over MM=196 -> attn hi/lo bf16 padded [n][224]
// ---------------------------------------------------------------------------
__global__ void softmax_kernel() {
    int warp = (blockIdx.x * blockDim.x + threadIdx.x) >> 5;
    int lane = threadIdx.x & 31;
    if (warp >= BSZ * NN) return;
    const float* row = g_f + (long)warp * MM;
    __nv_bfloat16* oh = g_ath + (long)warp * MMP;
    __nv_bfloat16* ol = g_atl + (long)warp * MMP;
    float vals[7];
    float mx = -1e30f;
#pragma unroll
    for (int s = 0; s < 7; s++) {
        int i = lane + s * 32;
        vals[s] = (i < MM) ? row[i] : -1e30f;
        mx = fmaxf(mx, vals[s]);
    }
#pragma unroll
    for (int o = 16; o; o >>= 1) mx = fmaxf(mx, __shfl_xor_sync(0xffffffffu, mx, o));
    float sum = 0.f;
#pragma unroll
    for (int s = 0; s < 7; s++) {
        int i = lane + s * 32;
        vals[s] = (i < MM) ? __expf(vals[s] - mx) : 0.f;
        sum += vals[s];
    }
#pragma unroll
    for (int o = 16; o; o >>= 1) sum += __shfl_xor_sync(0xffffffffu, sum, o);
    float inv = 1.f / sum;
#pragma unroll
    for (int s = 0; s < 7; s++) {
        int i = lane + s * 32;   // 0..223 == MMP
        float v = vals[s] * inv;
        __nv_bfloat16 h = __float2bfloat16(v);
        oh[i] = h;
        ol[i] = __float2bfloat16(v - __bfloat162float(h));
    }
}

// ---------------------------------------------------------------------------
// fused-pass bf16-split tensor GEMM (mma.sync m16n8k16).
//   128x128 CTA tile, 256 threads, 2 CTAs/SM, 3-stage cp.async pipeline,
//   swizzled 64B-row smem tiles, single __syncthreads per K-chunk.
//   Per K-chunk: load Ahi/Alo/Bhi/Blo once; mma hi*hi + hi*lo + lo*hi.
//   EPI 0: per-batch (blockIdx.z) fp32 store, M/N bounds
//   EPI 1: batch-flattened N (gn = b*784+n); +g_bstk[m]; no bounds
//   EPI 2: batch-flattened N; BN-fold + residual joint(x); no bounds
// ---------------------------------------------------------------------------
#define GTILE (128 * 32)            // bf16 elems per tile (128 rows x 64B)
#define ST    (4 * GTILE)           // per-stage: [Ahi | Bhi | Alo | Blo]
#define SMEM3 (3 * ST * 2)          // 98304 B

// swizzled element offset within a tile: row-major 64B rows, 16B segs XORed
__device__ __forceinline__ int swz(int row, int seg) {
    return row * 32 + ((seg ^ ((row >> 1) & 3)) << 3);
}

template <int EPI>
__global__ void __launch_bounds__(256, 2)
mma128_kernel(const __nv_bfloat16* __restrict__ Ahi, const __nv_bfloat16* __restrict__ Alo,
              const __nv_bfloat16* __restrict__ Bhi, const __nv_bfloat16* __restrict__ Blo,
              float* __restrict__ Cp, int K, int MV, int NB,
              long strideA, long strideB, int ldC, long sC,
              const float* __restrict__ xres) {
    extern __shared__ __align__(16) __nv_bfloat16 smem[];
    constexpr bool GN = (EPI == 1) || (EPI == 2);   // batch-flattened N

    const int tid = threadIdx.x;
    const int lane = tid & 31;
    const int wid = tid >> 5;
    const int wm = wid & 1;          // 2 M-warps -> 64 rows
    const int wn = wid >> 1;         // 4 N-warps -> 32 cols
    const int m0 = blockIdx.y * 128;
    const int n0 = blockIdx.x * 128;
    const int b  = blockIdx.z;       // 0 in GN mode

    const int NK = K / 32;
    const __nv_bfloat16* A0 = Ahi + (long)b * strideA + (long)m0 * K;
    const __nv_bfloat16* A1 = Alo + (long)b * strideA + (long)m0 * K;
    const __nv_bfloat16* B0 = Bhi + (long)b * strideB;
    const __nv_bfloat16* B1 = Blo + (long)b * strideB;

    float acc[4][4][4];
#pragma unroll
    for (int i = 0; i < 4; i++)
#pragma unroll
        for (int j = 0; j < 4; j++)
#pragma unroll
            for (int r = 0; r < 4; r++) acc[i][j][r] = 0.f;

    auto loadChunk = [&](int g, int stage) {
        long kc = (long)g * 32;
        __nv_bfloat16* st = smem + stage * ST;
#pragma unroll
        for (int i = 0; i < 2; i++) {
            int idx = tid + i * 256;
            int row = idx >> 2, seg = idx & 3;
            int off = swz(row, seg);
            long ga = (long)row * K + kc + seg * 8;
            if (GN) {
                // M multiple of 128 and N exactly 196*128: no bounds needed
                long gb = (long)(n0 + row) * K + kc + seg * 8;
                cpa16u(smem_u32(st + off), A0 + ga);
                cpa16u(smem_u32(st + GTILE + off), B0 + gb);
                cpa16u(smem_u32(st + 2 * GTILE + off), A1 + ga);
                cpa16u(smem_u32(st + 3 * GTILE + off), B1 + gb);
            } else {
                int okA = (m0 + row) < MV;
                int okB = (n0 + row) < NB;
                long gb = (long)(okB ? (n0 + row) : 0) * K + kc + seg * 8;
                cpa16(smem_u32(st + off), A0 + ga, okA ? 16 : 0);
                cpa16(smem_u32(st + GTILE + off), B0 + gb, okB ? 16 : 0);
                cpa16(smem_u32(st + 2 * GTILE + off), A1 + ga, okA ? 16 : 0);
                cpa16(smem_u32(st + 3 * GTILE + off), B1 + gb, okB ? 16 : 0);
            }
        }
    };

    loadChunk(0, 0); CPA_COMMIT();
    loadChunk(1, 1); CPA_COMMIT();

    int cs = 0;   // compute stage
    int ls = 2;   // next load stage
    for (int g = 0; g < NK; g++) {
        if (g + 1 < NK) { CPA_WAIT(1); } else { CPA_WAIT(0); }
        __syncthreads();
        if (g + 2 < NK) {
            loadChunk(g + 2, ls);
            CPA_COMMIT();
            ls = (ls == 2) ? 0 : ls + 1;
        }
        const __nv_bfloat16* st = smem + cs * ST;
        cs = (cs == 2) ? 0 : cs + 1;

#pragma unroll
        for (int ks = 0; ks < 2; ks++) {
            const int aRow = wm * 64 + ((lane >> 3) & 1) * 8 + (lane & 7);
            const int aSeg = ks * 2 + (lane >> 4);
            const int bRow = wn * 32 + (lane >> 4) * 8 + (lane & 7);
            const int bSeg = ks * 2 + ((lane >> 3) & 1);

            uint32_t bh[2][4];
#pragma unroll
            for (int ni = 0; ni < 2; ni++)
                ldm_x4(bh[ni], smem_u32(st + GTILE + swz(bRow + ni * 16, bSeg)));

            uint32_t a[4][4];
#pragma unroll
            for (int mi = 0; mi < 4; mi++)
                ldm_x4(a[mi], smem_u32(st + swz(aRow + mi * 16, aSeg)));

            // hi * hi
#pragma unroll
            for (int mi = 0; mi < 4; mi++)
#pragma unroll
                for (int nj = 0; nj < 4; nj++)
                    mma16816(acc[mi][nj], a[mi],
                             bh[nj >> 1][(nj & 1) * 2], bh[nj >> 1][(nj & 1) * 2 + 1]);

            // hi * lo
            uint32_t bl[2][4];
#pragma unroll
            for (int ni = 0; ni < 2; ni++)
                ldm_x4(bl[ni], smem_u32(st + 3 * GTILE + swz(bRow + ni * 16, bSeg)));
#pragma unroll
            for (int mi = 0; mi < 4; mi++)
#pragma unroll
                for (int nj = 0; nj < 4; nj++)
                    mma16816(acc[mi][nj], a[mi],
                             bl[nj >> 1][(nj & 1) * 2], bl[nj >> 1][(nj & 1) * 2 + 1]);

            // lo * hi (reuse a regs)
#pragma unroll
            for (int mi = 0; mi < 4; mi++)
                ldm_x4(a[mi], smem_u32(st + 2 * GTILE + swz(aRow + mi * 16, aSeg)));
#pragma unroll
            for (int mi = 0; mi < 4; mi++)
#pragma unroll
                for (int nj = 0; nj < 4; nj++)
                    mma16816(acc[mi][nj], a[mi],
                             bh[nj >> 1][(nj & 1) * 2], bh[nj >> 1][(nj & 1) * 2 + 1]);
        }
    }

    // ---- epilogue ----
    const int mbase = m0 + wm * 64;
    const int nbase = n0 + wn * 32;
#pragma unroll
    for (int mi = 0; mi < 4; mi++) {
        int mr0 = mbase + mi * 16 + (lane >> 2);
        int mr1 = mr0 + 8;
        bool ok0 = GN ? true : (mr0 < MV);
        bool ok1 = GN ? true : (mr1 < MV);
        float es0 = 1.f, eh0 = 0.f, es1 = 1.f, eh1 = 0.f;
        if (EPI == 1) { eh0 = g_bstk[mr0]; eh1 = g_bstk[mr1]; }
        if (EPI == 2) {
            es0 = g_escale[mr0]; eh0 = g_eshift[mr0];
            es1 = g_escale[mr1]; eh1 = g_eshift[mr1];
        }
#pragma unroll
        for (int nj = 0; nj < 4; nj++) {
            int n = nbase + nj * 8 + (lane & 3) * 2;
            float2 v0 = make_float2(acc[mi][nj][0], acc[mi][nj][1]);
            float2 v1 = make_float2(acc[mi][nj][2], acc[mi][nj][3]);
            if (GN) {
                // global column -> (batch, local n); pairs never straddle
                int bcol = n / NN;
                int nl = n - bcol * NN;
                float* Cb = Cp + (long)bcol * sC;
                if (EPI == 2) {
                    int hj = nl / WJ, wj0 = nl - hj * WJ;
#pragma unroll
                    for (int e = 0; e < 2; e++) {
                        int wj = wj0 + e;
                        int vv = ((hj >= HH) ? 2 : 0) + ((wj >= WW) ? 1 : 0);
                        int hl = (hj >= HH) ? hj - HH : hj;
                        int wl = (wj >= WW) ? wj - WW : wj;
                        long base = (((long)(bcol * 4 + vv) * CC) * HH + hl) * WW + wl;
                        float r0 = xres[base + (long)mr0 * HH * WW];
                        float r1 = xres[base + (long)mr1 * HH * WW];
                        if (e == 0) { v0.x = v0.x * es0 + eh0 + r0; v1.x = v1.x * es1 + eh1 + r1; }
                        else        { v0.y = v0.y * es0 + eh0 + r0; v1.y = v1.y * es1 + eh1 + r1; }
                    }
                } else {
                    v0.x += eh0; v0.y += eh0; v1.x += eh1; v1.y += eh1;
                }
                *(float2*)(Cb + (long)mr0 * ldC + nl) = v0;
                *(float2*)(Cb + (long)mr1 * ldC + nl) = v1;
            } else {
                if (n >= NB) continue;
                float* Cb = Cp + (long)b * sC;
                if (ok0) *(float2*)(Cb + (long)mr0 * ldC + n) = v0;
                if (ok1) *(float2*)(Cb + (long)mr1 * ldC + n) = v1;
            }
        }
    }
}

// ---------------------------------------------------------------------------
// Launch
// ---------------------------------------------------------------------------
extern "C" void kernel_launch(void* const* d_in, const int* in_sizes, int n_in,
                              void* d_out, int out_size) {
    const float* x     = (const float*)d_in[0];
    const float* wt    = (const float*)d_in[1];
    const float* bt    = (const float*)d_in[2];
    const float* wp    = (const float*)d_in[3];
    const float* bp    = (const float*)d_in[4];
    const float* wg    = (const float*)d_in[5];
    const float* bg    = (const float*)d_in[6];
    const float* wW    = (const float*)d_in[7];
    const float* bW    = (const float*)d_in[8];
    const float* gamma = (const float*)d_in[9];
    const float* beta  = (const float*)d_in[10];
    const float* mean  = (const float*)d_in[11];
    const float* var   = (const float*)d_in[12];
    float* out = (float*)d_out;

    float *p_tpg, *p_phi, *p_f, *p_y;
    __nv_bfloat16 *p_xhT, *p_xlT, *p_thh, *p_thl, *p_phh, *p_phl;
    __nv_bfloat16 *p_gph, *p_gpl, *p_ath, *p_atl, *p_yhT, *p_ylT;
    __nv_bfloat16 *p_whi, *p_wlo, *p_wWhi, *p_wWlo;
    cudaGetSymbolAddress((void**)&p_tpg, g_tpg);
    cudaGetSymbolAddress((void**)&p_phi, g_phi);
    cudaGetSymbolAddress((void**)&p_f, g_f);
    cudaGetSymbolAddress((void**)&p_y, g_y);
    cudaGetSymbolAddress((void**)&p_xhT, g_xhT);
    cudaGetSymbolAddress((void**)&p_xlT, g_xlT);
    cudaGetSymbolAddress((void**)&p_thh, g_thh);
    cudaGetSymbolAddress((void**)&p_thl, g_thl);
    cudaGetSymbolAddress((void**)&p_phh, g_phh);
    cudaGetSymbolAddress((void**)&p_phl, g_phl);
    cudaGetSymbolAddress((void**)&p_gph, g_gph);
    cudaGetSymbolAddress((void**)&p_gpl, g_gpl);
    cudaGetSymbolAddress((void**)&p_ath, g_ath);
    cudaGetSymbolAddress((void**)&p_atl, g_atl);
    cudaGetSymbolAddress((void**)&p_yhT, g_yhT);
    cudaGetSymbolAddress((void**)&p_ylT, g_ylT);
    cudaGetSymbolAddress((void**)&p_whi, g_whi);
    cudaGetSymbolAddress((void**)&p_wlo, g_wlo);
    cudaGetSymbolAddress((void**)&p_wWhi, g_wWhi);
    cudaGetSymbolAddress((void**)&p_wWlo, g_wWlo);

    cudaFuncSetAttribute((const void*)mma128_kernel<0>,
                         cudaFuncAttributeMaxDynamicSharedMemorySize, SMEM3);
    cudaFuncSetAttribute((const void*)mma128_kernel<1>,
                         cudaFuncAttributeMaxDynamicSharedMemorySize, SMEM3);
    cudaFuncSetAttribute((const void*)mma128_kernel<2>,
                         cudaFuncAttributeMaxDynamicSharedMemorySize, SMEM3);

    // #1 weight stack+split
    {
        long total = (long)CTPG * CC;
        wsplit_stack_kernel<<<(unsigned)((total + 255) / 256), 256>>>(wt, wp, wg, bt, bp, bg);
    }
    // #2 fused joint + transpose + split
    {
        dim3 grid((NN + 31) / 32, CC / 32, BSZ);
        tsplitX_kernel<<<grid, dim3(32, 8)>>>(x);
    }
    // #3 BN prep (keeps GEMM1 at launch #4 for ncu)
    bnprep_kernel<<<(CC + 255) / 256, 256>>>(gamma, beta, mean, var, bW);
    // #4 stacked theta|phi|g conv, batch-flattened N (25088 = 196*128)
    {
        mma128_kernel<1><<<dim3(GNTOT / 128, CTPG / 128, 1), 256, SMEM3>>>(
            p_whi, p_wlo, p_xhT, p_xlT, p_tpg, CC, CTPG, GNTOT,
            0L, 0L, NN, (long)CTPG * NN, nullptr);
    }
    // #5 W-conv weight split
    wsplitW_kernel<<<(unsigned)(((long)CC * CI + 255) / 256), 256>>>(wW);
    // #6 pool
    {
        int total = BSZ * CI * (MM + MMP);
        pool_kernel<<<(total + 255) / 256, 256>>>();
    }
    // #7 theta slice -> theta^T hi/lo
    {
        dim3 grid((NN + 31) / 32, CI / 32, BSZ);
        tsplit_kernel<<<grid, dim3(32, 8)>>>(p_tpg, p_thh, p_thl, CI, NN, (long)CTPG * NN);
    }
    // #8 phi -> phi^T hi/lo
    {
        dim3 grid((MM + 31) / 32, CI / 32, BSZ);
        tsplit_kernel<<<grid, dim3(32, 8)>>>(p_phi, p_phh, p_phl, CI, MM, (long)CI * MM);
    }
    // #9 f = thetaT @ phiT^T (per-batch)
    {
        mma128_kernel<0><<<dim3((MM + 127) / 128, (NN + 127) / 128, BSZ), 256, SMEM3>>>(
            p_thh, p_thl, p_phh, p_phl, p_f, CI, NN, MM,
            (long)NN * CI, (long)MM * CI, MM, (long)NN * MM, nullptr);
    }
    // #10 softmax -> attn hi/lo padded
    {
        int rows = BSZ * NN;
        softmax_kernel<<<(rows * 32 + 255) / 256, 256>>>();
    }
    // #11 y = g @ attn^T (per-batch)
    {
        mma128_kernel<0><<<dim3((NN + 127) / 128, CI / 128, BSZ), 256, SMEM3>>>(
            p_gph, p_gpl, p_ath, p_atl, p_y, MMP, CI, NN,
            (long)CI * MMP, (long)NN * MMP, NN, (long)CI * NN, nullptr);
    }
    // #12 y -> y^T hi/lo
    {
        dim3 grid((NN + 31) / 32, CI / 32, BSZ);
        tsplit_kernel<<<grid, dim3(32, 8)>>>(p_y, p_yhT, p_ylT, CI, NN, (long)CI * NN);
    }
    // #13 W conv, batch-flattened N, BN + residual -> out
    {
        mma128_kernel<2><<<dim3(GNTOT / 128, CC / 128, 1), 256, SMEM3>>>(
            p_wWhi, p_wWlo, p_yhT, p_ylT, out, CI, CC, GNTOT,
            0L, 0L, NN, (long)CC * NN, x);
    }
}

// round 12
// speedup vs baseline: 1.1647x; 1.0122x over previous
#include <cuda_runtime.h>
#include <cuda_bf16.h>
#include <cstdint>

// ---------------------------------------------------------------------------
// Problem constants
// ---------------------------------------------------------------------------
#define BSZ  32
#define CC   1536
#define CI   768
#define HH   14
#define WW   14
#define HJ   28
#define WJ   28
#define NN   784
#define MM   196
#define MMP  224          // MM padded to multiple of 32
#define CTPG 2304
#define GNTOT (BSZ * NN)  // 25088 = 196 * 128 exactly

// ---------------------------------------------------------------------------
// Scratch (device globals)
// ---------------------------------------------------------------------------
__device__ __align__(16) __nv_bfloat16 g_xhT[(size_t)BSZ * NN * CC];
__device__ __align__(16) __nv_bfloat16 g_xlT[(size_t)BSZ * NN * CC];
__device__ float g_tpg [(size_t)BSZ * CTPG * NN];
__device__ __align__(16) __nv_bfloat16 g_thh[(size_t)BSZ * NN * CI];
__device__ __align__(16) __nv_bfloat16 g_thl[(size_t)BSZ * NN * CI];
__device__ float g_phi [(size_t)BSZ * CI * MM];
__device__ __align__(16) __nv_bfloat16 g_phh[(size_t)BSZ * MM * CI];
__device__ __align__(16) __nv_bfloat16 g_phl[(size_t)BSZ * MM * CI];
__device__ __align__(16) __nv_bfloat16 g_gph[(size_t)BSZ * CI * MMP];
__device__ __align__(16) __nv_bfloat16 g_gpl[(size_t)BSZ * CI * MMP];
__device__ float g_f   [(size_t)BSZ * NN * MM];
__device__ __align__(16) __nv_bfloat16 g_ath[(size_t)BSZ * NN * MMP];
__device__ __align__(16) __nv_bfloat16 g_atl[(size_t)BSZ * NN * MMP];
__device__ float g_y   [(size_t)BSZ * CI * NN];
__device__ __align__(16) __nv_bfloat16 g_yhT[(size_t)BSZ * NN * CI];
__device__ __align__(16) __nv_bfloat16 g_ylT[(size_t)BSZ * NN * CI];
__device__ __align__(16) __nv_bfloat16 g_whi[(size_t)CTPG * CC];
__device__ __align__(16) __nv_bfloat16 g_wlo[(size_t)CTPG * CC];
__device__ __align__(16) __nv_bfloat16 g_wWhi[(size_t)CC * CI];
__device__ __align__(16) __nv_bfloat16 g_wWlo[(size_t)CC * CI];
__device__ float g_bstk[CTPG];
__device__ float g_escale[CC];
__device__ float g_eshift[CC];

// ---------------------------------------------------------------------------
// PTX helpers (base ISA only — harness's ptxas targets plain sm_103)
// ---------------------------------------------------------------------------
__device__ __forceinline__ uint32_t smem_u32(const void* p) {
    uint32_t a;
    asm("{ .reg .u64 t; cvta.to.shared.u64 t, %1; cvt.u32.u64 %0, t; }" : "=r"(a) : "l"(p));
    return a;
}
__device__ __forceinline__ void ldm_x4(uint32_t* r, uint32_t addr) {
    asm volatile("ldmatrix.sync.aligned.m8n8.x4.shared.b16 {%0,%1,%2,%3}, [%4];"
                 : "=r"(r[0]), "=r"(r[1]), "=r"(r[2]), "=r"(r[3]) : "r"(addr));
}
__device__ __forceinline__ void mma16816(float* d, const uint32_t* a, uint32_t b0, uint32_t b1) {
    asm volatile("mma.sync.aligned.m16n8k16.row.col.f32.bf16.bf16.f32 "
                 "{%0,%1,%2,%3}, {%4,%5,%6,%7}, {%8,%9}, {%0,%1,%2,%3};"
                 : "+f"(d[0]), "+f"(d[1]), "+f"(d[2]), "+f"(d[3])
                 : "r"(a[0]), "r"(a[1]), "r"(a[2]), "r"(a[3]), "r"(b0), "r"(b1));
}
__device__ __forceinline__ void cpa16(uint32_t dst, const void* src, int srcsz) {
    asm volatile("cp.async.cg.shared.global [%0], [%1], 16, %2;"
                 :: "r"(dst), "l"(src), "r"(srcsz));
}
__device__ __forceinline__ void cpa16u(uint32_t dst, const void* src) {
    asm volatile("cp.async.cg.shared.global [%0], [%1], 16;"
                 :: "r"(dst), "l"(src));
}
#define CPA_COMMIT()  asm volatile("cp.async.commit_group;" ::: "memory")
#define CPA_WAIT(n)   asm volatile("cp.async.wait_group %0;" :: "n"(n) : "memory")

// ---------------------------------------------------------------------------
// fused joint-gather + transpose + bf16 hi/lo split: x -> xjT [b][n][c]
// ---------------------------------------------------------------------------
__global__ void tsplitX_kernel(const float* __restrict__ x) {
    __shared__ float t[32][33];
    int b = blockIdx.z;
    int c0 = blockIdx.y * 32, n0 = blockIdx.x * 32;
    int tx = threadIdx.x, ty = threadIdx.y;
#pragma unroll
    for (int s = 0; s < 32; s += 8) {
        int c = c0 + ty + s, n = n0 + tx;
        float v = 0.f;
        if (n < NN) {
            int hj = n / WJ, wj = n % WJ;
            int vv = ((hj >= HH) ? 2 : 0) + ((wj >= WW) ? 1 : 0);
            int hl = (hj >= HH) ? hj - HH : hj;
            int wl = (wj >= WW) ? wj - WW : wj;
            v = x[(((long)(b * 4 + vv) * CC + c) * HH + hl) * WW + wl];
        }
        t[ty + s][tx] = v;
    }
    __syncthreads();
    long ob = (long)b * NN * CC;
#pragma unroll
    for (int s = 0; s < 32; s += 8) {
        int n = n0 + ty + s, c = c0 + tx;
        if (n < NN) {
            float v = t[tx][ty + s];
            __nv_bfloat16 h = __float2bfloat16(v);
            g_xhT[ob + (long)n * CC + c] = h;
            g_xlT[ob + (long)n * CC + c] = __float2bfloat16(v - __bfloat162float(h));
        }
    }
}

// ---------------------------------------------------------------------------
// generic tiled transpose + bf16 hi/lo split
// ---------------------------------------------------------------------------
__global__ void tsplit_kernel(const float* __restrict__ in,
                              __nv_bfloat16* __restrict__ hi,
                              __nv_bfloat16* __restrict__ lo,
                              int R, int Cn, long inStride) {
    __shared__ float t[32][33];
    int b = blockIdx.z;
    int r0 = blockIdx.y * 32, c0 = blockIdx.x * 32;
    const float* ib = in + (long)b * inStride;
    int tx = threadIdx.x, ty = threadIdx.y;
#pragma unroll
    for (int s = 0; s < 32; s += 8) {
        int r = r0 + ty + s, c = c0 + tx;
        t[ty + s][tx] = (r < R && c < Cn) ? ib[(long)r * Cn + c] : 0.f;
    }
    __syncthreads();
    long ob = (long)b * Cn * R;
#pragma unroll
    for (int s = 0; s < 32; s += 8) {
        int c = c0 + ty + s, r = r0 + tx;
        if (c < Cn && r < R) {
            float v = t[tx][ty + s];
            __nv_bfloat16 h = __float2bfloat16(v);
            hi[ob + (long)c * R + r] = h;
            lo[ob + (long)c * R + r] = __float2bfloat16(v - __bfloat162float(h));
        }
    }
}

// ---------------------------------------------------------------------------
// weight prep
// ---------------------------------------------------------------------------
__global__ void wsplit_stack_kernel(const float* __restrict__ wt, const float* __restrict__ wp,
                                    const float* __restrict__ wg, const float* __restrict__ bt,
                                    const float* __restrict__ bp, const float* __restrict__ bg) {
    long idx = (long)blockIdx.x * blockDim.x + threadIdx.x;
    if (idx < (long)CTPG * CC) {
        int r = (int)(idx / CC), c = (int)(idx % CC);
        const float* src = (r < CI) ? wt : ((r < 2 * CI) ? wp : wg);
        int rr = (r < CI) ? r : ((r < 2 * CI) ? r - CI : r - 2 * CI);
        float v = src[(long)rr * CC + c];
        __nv_bfloat16 h = __float2bfloat16(v);
        g_whi[idx] = h;
        g_wlo[idx] = __float2bfloat16(v - __bfloat162float(h));
    }
    if (idx < CTPG) {
        int r = (int)idx;
        g_bstk[r] = (r < CI) ? bt[r] : ((r < 2 * CI) ? bp[r - CI] : bg[r - 2 * CI]);
    }
}

__global__ void wsplitW_kernel(const float* __restrict__ wW) {
    long idx = (long)blockIdx.x * blockDim.x + threadIdx.x;
    if (idx >= (long)CC * CI) return;
    float v = wW[idx];
    __nv_bfloat16 h = __float2bfloat16(v);
    g_wWhi[idx] = h;
    g_wWlo[idx] = __float2bfloat16(v - __bfloat162float(h));
}

__global__ void bnprep_kernel(const float* __restrict__ gamma, const float* __restrict__ beta,
                              const float* __restrict__ mean, const float* __restrict__ var,
                              const float* __restrict__ bW) {
    int m = blockIdx.x * blockDim.x + threadIdx.x;
    if (m < CC) {
        float s = gamma[m] * rsqrtf(var[m] + 1e-5f);
        g_escale[m] = s;
        g_eshift[m] = beta[m] - mean[m] * s + bW[m] * s;
    }
}

// ---------------------------------------------------------------------------
// 2x2 maxpool: phi -> fp32 [c][196]; g -> bf16 hi/lo [c][224] padded
// ---------------------------------------------------------------------------
__global__ void pool_kernel() {
    int idx = blockIdx.x * blockDim.x + threadIdx.x;
    const int totPhi = BSZ * CI * MM;
    const int totG = BSZ * CI * MMP;
    if (idx < totPhi) {
        int m = idx % MM;
        int c = (idx / MM) % CI;
        int b = idx / (MM * CI);
        int hm = m / 14, wm = m % 14;
        const float* src = g_tpg + ((long)b * CTPG + CI + c) * NN;
        int base = (2 * hm) * WJ + 2 * wm;
        g_phi[idx] = fmaxf(fmaxf(src[base], src[base + 1]),
                           fmaxf(src[base + WJ], src[base + WJ + 1]));
    } else if (idx < totPhi + totG) {
        int r = idx - totPhi;
        int j = r % MMP;
        int c = (r / MMP) % CI;
        int b = r / (MMP * CI);
        float v = 0.f;
        if (j < MM) {
            int hm = j / 14, wm = j % 14;
            const float* src = g_tpg + ((long)b * CTPG + 2 * CI + c) * NN;
            int base = (2 * hm) * WJ + 2 * wm;
            v = fmaxf(fmaxf(src[base], src[base + 1]),
                      fmaxf(src[base + WJ], src[base + WJ + 1]));
        }
        __nv_bfloat16 h = __float2bfloat16(v);
        g_gph[r] = h;
        g_gpl[r] = (j < MM) ? __float2bfloat16(v - __bfloat162float(h)) : __nv_bfloat16(0.f);
    }
}

// ---------------------------------------------------------------------------
// row softmax over MM=196 -> attn hi/lo bf16 padded [n][224]
// ---------------------------------------------------------------------------
__global__ void softmax_kernel() {
    int warp = (blockIdx.x * blockDim.x + threadIdx.x) >> 5;
    int lane = threadIdx.x & 31;
    if (warp >= BSZ * NN) return;
    const float* row = g_f + (long)warp * MM;
    __nv_bfloat16* oh = g_ath + (long)warp * MMP;
    __nv_bfloat16* ol = g_atl + (long)warp * MMP;
    float vals[7];
    float mx = -1e30f;
#pragma unroll
    for (int s = 0; s < 7; s++) {
        int i = lane + s * 32;
        vals[s] = (i < MM) ? row[i] : -1e30f;
        mx = fmaxf(mx, vals[s]);
    }
#pragma unroll
    for (int o = 16; o; o >>= 1) mx = fmaxf(mx, __shfl_xor_sync(0xffffffffu, mx, o));
    float sum = 0.f;
#pragma unroll
    for (int s = 0; s < 7; s++) {
        int i = lane + s * 32;
        vals[s] = (i < MM) ? __expf(vals[s] - mx) : 0.f;
        sum += vals[s];
    }
#pragma unroll
    for (int o = 16; o; o >>= 1) sum += __shfl_xor_sync(0xffffffffu, sum, o);
    float inv = 1.f / sum;
#pragma unroll
    for (int s = 0; s < 7; s++) {
        int i = lane + s * 32;   // 0..223 == MMP
        float v = vals[s] * inv;
        __nv_bfloat16 h = __float2bfloat16(v);
        oh[i] = h;
        ol[i] = __float2bfloat16(v - __bfloat162float(h));
    }
}

// ---------------------------------------------------------------------------
// fused-pass bf16-split tensor GEMM (mma.sync m16n8k16).
//   128x128 CTA tile, 256 threads, 2 CTAs/SM, 3-stage cp.async pipeline,
//   swizzled 64B-row smem tiles, single __syncthreads per K-chunk.
//   Per K-chunk: load Ahi/Alo/Bhi/Blo once; mma hi*hi + hi*lo + lo*hi.
//   EPI 0: per-batch (blockIdx.z) fp32 store, M/N bounds
//   EPI 1: batch-flattened N (blockIdx: x=M tiles, y=N tiles); +g_bstk[m]
//   EPI 2: batch-flattened N; BN-fold + residual from g_xhT+g_xlT (coalesced)
// ---------------------------------------------------------------------------
#define GTILE (128 * 32)            // bf16 elems per tile (128 rows x 64B)
#define ST    (4 * GTILE)           // per-stage: [Ahi | Bhi | Alo | Blo]
#define SMEM3 (3 * ST * 2)          // 98304 B

// swizzled element offset within a tile: row-major 64B rows, 16B segs XORed
__device__ __forceinline__ int swz(int row, int seg) {
    return row * 32 + ((seg ^ ((row >> 1) & 3)) << 3);
}

template <int EPI>
__global__ void __launch_bounds__(256, 2)
mma128_kernel(const __nv_bfloat16* __restrict__ Ahi, const __nv_bfloat16* __restrict__ Alo,
              const __nv_bfloat16* __restrict__ Bhi, const __nv_bfloat16* __restrict__ Blo,
              float* __restrict__ Cp, int K, int MV, int NB,
              long strideA, long strideB, int ldC, long sC) {
    extern __shared__ __align__(16) __nv_bfloat16 smem[];
    constexpr bool GN = (EPI == 1) || (EPI == 2);   // batch-flattened N

    const int tid = threadIdx.x;
    const int lane = tid & 31;
    const int wid = tid >> 5;
    const int wm = wid & 1;          // 2 M-warps -> 64 rows
    const int wn = wid >> 1;         // 4 N-warps -> 32 cols
    // GN mode: x = M tiles (few), y = N tiles (many) -> wave covers all M
    // tiles for a band of N tiles => B tiles served from L2 (18x/12x reuse).
    const int m0 = (GN ? blockIdx.x : blockIdx.y) * 128;
    const int n0 = (GN ? blockIdx.y : blockIdx.x) * 128;
    const int b  = blockIdx.z;       // 0 in GN mode

    const int NK = K / 32;
    const __nv_bfloat16* A0 = Ahi + (long)b * strideA + (long)m0 * K;
    const __nv_bfloat16* A1 = Alo + (long)b * strideA + (long)m0 * K;
    const __nv_bfloat16* B0 = Bhi + (long)b * strideB;
    const __nv_bfloat16* B1 = Blo + (long)b * strideB;

    float acc[4][4][4];
#pragma unroll
    for (int i = 0; i < 4; i++)
#pragma unroll
        for (int j = 0; j < 4; j++)
#pragma unroll
            for (int r = 0; r < 4; r++) acc[i][j][r] = 0.f;

    auto loadChunk = [&](int g, int stage) {
        long kc = (long)g * 32;
        __nv_bfloat16* st = smem + stage * ST;
#pragma unroll
        for (int i = 0; i < 2; i++) {
            int idx = tid + i * 256;
            int row = idx >> 2, seg = idx & 3;
            int off = swz(row, seg);
            long ga = (long)row * K + kc + seg * 8;
            if (GN) {
                long gb = (long)(n0 + row) * K + kc + seg * 8;
                cpa16u(smem_u32(st + off), A0 + ga);
                cpa16u(smem_u32(st + GTILE + off), B0 + gb);
                cpa16u(smem_u32(st + 2 * GTILE + off), A1 + ga);
                cpa16u(smem_u32(st + 3 * GTILE + off), B1 + gb);
            } else {
                int okA = (m0 + row) < MV;
                int okB = (n0 + row) < NB;
                long gb = (long)(okB ? (n0 + row) : 0) * K + kc + seg * 8;
                cpa16(smem_u32(st + off), A0 + ga, okA ? 16 : 0);
                cpa16(smem_u32(st + GTILE + off), B0 + gb, okB ? 16 : 0);
                cpa16(smem_u32(st + 2 * GTILE + off), A1 + ga, okA ? 16 : 0);
                cpa16(smem_u32(st + 3 * GTILE + off), B1 + gb, okB ? 16 : 0);
            }
        }
    };

    loadChunk(0, 0); CPA_COMMIT();
    loadChunk(1, 1); CPA_COMMIT();

    int cs = 0;   // compute stage
    int ls = 2;   // next load stage
    for (int g = 0; g < NK; g++) {
        if (g + 1 < NK) { CPA_WAIT(1); } else { CPA_WAIT(0); }
        __syncthreads();
        if (g + 2 < NK) {
            loadChunk(g + 2, ls);
            CPA_COMMIT();
            ls = (ls == 2) ? 0 : ls + 1;
        }
        const __nv_bfloat16* st = smem + cs * ST;
        cs = (cs == 2) ? 0 : cs + 1;

#pragma unroll
        for (int ks = 0; ks < 2; ks++) {
            const int aRow = wm * 64 + ((lane >> 3) & 1) * 8 + (lane & 7);
            const int aSeg = ks * 2 + (lane >> 4);
            const int bRow = wn * 32 + (lane >> 4) * 8 + (lane & 7);
            const int bSeg = ks * 2 + ((lane >> 3) & 1);

            uint32_t bh[2][4];
#pragma unroll
            for (int ni = 0; ni < 2; ni++)
                ldm_x4(bh[ni], smem_u32(st + GTILE + swz(bRow + ni * 16, bSeg)));

            uint32_t a[4][4];
#pragma unroll
            for (int mi = 0; mi < 4; mi++)
                ldm_x4(a[mi], smem_u32(st + swz(aRow + mi * 16, aSeg)));

            // hi * hi
#pragma unroll
            for (int mi = 0; mi < 4; mi++)
#pragma unroll
                for (int nj = 0; nj < 4; nj++)
                    mma16816(acc[mi][nj], a[mi],
                             bh[nj >> 1][(nj & 1) * 2], bh[nj >> 1][(nj & 1) * 2 + 1]);

            // hi * lo
            uint32_t bl[2][4];
#pragma unroll
            for (int ni = 0; ni < 2; ni++)
                ldm_x4(bl[ni], smem_u32(st + 3 * GTILE + swz(bRow + ni * 16, bSeg)));
#pragma unroll
            for (int mi = 0; mi < 4; mi++)
#pragma unroll
                for (int nj = 0; nj < 4; nj++)
                    mma16816(acc[mi][nj], a[mi],
                             bl[nj >> 1][(nj & 1) * 2], bl[nj >> 1][(nj & 1) * 2 + 1]);

            // lo * hi (reuse a regs)
#pragma unroll
            for (int mi = 0; mi < 4; mi++)
                ldm_x4(a[mi], smem_u32(st + 2 * GTILE + swz(aRow + mi * 16, aSeg)));
#pragma unroll
            for (int mi = 0; mi < 4; mi++)
#pragma unroll
                for (int nj = 0; nj < 4; nj++)
                    mma16816(acc[mi][nj], a[mi],
                             bh[nj >> 1][(nj & 1) * 2], bh[nj >> 1][(nj & 1) * 2 + 1]);
        }
    }

    // ---- epilogue ----
    const int mbase = m0 + wm * 64;
    const int nbase = n0 + wn * 32;
#pragma unroll
    for (int mi = 0; mi < 4; mi++) {
        int mr0 = mbase + mi * 16 + (lane >> 2);
        int mr1 = mr0 + 8;
        bool ok0 = GN ? true : (mr0 < MV);
        bool ok1 = GN ? true : (mr1 < MV);
        float es0 = 1.f, eh0 = 0.f, es1 = 1.f, eh1 = 0.f;
        if (EPI == 1) { eh0 = g_bstk[mr0]; eh1 = g_bstk[mr1]; }
        if (EPI == 2) {
            es0 = g_escale[mr0]; eh0 = g_eshift[mr0];
            es1 = g_escale[mr1]; eh1 = g_eshift[mr1];
        }
#pragma unroll
        for (int nj = 0; nj < 4; nj++) {
            int n = nbase + nj * 8 + (lane & 3) * 2;
            float2 v0 = make_float2(acc[mi][nj][0], acc[mi][nj][1]);
            float2 v1 = make_float2(acc[mi][nj][2], acc[mi][nj][3]);
            if (GN) {
                int bcol = n / NN;
                int nl = n - bcol * NN;
                float* Cb = Cp + (long)bcol * sC;
                if (EPI == 2) {
                    // residual = joint(x) reconstructed from bf16 hi+lo
                    // (layout [gn][c]: contiguous in mr -> coalesced loads)
#pragma unroll
                    for (int e = 0; e < 2; e++) {
                        long rbase = (long)(n + e) * CC;
                        float r0 = __bfloat162float(g_xhT[rbase + mr0]) +
                                   __bfloat162float(g_xlT[rbase + mr0]);
                        float r1 = __bfloat162float(g_xhT[rbase + mr1]) +
                                   __bfloat162float(g_xlT[rbase + mr1]);
                        if (e == 0) { v0.x = v0.x * es0 + eh0 + r0; v1.x = v1.x * es1 + eh1 + r1; }
                        else        { v0.y = v0.y * es0 + eh0 + r0; v1.y = v1.y * es1 + eh1 + r1; }
                    }
                } else {
                    v0.x += eh0; v0.y += eh0; v1.x += eh1; v1.y += eh1;
                }
                *(float2*)(Cb + (long)mr0 * ldC + nl) = v0;
                *(float2*)(Cb + (long)mr1 * ldC + nl) = v1;
            } else {
                if (n >= NB) continue;
                float* Cb = Cp + (long)b * sC;
                if (ok0) *(float2*)(Cb + (long)mr0 * ldC + n) = v0;
                if (ok1) *(float2*)(Cb + (long)mr1 * ldC + n) = v1;
            }
        }
    }
}

// ---------------------------------------------------------------------------
// Launch
// ---------------------------------------------------------------------------
extern "C" void kernel_launch(void* const* d_in, const int* in_sizes, int n_in,
                              void* d_out, int out_size) {
    const float* x     = (const float*)d_in[0];
    const float* wt    = (const float*)d_in[1];
    const float* bt    = (const float*)d_in[2];
    const float* wp    = (const float*)d_in[3];
    const float* bp    = (const float*)d_in[4];
    const float* wg    = (const float*)d_in[5];
    const float* bg    = (const float*)d_in[6];
    const float* wW    = (const float*)d_in[7];
    const float* bW    = (const float*)d_in[8];
    const float* gamma = (const float*)d_in[9];
    const float* beta  = (const float*)d_in[10];
    const float* mean  = (const float*)d_in[11];
    const float* var   = (const float*)d_in[12];
    float* out = (float*)d_out;

    float *p_tpg, *p_phi, *p_f, *p_y;
    __nv_bfloat16 *p_xhT, *p_xlT, *p_thh, *p_thl, *p_phh, *p_phl;
    __nv_bfloat16 *p_gph, *p_gpl, *p_ath, *p_atl, *p_yhT, *p_ylT;
    __nv_bfloat16 *p_whi, *p_wlo, *p_wWhi, *p_wWlo;
    cudaGetSymbolAddress((void**)&p_tpg, g_tpg);
    cudaGetSymbolAddress((void**)&p_phi, g_phi);
    cudaGetSymbolAddress((void**)&p_f, g_f);
    cudaGetSymbolAddress((void**)&p_y, g_y);
    cudaGetSymbolAddress((void**)&p_xhT, g_xhT);
    cudaGetSymbolAddress((void**)&p_xlT, g_xlT);
    cudaGetSymbolAddress((void**)&p_thh, g_thh);
    cudaGetSymbolAddress((void**)&p_thl, g_thl);
    cudaGetSymbolAddress((void**)&p_phh, g_phh);
    cudaGetSymbolAddress((void**)&p_phl, g_phl);
    cudaGetSymbolAddress((void**)&p_gph, g_gph);
    cudaGetSymbolAddress((void**)&p_gpl, g_gpl);
    cudaGetSymbolAddress((void**)&p_ath, g_ath);
    cudaGetSymbolAddress((void**)&p_atl, g_atl);
    cudaGetSymbolAddress((void**)&p_yhT, g_yhT);
    cudaGetSymbolAddress((void**)&p_ylT, g_ylT);
    cudaGetSymbolAddress((void**)&p_whi, g_whi);
    cudaGetSymbolAddress((void**)&p_wlo, g_wlo);
    cudaGetSymbolAddress((void**)&p_wWhi, g_wWhi);
    cudaGetSymbolAddress((void**)&p_wWlo, g_wWlo);

    cudaFuncSetAttribute((const void*)mma128_kernel<0>,
                         cudaFuncAttributeMaxDynamicSharedMemorySize, SMEM3);
    cudaFuncSetAttribute((const void*)mma128_kernel<1>,
                         cudaFuncAttributeMaxDynamicSharedMemorySize, SMEM3);
    cudaFuncSetAttribute((const void*)mma128_kernel<2>,
                         cudaFuncAttributeMaxDynamicSharedMemorySize, SMEM3);

    // #1 weight stack+split
    {
        long total = (long)CTPG * CC;
        wsplit_stack_kernel<<<(unsigned)((total + 255) / 256), 256>>>(wt, wp, wg, bt, bp, bg);
    }
    // #2 fused joint + transpose + split
    {
        dim3 grid((NN + 31) / 32, CC / 32, BSZ);
        tsplitX_kernel<<<grid, dim3(32, 8)>>>(x);
    }
    // #3 BN prep (keeps GEMM1 at launch #4 for ncu)
    bnprep_kernel<<<(CC + 255) / 256, 256>>>(gamma, beta, mean, var, bW);
    // #4 stacked theta|phi|g conv, batch-flattened N; x = M tiles (L2 reuse)
    {
        mma128_kernel<1><<<dim3(CTPG / 128, GNTOT / 128, 1), 256, SMEM3>>>(
            p_whi, p_wlo, p_xhT, p_xlT, p_tpg, CC, CTPG, GNTOT,
            0L, 0L, NN, (long)CTPG * NN);
    }
    // #5 W-conv weight split
    wsplitW_kernel<<<(unsigned)(((long)CC * CI + 255) / 256), 256>>>(wW);
    // #6 pool
    {
        int total = BSZ * CI * (MM + MMP);
        pool_kernel<<<(total + 255) / 256, 256>>>();
    }
    // #7 theta slice -> theta^T hi/lo
    {
        dim3 grid((NN + 31) / 32, CI / 32, BSZ);
        tsplit_kernel<<<grid, dim3(32, 8)>>>(p_tpg, p_thh, p_thl, CI, NN, (long)CTPG * NN);
    }
    // #8 phi -> phi^T hi/lo
    {
        dim3 grid((MM + 31) / 32, CI / 32, BSZ);
        tsplit_kernel<<<grid, dim3(32, 8)>>>(p_phi, p_phh, p_phl, CI, MM, (long)CI * MM);
    }
    // #9 f = thetaT @ phiT^T (per-batch)
    {
        mma128_kernel<0><<<dim3((MM + 127) / 128, (NN + 127) / 128, BSZ), 256, SMEM3>>>(
            p_thh, p_thl, p_phh, p_phl, p_f, CI, NN, MM,
            (long)NN * CI, (long)MM * CI, MM, (long)NN * MM);
    }
    // #10 softmax -> attn hi/lo padded
    {
        int rows = BSZ * NN;
        softmax_kernel<<<(rows * 32 + 255) / 256, 256>>>();
    }
    // #11 y = g @ attn^T (per-batch)
    {
        mma128_kernel<0><<<dim3((NN + 127) / 128, CI / 128, BSZ), 256, SMEM3>>>(
            p_gph, p_gpl, p_ath, p_atl, p_y, MMP, CI, NN,
            (long)CI * MMP, (long)NN * MMP, NN, (long)CI * NN);
    }
    // #12 y -> y^T hi/lo
    {
        dim3 grid((NN + 31) / 32, CI / 32, BSZ);
        tsplit_kernel<<<grid, dim3(32, 8)>>>(p_y, p_yhT, p_ylT, CI, NN, (long)CI * NN);
    }
    // #13 W conv, batch-flattened N, BN + residual(g_xhT+g_xlT) -> out
    {
        mma128_kernel<2><<<dim3(CC / 128, GNTOT / 128, 1), 256, SMEM3>>>(
            p_wWhi, p_wWlo, p_yhT, p_ylT, out, CI, CC, GNTOT,
            0L, 0L, NN, (long)CC * NN);
    }
}

// round 13
// speedup vs baseline: 1.1720x; 1.0063x over previous
#include <cuda_runtime.h>
#include <cuda_bf16.h>
#include <cstdint>

// ---------------------------------------------------------------------------
// Problem constants
// ---------------------------------------------------------------------------
#define BSZ  32
#define CC   1536
#define CI   768
#define HH   14
#define WW   14
#define HJ   28
#define WJ   28
#define NN   784
#define MM   196
#define MMP  224          // pooled K padded to multiple of 32
#define CTPG 2304
#define GNTOT (BSZ * NN)  // 25088 = 196 * 128 exactly

// ---------------------------------------------------------------------------
// Scratch (device globals)
// ---------------------------------------------------------------------------
__device__ __align__(16) __nv_bfloat16 g_xhT[(size_t)BSZ * NN * CC];
__device__ __align__(16) __nv_bfloat16 g_xlT[(size_t)BSZ * NN * CC];
__device__ float g_tpg [(size_t)BSZ * CTPG * NN];
__device__ __align__(16) __nv_bfloat16 g_thh[(size_t)BSZ * NN * CI];
__device__ __align__(16) __nv_bfloat16 g_thl[(size_t)BSZ * NN * CI];
__device__ float g_phi [(size_t)BSZ * CI * MM];
__device__ __align__(16) __nv_bfloat16 g_phh[(size_t)BSZ * MM * CI];
__device__ __align__(16) __nv_bfloat16 g_phl[(size_t)BSZ * MM * CI];
__device__ __align__(16) __nv_bfloat16 g_gph[(size_t)BSZ * CI * MMP];
__device__ __align__(16) __nv_bfloat16 g_gpl[(size_t)BSZ * CI * MMP];
__device__ __align__(16) __nv_bfloat16 g_yhT[(size_t)BSZ * NN * CI];
__device__ __align__(16) __nv_bfloat16 g_ylT[(size_t)BSZ * NN * CI];
__device__ __align__(16) __nv_bfloat16 g_whi[(size_t)CTPG * CC];
__device__ __align__(16) __nv_bfloat16 g_wlo[(size_t)CTPG * CC];
__device__ __align__(16) __nv_bfloat16 g_wWhi[(size_t)CC * CI];
__device__ __align__(16) __nv_bfloat16 g_wWlo[(size_t)CC * CI];
__device__ float g_bstk[CTPG];
__device__ float g_escale[CC];
__device__ float g_eshift[CC];

// ---------------------------------------------------------------------------
// PTX helpers (base ISA only — harness's ptxas targets plain sm_103)
// ---------------------------------------------------------------------------
__device__ __forceinline__ uint32_t smem_u32(const void* p) {
    uint32_t a;
    asm("{ .reg .u64 t; cvta.to.shared.u64 t, %1; cvt.u32.u64 %0, t; }" : "=r"(a) : "l"(p));
    return a;
}
__device__ __forceinline__ void ldm_x4(uint32_t* r, uint32_t addr) {
    asm volatile("ldmatrix.sync.aligned.m8n8.x4.shared.b16 {%0,%1,%2,%3}, [%4];"
                 : "=r"(r[0]), "=r"(r[1]), "=r"(r[2]), "=r"(r[3]) : "r"(addr));
}
__device__ __forceinline__ void mma16816(float* d, const uint32_t* a, uint32_t b0, uint32_t b1) {
    asm volatile("mma.sync.aligned.m16n8k16.row.col.f32.bf16.bf16.f32 "
                 "{%0,%1,%2,%3}, {%4,%5,%6,%7}, {%8,%9}, {%0,%1,%2,%3};"
                 : "+f"(d[0]), "+f"(d[1]), "+f"(d[2]), "+f"(d[3])
                 : "r"(a[0]), "r"(a[1]), "r"(a[2]), "r"(a[3]), "r"(b0), "r"(b1));
}
__device__ __forceinline__ void cpa16(uint32_t dst, const void* src, int srcsz) {
    asm volatile("cp.async.cg.shared.global [%0], [%1], 16, %2;"
                 :: "r"(dst), "l"(src), "r"(srcsz));
}
__device__ __forceinline__ void cpa16u(uint32_t dst, const void* src) {
    asm volatile("cp.async.cg.shared.global [%0], [%1], 16;"
                 :: "r"(dst), "l"(src));
}
#define CPA_COMMIT()  asm volatile("cp.async.commit_group;" ::: "memory")
#define CPA_WAIT(n)   asm volatile("cp.async.wait_group %0;" :: "n"(n) : "memory")

// swizzled element offset: row-major 64B rows, 16B segs XORed
__device__ __forceinline__ int swz(int row, int seg) {
    return row * 32 + ((seg ^ ((row >> 1) & 3)) << 3);
}

// ---------------------------------------------------------------------------
// fused joint-gather + transpose + bf16 hi/lo split: x -> xjT [b][n][c]
// ---------------------------------------------------------------------------
__global__ void tsplitX_kernel(const float* __restrict__ x) {
    __shared__ float t[32][33];
    int b = blockIdx.z;
    int c0 = blockIdx.y * 32, n0 = blockIdx.x * 32;
    int tx = threadIdx.x, ty = threadIdx.y;
#pragma unroll
    for (int s = 0; s < 32; s += 8) {
        int c = c0 + ty + s, n = n0 + tx;
        float v = 0.f;
        if (n < NN) {
            int hj = n / WJ, wj = n % WJ;
            int vv = ((hj >= HH) ? 2 : 0) + ((wj >= WW) ? 1 : 0);
            int hl = (hj >= HH) ? hj - HH : hj;
            int wl = (wj >= WW) ? wj - WW : wj;
            v = x[(((long)(b * 4 + vv) * CC + c) * HH + hl) * WW + wl];
        }
        t[ty + s][tx] = v;
    }
    __syncthreads();
    long ob = (long)b * NN * CC;
#pragma unroll
    for (int s = 0; s < 32; s += 8) {
        int n = n0 + ty + s, c = c0 + tx;
        if (n < NN) {
            float v = t[tx][ty + s];
            __nv_bfloat16 h = __float2bfloat16(v);
            g_xhT[ob + (long)n * CC + c] = h;
            g_xlT[ob + (long)n * CC + c] = __float2bfloat16(v - __bfloat162float(h));
        }
    }
}

// ---------------------------------------------------------------------------
// generic tiled transpose + bf16 hi/lo split
// ---------------------------------------------------------------------------
__global__ void tsplit_kernel(const float* __restrict__ in,
                              __nv_bfloat16* __restrict__ hi,
                              __nv_bfloat16* __restrict__ lo,
                              int R, int Cn, long inStride) {
    __shared__ float t[32][33];
    int b = blockIdx.z;
    int r0 = blockIdx.y * 32, c0 = blockIdx.x * 32;
    const float* ib = in + (long)b * inStride;
    int tx = threadIdx.x, ty = threadIdx.y;
#pragma unroll
    for (int s = 0; s < 32; s += 8) {
        int r = r0 + ty + s, c = c0 + tx;
        t[ty + s][tx] = (r < R && c < Cn) ? ib[(long)r * Cn + c] : 0.f;
    }
    __syncthreads();
    long ob = (long)b * Cn * R;
#pragma unroll
    for (int s = 0; s < 32; s += 8) {
        int c = c0 + ty + s, r = r0 + tx;
        if (c < Cn && r < R) {
            float v = t[tx][ty + s];
            __nv_bfloat16 h = __float2bfloat16(v);
            hi[ob + (long)c * R + r] = h;
            lo[ob + (long)c * R + r] = __float2bfloat16(v - __bfloat162float(h));
        }
    }
}

// ---------------------------------------------------------------------------
// weight prep
// ---------------------------------------------------------------------------
__global__ void wsplit_stack_kernel(const float* __restrict__ wt, const float* __restrict__ wp,
                                    const float* __restrict__ wg, const float* __restrict__ bt,
                                    const float* __restrict__ bp, const float* __restrict__ bg) {
    long idx = (long)blockIdx.x * blockDim.x + threadIdx.x;
    if (idx < (long)CTPG * CC) {
        int r = (int)(idx / CC), c = (int)(idx % CC);
        const float* src = (r < CI) ? wt : ((r < 2 * CI) ? wp : wg);
        int rr = (r < CI) ? r : ((r < 2 * CI) ? r - CI : r - 2 * CI);
        float v = src[(long)rr * CC + c];
        __nv_bfloat16 h = __float2bfloat16(v);
        g_whi[idx] = h;
        g_wlo[idx] = __float2bfloat16(v - __bfloat162float(h));
    }
    if (idx < CTPG) {
        int r = (int)idx;
        g_bstk[r] = (r < CI) ? bt[r] : ((r < 2 * CI) ? bp[r - CI] : bg[r - 2 * CI]);
    }
}

__global__ void wsplitW_kernel(const float* __restrict__ wW) {
    long idx = (long)blockIdx.x * blockDim.x + threadIdx.x;
    if (idx >= (long)CC * CI) return;
    float v = wW[idx];
    __nv_bfloat16 h = __float2bfloat16(v);
    g_wWhi[idx] = h;
    g_wWlo[idx] = __float2bfloat16(v - __bfloat162float(h));
}

__global__ void bnprep_kernel(const float* __restrict__ gamma, const float* __restrict__ beta,
                              const float* __restrict__ mean, const float* __restrict__ var,
                              const float* __restrict__ bW) {
    int m = blockIdx.x * blockDim.x + threadIdx.x;
    if (m < CC) {
        float s = gamma[m] * rsqrtf(var[m] + 1e-5f);
        g_escale[m] = s;
        g_eshift[m] = beta[m] - mean[m] * s + bW[m] * s;
    }
}

// ---------------------------------------------------------------------------
// 2x2 maxpool: phi -> fp32 [c][196]; g -> bf16 hi/lo [c][224] padded
// ---------------------------------------------------------------------------
__global__ void pool_kernel() {
    int idx = blockIdx.x * blockDim.x + threadIdx.x;
    const int totPhi = BSZ * CI * MM;
    const int totG = BSZ * CI * MMP;
    if (idx < totPhi) {
        int m = idx % MM;
        int c = (idx / MM) % CI;
        int b = idx / (MM * CI);
        int hm = m / 14, wm = m % 14;
        const float* src = g_tpg + ((long)b * CTPG + CI + c) * NN;
        int base = (2 * hm) * WJ + 2 * wm;
        g_phi[idx] = fmaxf(fmaxf(src[base], src[base + 1]),
                           fmaxf(src[base + WJ], src[base + WJ + 1]));
    } else if (idx < totPhi + totG) {
        int r = idx - totPhi;
        int j = r % MMP;
        int c = (r / MMP) % CI;
        int b = r / (MMP * CI);
        float v = 0.f;
        if (j < MM) {
            int hm = j / 14, wm = j % 14;
            const float* src = g_tpg + ((long)b * CTPG + 2 * CI + c) * NN;
            int base = (2 * hm) * WJ + 2 * wm;
            v = fmaxf(fmaxf(src[base], src[base + 1]),
                      fmaxf(src[base + WJ], src[base + WJ + 1]));
        }
        __nv_bfloat16 h = __float2bfloat16(v);
        g_gph[r] = h;
        g_gpl[r] = (j < MM) ? __float2bfloat16(v - __bfloat162float(h)) : __nv_bfloat16(0.f);
    }
}

// ---------------------------------------------------------------------------
// fused-pass bf16-split tensor GEMM (unchanged core; EPI 1 & 2 only)
// ---------------------------------------------------------------------------
#define GTILE (128 * 32)
#define ST    (4 * GTILE)
#define SMEM3 (3 * ST * 2)          // 98304 B

template <int EPI>
__global__ void __launch_bounds__(256, 2)
mma128_kernel(const __nv_bfloat16* __restrict__ Ahi, const __nv_bfloat16* __restrict__ Alo,
              const __nv_bfloat16* __restrict__ Bhi, const __nv_bfloat16* __restrict__ Blo,
              float* __restrict__ Cp, int K, int ldC, long sC) {
    extern __shared__ __align__(16) __nv_bfloat16 smem[];
    const int tid = threadIdx.x;
    const int lane = tid & 31;
    const int wid = tid >> 5;
    const int wm = wid & 1;
    const int wn = wid >> 1;
    const int m0 = blockIdx.x * 128;     // x = M tiles (L2 reuse of B)
    const int n0 = blockIdx.y * 128;     // y = flattened-N tiles

    const int NK = K / 32;
    const __nv_bfloat16* A0 = Ahi + (long)m0 * K;
    const __nv_bfloat16* A1 = Alo + (long)m0 * K;

    float acc[4][4][4];
#pragma unroll
    for (int i = 0; i < 4; i++)
#pragma unroll
        for (int j = 0; j < 4; j++)
#pragma unroll
            for (int r = 0; r < 4; r++) acc[i][j][r] = 0.f;

    auto loadChunk = [&](int g, int stage) {
        long kc = (long)g * 32;
        __nv_bfloat16* st = smem + stage * ST;
#pragma unroll
        for (int i = 0; i < 2; i++) {
            int idx = tid + i * 256;
            int row = idx >> 2, seg = idx & 3;
            int off = swz(row, seg);
            long ga = (long)row * K + kc + seg * 8;
            long gb = (long)(n0 + row) * K + kc + seg * 8;
            cpa16u(smem_u32(st + off), A0 + ga);
            cpa16u(smem_u32(st + GTILE + off), Bhi + gb);
            cpa16u(smem_u32(st + 2 * GTILE + off), A1 + ga);
            cpa16u(smem_u32(st + 3 * GTILE + off), Blo + gb);
        }
    };

    loadChunk(0, 0); CPA_COMMIT();
    loadChunk(1, 1); CPA_COMMIT();

    int cs = 0, ls = 2;
    for (int g = 0; g < NK; g++) {
        if (g + 1 < NK) { CPA_WAIT(1); } else { CPA_WAIT(0); }
        __syncthreads();
        if (g + 2 < NK) {
            loadChunk(g + 2, ls);
            CPA_COMMIT();
            ls = (ls == 2) ? 0 : ls + 1;
        }
        const __nv_bfloat16* st = smem + cs * ST;
        cs = (cs == 2) ? 0 : cs + 1;

#pragma unroll
        for (int ks = 0; ks < 2; ks++) {
            const int aRow = wm * 64 + ((lane >> 3) & 1) * 8 + (lane & 7);
            const int aSeg = ks * 2 + (lane >> 4);
            const int bRow = wn * 32 + (lane >> 4) * 8 + (lane & 7);
            const int bSeg = ks * 2 + ((lane >> 3) & 1);

            uint32_t bh[2][4];
#pragma unroll
            for (int ni = 0; ni < 2; ni++)
                ldm_x4(bh[ni], smem_u32(st + GTILE + swz(bRow + ni * 16, bSeg)));
            uint32_t a[4][4];
#pragma unroll
            for (int mi = 0; mi < 4; mi++)
                ldm_x4(a[mi], smem_u32(st + swz(aRow + mi * 16, aSeg)));
#pragma unroll
            for (int mi = 0; mi < 4; mi++)
#pragma unroll
                for (int nj = 0; nj < 4; nj++)
                    mma16816(acc[mi][nj], a[mi],
                             bh[nj >> 1][(nj & 1) * 2], bh[nj >> 1][(nj & 1) * 2 + 1]);
            uint32_t bl[2][4];
#pragma unroll
            for (int ni = 0; ni < 2; ni++)
                ldm_x4(bl[ni], smem_u32(st + 3 * GTILE + swz(bRow + ni * 16, bSeg)));
#pragma unroll
            for (int mi = 0; mi < 4; mi++)
#pragma unroll
                for (int nj = 0; nj < 4; nj++)
                    mma16816(acc[mi][nj], a[mi],
                             bl[nj >> 1][(nj & 1) * 2], bl[nj >> 1][(nj & 1) * 2 + 1]);
#pragma unroll
            for (int mi = 0; mi < 4; mi++)
                ldm_x4(a[mi], smem_u32(st + 2 * GTILE + swz(aRow + mi * 16, aSeg)));
#pragma unroll
            for (int mi = 0; mi < 4; mi++)
#pragma unroll
                for (int nj = 0; nj < 4; nj++)
                    mma16816(acc[mi][nj], a[mi],
                             bh[nj >> 1][(nj & 1) * 2], bh[nj >> 1][(nj & 1) * 2 + 1]);
        }
    }

    const int mbase = m0 + wm * 64;
    const int nbase = n0 + wn * 32;
#pragma unroll
    for (int mi = 0; mi < 4; mi++) {
        int mr0 = mbase + mi * 16 + (lane >> 2);
        int mr1 = mr0 + 8;
        float es0 = 1.f, eh0 = 0.f, es1 = 1.f, eh1 = 0.f;
        if (EPI == 1) { eh0 = g_bstk[mr0]; eh1 = g_bstk[mr1]; }
        if (EPI == 2) {
            es0 = g_escale[mr0]; eh0 = g_eshift[mr0];
            es1 = g_escale[mr1]; eh1 = g_eshift[mr1];
        }
#pragma unroll
        for (int nj = 0; nj < 4; nj++) {
            int n = nbase + nj * 8 + (lane & 3) * 2;
            float2 v0 = make_float2(acc[mi][nj][0], acc[mi][nj][1]);
            float2 v1 = make_float2(acc[mi][nj][2], acc[mi][nj][3]);
            int bcol = n / NN;
            int nl = n - bcol * NN;
            float* Cb = Cp + (long)bcol * sC;
            if (EPI == 2) {
#pragma unroll
                for (int e = 0; e < 2; e++) {
                    long rbase = (long)(n + e) * CC;
                    float r0 = __bfloat162float(g_xhT[rbase + mr0]) +
                               __bfloat162float(g_xlT[rbase + mr0]);
                    float r1 = __bfloat162float(g_xhT[rbase + mr1]) +
                               __bfloat162float(g_xlT[rbase + mr1]);
                    if (e == 0) { v0.x = v0.x * es0 + eh0 + r0; v1.x = v1.x * es1 + eh1 + r1; }
                    else        { v0.y = v0.y * es0 + eh0 + r0; v1.y = v1.y * es1 + eh1 + r1; }
                }
            } else {
                v0.x += eh0; v0.y += eh0; v1.x += eh1; v1.y += eh1;
            }
            *(float2*)(Cb + (long)mr0 * ldC + nl) = v0;
            *(float2*)(Cb + (long)mr1 * ldC + nl) = v1;
        }
    }
}

// ---------------------------------------------------------------------------
// Fused attention kernel. Per CTA: (batch b, 64-row query block n0).
//   Stage A: f[64][256] = theta^T(64,K=768) . phi(cols, zero-padded >=196)
//   Softmax over 196 cols (pads masked), attn -> swizzled bf16 hi/lo smem tiles
//   Stage C: yT[64][768] = attn(K=224) . g^T, stored split to g_yhT/g_ylT
// smem: stageA pipe 2x40KB @0 | attn tiles 64KB @0 | stageC pipe 32KB @64KB
//       | red 1KB @96KB.   Total 99328 B, 2 CTAs/SM.
// ---------------------------------------------------------------------------
#define FA_SMEM 99328
#define NBLK 13   // ceil(784/64)

__global__ void __launch_bounds__(256, 2)
fused_attn_kernel() {
    extern __shared__ __align__(16) __nv_bfloat16 smem[];
    const int tid = threadIdx.x;
    const int lane = tid & 31;
    const int wid = tid >> 5;
    const int wm = wid & 1;          // 2 M-warps (32 rows each)
    const int wn = wid >> 1;         // 4 N-warps
    const int n0 = blockIdx.x * 64;
    const int b = blockIdx.y;

    const __nv_bfloat16* Ah = g_thh + ((long)b * NN + n0) * CI;
    const __nv_bfloat16* Al = g_thl + ((long)b * NN + n0) * CI;
    const __nv_bfloat16* Bh = g_phh + (long)b * MM * CI;
    const __nv_bfloat16* Bl = g_phl + (long)b * MM * CI;

    // ================= stage A: f = theta^T . phi =================
    float acc[2][8][4];
#pragma unroll
    for (int i = 0; i < 2; i++)
#pragma unroll
        for (int j = 0; j < 8; j++)
#pragma unroll
            for (int r = 0; r < 4; r++) acc[i][j][r] = 0.f;

    // stage layout (elems): Ahi[0,2048) Bhi[2048,10240) Alo[10240,12288) Blo[12288,20480)
    auto loadA = [&](int g, int buf) {
        long kc = (long)g * 32;
        __nv_bfloat16* st = smem + buf * 20480;
        {
            int row = tid >> 2, seg = tid & 3;
            int off = swz(row, seg);
            int ok = (n0 + row) < NN;
            long ga = (long)row * CI + kc + seg * 8;
            cpa16(smem_u32(st + off), Ah + ga, ok ? 16 : 0);
            cpa16(smem_u32(st + 10240 + off), Al + ga, ok ? 16 : 0);
        }
#pragma unroll
        for (int i = 0; i < 4; i++) {
            int idx = tid + i * 256;
            int row = idx >> 2, seg = idx & 3;
            int off = swz(row, seg);
            int ok = row < MM;
            long gb = (long)row * CI + kc + seg * 8;
            cpa16(smem_u32(st + 2048 + off), Bh + gb, ok ? 16 : 0);
            cpa16(smem_u32(st + 12288 + off), Bl + gb, ok ? 16 : 0);
        }
    };

    loadA(0, 0); CPA_COMMIT();
    const int NKA = CI / 32;   // 24
    for (int g = 0; g < NKA; g++) {
        int buf = g & 1;
        if (g + 1 < NKA) { loadA(g + 1, buf ^ 1); CPA_COMMIT(); CPA_WAIT(1); }
        else { CPA_WAIT(0); }
        __syncthreads();
        const __nv_bfloat16* st = smem + buf * 20480;
#pragma unroll
        for (int ks = 0; ks < 2; ks++) {
            const int aRow = wm * 32 + ((lane >> 3) & 1) * 8 + (lane & 7);
            const int aSeg = ks * 2 + (lane >> 4);
            const int bRow = wn * 64 + (lane >> 4) * 8 + (lane & 7);
            const int bSeg = ks * 2 + ((lane >> 3) & 1);

            uint32_t a[2][4], b4[4][4];
#pragma unroll
            for (int mi = 0; mi < 2; mi++)
                ldm_x4(a[mi], smem_u32(st + swz(aRow + mi * 16, aSeg)));
#pragma unroll
            for (int ng = 0; ng < 4; ng++)
                ldm_x4(b4[ng], smem_u32(st + 2048 + swz(bRow + ng * 16, bSeg)));
            // hi.hi
#pragma unroll
            for (int mi = 0; mi < 2; mi++)
#pragma unroll
                for (int nj = 0; nj < 8; nj++)
                    mma16816(acc[mi][nj], a[mi],
                             b4[nj >> 1][(nj & 1) * 2], b4[nj >> 1][(nj & 1) * 2 + 1]);
            // lo.hi
#pragma unroll
            for (int mi = 0; mi < 2; mi++)
                ldm_x4(a[mi], smem_u32(st + 10240 + swz(aRow + mi * 16, aSeg)));
#pragma unroll
            for (int mi = 0; mi < 2; mi++)
#pragma unroll
                for (int nj = 0; nj < 8; nj++)
                    mma16816(acc[mi][nj], a[mi],
                             b4[nj >> 1][(nj & 1) * 2], b4[nj >> 1][(nj & 1) * 2 + 1]);
            // hi.lo
#pragma unroll
            for (int mi = 0; mi < 2; mi++)
                ldm_x4(a[mi], smem_u32(st + swz(aRow + mi * 16, aSeg)));
#pragma unroll
            for (int ng = 0; ng < 4; ng++)
                ldm_x4(b4[ng], smem_u32(st + 12288 + swz(bRow + ng * 16, bSeg)));
#pragma unroll
            for (int mi = 0; mi < 2; mi++)
#pragma unroll
                for (int nj = 0; nj < 8; nj++)
                    mma16816(acc[mi][nj], a[mi],
                             b4[nj >> 1][(nj & 1) * 2], b4[nj >> 1][(nj & 1) * 2 + 1]);
        }
        __syncthreads();
    }

    // smem regions for the rest
    __nv_bfloat16* attnHi = smem;              // [7+1 chunks][64*32]
    __nv_bfloat16* attnLo = smem + 16384;
    __nv_bfloat16* pipeC  = smem + 32768;      // 2 stages x 8192 elems
    float* red = (float*)(smem + 49152);       // 64 x 4 floats @ byte 98304

    const __nv_bfloat16* Gh = g_gph + (long)b * CI * MMP;
    const __nv_bfloat16* Gl = g_gpl + (long)b * CI * MMP;

    // prefetch first stage-C tile (pipeC region is free after mainloop sync)
    auto loadC = [&](int q, int buf) {
        int nt = q / 7, k = q - nt * 7;
        __nv_bfloat16* st = pipeC + buf * 8192;
        long kc = (long)k * 32;
#pragma unroll
        for (int i = 0; i < 2; i++) {
            int idx = tid + i * 256;
            int row = idx >> 2, seg = idx & 3;
            int off = swz(row, seg);
            long gb = (long)(nt * 128 + row) * MMP + kc + seg * 8;
            cpa16u(smem_u32(st + off), Gh + gb);
            cpa16u(smem_u32(st + 4096 + off), Gl + gb);
        }
    };
    loadC(0, 0); CPA_COMMIT();

    // ================= softmax (in registers + 1KB smem) =================
    float rowmax[2][2], rowinv[2][2];
#pragma unroll
    for (int mi = 0; mi < 2; mi++)
#pragma unroll
        for (int rh = 0; rh < 2; rh++) {
            int r = wm * 32 + mi * 16 + (lane >> 2) + rh * 8;
            float m = -1e30f;
#pragma unroll
            for (int nj = 0; nj < 8; nj++)
#pragma unroll
                for (int e = 0; e < 2; e++) {
                    int col = wn * 64 + nj * 8 + (lane & 3) * 2 + e;
                    float v = acc[mi][nj][rh * 2 + e];
                    if (col >= MM) { v = -1e30f; acc[mi][nj][rh * 2 + e] = v; }
                    m = fmaxf(m, v);
                }
            m = fmaxf(m, __shfl_xor_sync(0xffffffffu, m, 1));
            m = fmaxf(m, __shfl_xor_sync(0xffffffffu, m, 2));
            if ((lane & 3) == 0) red[r * 4 + wn] = m;
        }
    __syncthreads();
#pragma unroll
    for (int mi = 0; mi < 2; mi++)
#pragma unroll
        for (int rh = 0; rh < 2; rh++) {
            int r = wm * 32 + mi * 16 + (lane >> 2) + rh * 8;
            rowmax[mi][rh] = fmaxf(fmaxf(red[r * 4], red[r * 4 + 1]),
                                   fmaxf(red[r * 4 + 2], red[r * 4 + 3]));
        }
    __syncthreads();
#pragma unroll
    for (int mi = 0; mi < 2; mi++)
#pragma unroll
        for (int rh = 0; rh < 2; rh++) {
            int r = wm * 32 + mi * 16 + (lane >> 2) + rh * 8;
            float s = 0.f;
#pragma unroll
            for (int nj = 0; nj < 8; nj++)
#pragma unroll
                for (int e = 0; e < 2; e++) {
                    float v = __expf(acc[mi][nj][rh * 2 + e] - rowmax[mi][rh]);
                    acc[mi][nj][rh * 2 + e] = v;
                    s += v;
                }
            s += __shfl_xor_sync(0xffffffffu, s, 1);
            s += __shfl_xor_sync(0xffffffffu, s, 2);
            if ((lane & 3) == 0) red[r * 4 + wn] = s;
        }
    __syncthreads();
#pragma unroll
    for (int mi = 0; mi < 2; mi++)
#pragma unroll
        for (int rh = 0; rh < 2; rh++) {
            int r = wm * 32 + mi * 16 + (lane >> 2) + rh * 8;
            rowinv[mi][rh] = 1.f / (red[r * 4] + red[r * 4 + 1] +
                                    red[r * 4 + 2] + red[r * 4 + 3]);
        }
    // write attn bf16 hi/lo into swizzled tiles (chunks of 32 cols)
#pragma unroll
    for (int mi = 0; mi < 2; mi++)
#pragma unroll
        for (int rh = 0; rh < 2; rh++) {
            int r = wm * 32 + mi * 16 + (lane >> 2) + rh * 8;
#pragma unroll
            for (int nj = 0; nj < 8; nj++) {
                int col = wn * 64 + nj * 8 + (lane & 3) * 2;
                if (col >= MMP) continue;   // chunk 7 never read
                float v0 = acc[mi][nj][rh * 2] * rowinv[mi][rh];
                float v1 = acc[mi][nj][rh * 2 + 1] * rowinv[mi][rh];
                __nv_bfloat16 h0 = __float2bfloat16(v0);
                __nv_bfloat16 h1 = __float2bfloat16(v1);
                __nv_bfloat16 l0 = __float2bfloat16(v0 - __bfloat162float(h0));
                __nv_bfloat16 l1 = __float2bfloat16(v1 - __bfloat162float(h1));
                int k = col >> 5, kc = col & 31;
                int off = swz(r, kc >> 3) + (kc & 7);
                uint16_t h0b = *(uint16_t*)&h0, h1b = *(uint16_t*)&h1;
                uint16_t l0b = *(uint16_t*)&l0, l1b = *(uint16_t*)&l1;
                *(uint32_t*)(attnHi + k * 2048 + off) = (uint32_t)h0b | ((uint32_t)h1b << 16);
                *(uint32_t*)(attnLo + k * 2048 + off) = (uint32_t)l0b | ((uint32_t)l1b << 16);
            }
        }
    __syncthreads();

    // ================= stage C: yT = attn . g^T =================
    float acc2[2][4][4];
    const int QT = 6 * 7;   // 6 c-tiles x 7 K-chunks
    for (int q = 0; q < QT; q++) {
        int nt = q / 7, k = q - nt * 7;
        if (k == 0) {
#pragma unroll
            for (int i = 0; i < 2; i++)
#pragma unroll
                for (int j = 0; j < 4; j++)
#pragma unroll
                    for (int r = 0; r < 4; r++) acc2[i][j][r] = 0.f;
        }
        int buf = q & 1;
        if (q + 1 < QT) { loadC(q + 1, buf ^ 1); CPA_COMMIT(); CPA_WAIT(1); }
        else { CPA_WAIT(0); }
        __syncthreads();
        const __nv_bfloat16* st = pipeC + buf * 8192;
#pragma unroll
        for (int ks = 0; ks < 2; ks++) {
            const int aRow = wm * 32 + ((lane >> 3) & 1) * 8 + (lane & 7);
            const int aSeg = ks * 2 + (lane >> 4);
            const int bRow = wn * 32 + (lane >> 4) * 8 + (lane & 7);
            const int bSeg = ks * 2 + ((lane >> 3) & 1);

            uint32_t a[2][4], bb[2][4];
#pragma unroll
            for (int mi = 0; mi < 2; mi++)
                ldm_x4(a[mi], smem_u32(attnHi + k * 2048 + swz(aRow + mi * 16, aSeg)));
#pragma unroll
            for (int ni = 0; ni < 2; ni++)
                ldm_x4(bb[ni], smem_u32(st + swz(bRow + ni * 16, bSeg)));
#pragma unroll
            for (int mi = 0; mi < 2; mi++)
#pragma unroll
                for (int nj = 0; nj < 4; nj++)
                    mma16816(acc2[mi][nj], a[mi],
                             bb[nj >> 1][(nj & 1) * 2], bb[nj >> 1][(nj & 1) * 2 + 1]);
#pragma unroll
            for (int mi = 0; mi < 2; mi++)
                ldm_x4(a[mi], smem_u32(attnLo + k * 2048 + swz(aRow + mi * 16, aSeg)));
#pragma unroll
            for (int mi = 0; mi < 2; mi++)
#pragma unroll
                for (int nj = 0; nj < 4; nj++)
                    mma16816(acc2[mi][nj], a[mi],
                             bb[nj >> 1][(nj & 1) * 2], bb[nj >> 1][(nj & 1) * 2 + 1]);
#pragma unroll
            for (int mi = 0; mi < 2; mi++)
                ldm_x4(a[mi], smem_u32(attnHi + k * 2048 + swz(aRow + mi * 16, aSeg)));
#pragma unroll
            for (int ni = 0; ni < 2; ni++)
                ldm_x4(bb[ni], smem_u32(st + 4096 + swz(bRow + ni * 16, bSeg)));
#pragma unroll
            for (int mi = 0; mi < 2; mi++)
#pragma unroll
                for (int nj = 0; nj < 4; nj++)
                    mma16816(acc2[mi][nj], a[mi],
                             bb[nj >> 1][(nj & 1) * 2], bb[nj >> 1][(nj & 1) * 2 + 1]);
        }
        __syncthreads();
        if (k == 6) {
            // epilogue for c-tile nt: store yT split hi/lo
#pragma unroll
            for (int mi = 0; mi < 2; mi++) {
                int r0 = wm * 32 + mi * 16 + (lane >> 2);
                int r1 = r0 + 8;
                int nn0 = n0 + r0, nn1 = n0 + r1;
#pragma unroll
                for (int nj = 0; nj < 4; nj++) {
                    int c = nt * 128 + wn * 32 + nj * 8 + (lane & 3) * 2;
#pragma unroll
                    for (int half = 0; half < 2; half++) {
                        int nn = half ? nn1 : nn0;
                        if (nn >= NN) continue;
                        float v0 = acc2[mi][nj][half * 2];
                        float v1 = acc2[mi][nj][half * 2 + 1];
                        __nv_bfloat16 h0 = __float2bfloat16(v0);
                        __nv_bfloat16 h1 = __float2bfloat16(v1);
                        __nv_bfloat16 l0 = __float2bfloat16(v0 - __bfloat162float(h0));
                        __nv_bfloat16 l1 = __float2bfloat16(v1 - __bfloat162float(h1));
                        long obase = ((long)b * NN + nn) * CI + c;
                        uint16_t h0b = *(uint16_t*)&h0, h1b = *(uint16_t*)&h1;
                        uint16_t l0b = *(uint16_t*)&l0, l1b = *(uint16_t*)&l1;
                        *(uint32_t*)(g_yhT + obase) = (uint32_t)h0b | ((uint32_t)h1b << 16);
                        *(uint32_t*)(g_ylT + obase) = (uint32_t)l0b | ((uint32_t)l1b << 16);
                    }
                }
            }
        }
    }
}

// ---------------------------------------------------------------------------
// Launch
// ---------------------------------------------------------------------------
extern "C" void kernel_launch(void* const* d_in, const int* in_sizes, int n_in,
                              void* d_out, int out_size) {
    const float* x     = (const float*)d_in[0];
    const float* wt    = (const float*)d_in[1];
    const float* bt    = (const float*)d_in[2];
    const float* wp    = (const float*)d_in[3];
    const float* bp    = (const float*)d_in[4];
    const float* wg    = (const float*)d_in[5];
    const float* bg    = (const float*)d_in[6];
    const float* wW    = (const float*)d_in[7];
    const float* bW    = (const float*)d_in[8];
    const float* gamma = (const float*)d_in[9];
    const float* beta  = (const float*)d_in[10];
    const float* mean  = (const float*)d_in[11];
    const float* var   = (const float*)d_in[12];
    float* out = (float*)d_out;

    float *p_tpg, *p_phi;
    __nv_bfloat16 *p_xhT, *p_xlT, *p_thh, *p_thl, *p_phh, *p_phl;
    __nv_bfloat16 *p_yhT, *p_ylT, *p_whi, *p_wlo, *p_wWhi, *p_wWlo;
    cudaGetSymbolAddress((void**)&p_tpg, g_tpg);
    cudaGetSymbolAddress((void**)&p_phi, g_phi);
    cudaGetSymbolAddress((void**)&p_xhT, g_xhT);
    cudaGetSymbolAddress((void**)&p_xlT, g_xlT);
    cudaGetSymbolAddress((void**)&p_thh, g_thh);
    cudaGetSymbolAddress((void**)&p_thl, g_thl);
    cudaGetSymbolAddress((void**)&p_phh, g_phh);
    cudaGetSymbolAddress((void**)&p_phl, g_phl);
    cudaGetSymbolAddress((void**)&p_yhT, g_yhT);
    cudaGetSymbolAddress((void**)&p_ylT, g_ylT);
    cudaGetSymbolAddress((void**)&p_whi, g_whi);
    cudaGetSymbolAddress((void**)&p_wlo, g_wlo);
    cudaGetSymbolAddress((void**)&p_wWhi, g_wWhi);
    cudaGetSymbolAddress((void**)&p_wWlo, g_wWlo);

    cudaFuncSetAttribute((const void*)mma128_kernel<1>,
                         cudaFuncAttributeMaxDynamicSharedMemorySize, SMEM3);
    cudaFuncSetAttribute((const void*)mma128_kernel<2>,
                         cudaFuncAttributeMaxDynamicSharedMemorySize, SMEM3);
    cudaFuncSetAttribute((const void*)fused_attn_kernel,
                         cudaFuncAttributeMaxDynamicSharedMemorySize, FA_SMEM);

    // #1 weight stack+split
    {
        long total = (long)CTPG * CC;
        wsplit_stack_kernel<<<(unsigned)((total + 255) / 256), 256>>>(wt, wp, wg, bt, bp, bg);
    }
    // #2 fused joint + transpose + split
    {
        dim3 grid((NN + 31) / 32, CC / 32, BSZ);
        tsplitX_kernel<<<grid, dim3(32, 8)>>>(x);
    }
    // #3 BN prep (keeps GEMM1 at launch #4 for ncu)
    bnprep_kernel<<<(CC + 255) / 256, 256>>>(gamma, beta, mean, var, bW);
    // #4 stacked theta|phi|g conv, batch-flattened N
    {
        mma128_kernel<1><<<dim3(CTPG / 128, GNTOT / 128, 1), 256, SMEM3>>>(
            p_whi, p_wlo, p_xhT, p_xlT, p_tpg, CC, NN, (long)CTPG * NN);
    }
    // #5 W-conv weight split
    wsplitW_kernel<<<(unsigned)(((long)CC * CI + 255) / 256), 256>>>(wW);
    // #6 pool
    {
        int total = BSZ * CI * (MM + MMP);
        pool_kernel<<<(total + 255) / 256, 256>>>();
    }
    // #7 theta slice -> theta^T hi/lo
    {
        dim3 grid((NN + 31) / 32, CI / 32, BSZ);
        tsplit_kernel<<<grid, dim3(32, 8)>>>(p_tpg, p_thh, p_thl, CI, NN, (long)CTPG * NN);
    }
    // #8 phi -> phi^T hi/lo
    {
        dim3 grid((MM + 31) / 32, CI / 32, BSZ);
        tsplit_kernel<<<grid, dim3(32, 8)>>>(p_phi, p_phh, p_phl, CI, MM, (long)CI * MM);
    }
    // #9 fused attention: f -> softmax -> yT hi/lo
    {
        fused_attn_kernel<<<dim3(NBLK, BSZ, 1), 256, FA_SMEM>>>();
    }
    // #10 W conv, batch-flattened N, BN + residual(g_xhT+g_xlT) -> out
    {
        mma128_kernel<2><<<dim3(CC / 128, GNTOT / 128, 1), 256, SMEM3>>>(
            p_wWhi, p_wWlo, p_yhT, p_ylT, out, CI, NN, (long)CC * NN);
    }
}

// round 14
// speedup vs baseline: 1.1743x; 1.0019x over previous
#include <cuda_runtime.h>
#include <cuda_bf16.h>
#include <cstdint>

// ---------------------------------------------------------------------------
// Problem constants
// ---------------------------------------------------------------------------
#define BSZ  32
#define CC   1536
#define CI   768
#define HH   14
#define WW   14
#define HJ   28
#define WJ   28
#define NN   784
#define MM   196
#define MMP  224          // pooled K padded to multiple of 32
#define GNTOT (BSZ * NN)  // 25088 = 196 * 128 exactly

// ---------------------------------------------------------------------------
// Scratch (device globals)
// ---------------------------------------------------------------------------
__device__ __align__(16) __nv_bfloat16 g_xhT[(size_t)BSZ * NN * CC];
__device__ __align__(16) __nv_bfloat16 g_xlT[(size_t)BSZ * NN * CC];
__device__ float g_gconv[(size_t)BSZ * CI * NN];            // g conv out [b][c][n]
__device__ float g_phiN [(size_t)GNTOT * CI];               // phi conv out [gn][c]
__device__ __align__(16) __nv_bfloat16 g_thh[(size_t)BSZ * NN * CI];   // theta^T hi
__device__ __align__(16) __nv_bfloat16 g_thl[(size_t)BSZ * NN * CI];
__device__ __align__(16) __nv_bfloat16 g_phh[(size_t)BSZ * MM * CI];   // phi^T hi
__device__ __align__(16) __nv_bfloat16 g_phl[(size_t)BSZ * MM * CI];
__device__ __align__(16) __nv_bfloat16 g_gph[(size_t)BSZ * CI * MMP];  // pooled g hi
__device__ __align__(16) __nv_bfloat16 g_gpl[(size_t)BSZ * CI * MMP];
__device__ __align__(16) __nv_bfloat16 g_yhT[(size_t)BSZ * NN * CI];
__device__ __align__(16) __nv_bfloat16 g_ylT[(size_t)BSZ * NN * CI];
__device__ __align__(16) __nv_bfloat16 g_wthh[(size_t)CI * CC];   // w_theta hi/lo
__device__ __align__(16) __nv_bfloat16 g_wthl[(size_t)CI * CC];
__device__ __align__(16) __nv_bfloat16 g_wphh[(size_t)CI * CC];   // w_phi hi/lo
__device__ __align__(16) __nv_bfloat16 g_wphl[(size_t)CI * CC];
__device__ __align__(16) __nv_bfloat16 g_wghh[(size_t)CI * CC];   // w_g hi/lo
__device__ __align__(16) __nv_bfloat16 g_wghl[(size_t)CI * CC];
__device__ __align__(16) __nv_bfloat16 g_wWhi[(size_t)CC * CI];
__device__ __align__(16) __nv_bfloat16 g_wWlo[(size_t)CC * CI];
__device__ float g_bstk[CI];        // g bias
__device__ float g_escale[CC];
__device__ float g_eshift[CC];

// ---------------------------------------------------------------------------
// PTX helpers (base ISA only — harness's ptxas targets plain sm_103)
// ---------------------------------------------------------------------------
__device__ __forceinline__ uint32_t smem_u32(const void* p) {
    uint32_t a;
    asm("{ .reg .u64 t; cvta.to.shared.u64 t, %1; cvt.u32.u64 %0, t; }" : "=r"(a) : "l"(p));
    return a;
}
__device__ __forceinline__ void ldm_x4(uint32_t* r, uint32_t addr) {
    asm volatile("ldmatrix.sync.aligned.m8n8.x4.shared.b16 {%0,%1,%2,%3}, [%4];"
                 : "=r"(r[0]), "=r"(r[1]), "=r"(r[2]), "=r"(r[3]) : "r"(addr));
}
__device__ __forceinline__ void mma16816(float* d, const uint32_t* a, uint32_t b0, uint32_t b1) {
    asm volatile("mma.sync.aligned.m16n8k16.row.col.f32.bf16.bf16.f32 "
                 "{%0,%1,%2,%3}, {%4,%5,%6,%7}, {%8,%9}, {%0,%1,%2,%3};"
                 : "+f"(d[0]), "+f"(d[1]), "+f"(d[2]), "+f"(d[3])
                 : "r"(a[0]), "r"(a[1]), "r"(a[2]), "r"(a[3]), "r"(b0), "r"(b1));
}
__device__ __forceinline__ void cpa16(uint32_t dst, const void* src, int srcsz) {
    asm volatile("cp.async.cg.shared.global [%0], [%1], 16, %2;"
                 :: "r"(dst), "l"(src), "r"(srcsz));
}
__device__ __forceinline__ void cpa16u(uint32_t dst, const void* src) {
    asm volatile("cp.async.cg.shared.global [%0], [%1], 16;"
                 :: "r"(dst), "l"(src));
}
#define CPA_COMMIT()  asm volatile("cp.async.commit_group;" ::: "memory")
#define CPA_WAIT(n)   asm volatile("cp.async.wait_group %0;" :: "n"(n) : "memory")

// swizzled element offset: row-major 64B rows, 16B segs XORed
__device__ __forceinline__ int swz(int row, int seg) {
    return row * 32 + ((seg ^ ((row >> 1) & 3)) << 3);
}
__device__ __forceinline__ uint32_t pack_bf16x2(float a, float b) {
    __nv_bfloat16 ha = __float2bfloat16(a), hb = __float2bfloat16(b);
    return (uint32_t)(*(uint16_t*)&ha) | ((uint32_t)(*(uint16_t*)&hb) << 16);
}

// ---------------------------------------------------------------------------
// fused joint-gather + transpose + bf16 hi/lo split: x -> xjT [b][n][c]
// ---------------------------------------------------------------------------
__global__ void tsplitX_kernel(const float* __restrict__ x) {
    __shared__ float t[32][33];
    int b = blockIdx.z;
    int c0 = blockIdx.y * 32, n0 = blockIdx.x * 32;
    int tx = threadIdx.x, ty = threadIdx.y;
#pragma unroll
    for (int s = 0; s < 32; s += 8) {
        int c = c0 + ty + s, n = n0 + tx;
        float v = 0.f;
        if (n < NN) {
            int hj = n / WJ, wj = n % WJ;
            int vv = ((hj >= HH) ? 2 : 0) + ((wj >= WW) ? 1 : 0);
            int hl = (hj >= HH) ? hj - HH : hj;
            int wl = (wj >= WW) ? wj - WW : wj;
            v = x[(((long)(b * 4 + vv) * CC + c) * HH + hl) * WW + wl];
        }
        t[ty + s][tx] = v;
    }
    __syncthreads();
    long ob = (long)b * NN * CC;
#pragma unroll
    for (int s = 0; s < 32; s += 8) {
        int n = n0 + ty + s, c = c0 + tx;
        if (n < NN) {
            float v = t[tx][ty + s];
            __nv_bfloat16 h = __float2bfloat16(v);
            g_xhT[ob + (long)n * CC + c] = h;
            g_xlT[ob + (long)n * CC + c] = __float2bfloat16(v - __bfloat162float(h));
        }
    }
}

// ---------------------------------------------------------------------------
// weight prep: split theta/phi/g weights into hi/lo; bias for g
// ---------------------------------------------------------------------------
__global__ void wsplit3_kernel(const float* __restrict__ wt, const float* __restrict__ wp,
                               const float* __restrict__ wg, const float* __restrict__ bg) {
    long idx = (long)blockIdx.x * blockDim.x + threadIdx.x;
    if (idx < (long)CI * CC) {
        float v = wt[idx];
        __nv_bfloat16 h = __float2bfloat16(v);
        g_wthh[idx] = h; g_wthl[idx] = __float2bfloat16(v - __bfloat162float(h));
        v = wp[idx];
        h = __float2bfloat16(v);
        g_wphh[idx] = h; g_wphl[idx] = __float2bfloat16(v - __bfloat162float(h));
        v = wg[idx];
        h = __float2bfloat16(v);
        g_wghh[idx] = h; g_wghl[idx] = __float2bfloat16(v - __bfloat162float(h));
    }
    if (idx < CI) g_bstk[idx] = bg[idx];
}

__global__ void wsplitW_kernel(const float* __restrict__ wW) {
    long idx = (long)blockIdx.x * blockDim.x + threadIdx.x;
    if (idx >= (long)CC * CI) return;
    float v = wW[idx];
    __nv_bfloat16 h = __float2bfloat16(v);
    g_wWhi[idx] = h;
    g_wWlo[idx] = __float2bfloat16(v - __bfloat162float(h));
}

__global__ void bnprep_kernel(const float* __restrict__ gamma, const float* __restrict__ beta,
                              const float* __restrict__ mean, const float* __restrict__ var,
                              const float* __restrict__ bW) {
    int m = blockIdx.x * blockDim.x + threadIdx.x;
    if (m < CC) {
        float s = gamma[m] * rsqrtf(var[m] + 1e-5f);
        g_escale[m] = s;
        g_eshift[m] = beta[m] - mean[m] * s + bW[m] * s;
    }
}

// ---------------------------------------------------------------------------
// pool_g: 2x2 maxpool on g conv [b][c][n] -> bf16 hi/lo [b][c][224] padded
// ---------------------------------------------------------------------------
__global__ void pool_g_kernel() {
    int idx = blockIdx.x * blockDim.x + threadIdx.x;
    const int tot = BSZ * CI * MMP;
    if (idx >= tot) return;
    int j = idx % MMP;
    int c = (idx / MMP) % CI;
    int b = idx / (MMP * CI);
    float v = 0.f;
    if (j < MM) {
        int hm = j / 14, wm = j % 14;
        const float* src = g_gconv + ((long)b * CI + c) * NN;
        int base = (2 * hm) * WJ + 2 * wm;
        v = fmaxf(fmaxf(src[base], src[base + 1]),
                  fmaxf(src[base + WJ], src[base + WJ + 1]));
    }
    __nv_bfloat16 h = __float2bfloat16(v);
    g_gph[idx] = h;
    g_gpl[idx] = (j < MM) ? __float2bfloat16(v - __bfloat162float(h)) : __nv_bfloat16(0.f);
}

// ---------------------------------------------------------------------------
// pool_phi: 2x2 maxpool on phi conv [gn][c] -> phi^T bf16 hi/lo [b][m][c]
//   coalesced: adjacent threads handle adjacent c
// ---------------------------------------------------------------------------
__global__ void pool_phi_kernel() {
    int idx = blockIdx.x * blockDim.x + threadIdx.x;
    const int tot = BSZ * MM * CI;
    if (idx >= tot) return;
    int c = idx % CI;
    int m = (idx / CI) % MM;
    int b = idx / (CI * MM);
    int hm = m / 14, wm = m % 14;
    int n = (2 * hm) * WJ + 2 * wm;
    long base = ((long)b * NN + n) * CI + c;
    float v = fmaxf(fmaxf(g_phiN[base], g_phiN[base + CI]),
                    fmaxf(g_phiN[base + WJ * CI], g_phiN[base + (WJ + 1) * CI]));
    __nv_bfloat16 h = __float2bfloat16(v);
    g_phh[idx] = h;
    g_phl[idx] = __float2bfloat16(v - __bfloat162float(h));
}

// ---------------------------------------------------------------------------
// fused-pass bf16-split tensor GEMM (mma.sync m16n8k16), 128x128 tile,
// 256 thr, 2 CTA/SM, 3-stage cp.async, swizzled smem, 1 barrier/chunk.
//   EPI 1: g conv  — C[b][c][n] fp32 + g_bstk[row];      grid(x=M/128, y=N/128)
//   EPI 2: W conv  — BN-fold + residual(xhT+xlT);        grid(x=M/128, y=N/128)
//   EPI 4: theta   — bf16 hi/lo [mr][col] + bias[col];   grid(x=N/128, y=M/128)
//   EPI 5: phi     — fp32 [mr][col] + bias[col];         grid(x=N/128, y=M/128)
// ---------------------------------------------------------------------------
#define GTILE (128 * 32)
#define ST    (4 * GTILE)
#define SMEM3 (3 * ST * 2)          // 98304 B

template <int EPI>
__global__ void __launch_bounds__(256, 2)
mma128_kernel(const __nv_bfloat16* __restrict__ Ahi, const __nv_bfloat16* __restrict__ Alo,
              const __nv_bfloat16* __restrict__ Bhi, const __nv_bfloat16* __restrict__ Blo,
              float* __restrict__ Cp, int K, int ldC, long sC,
              __nv_bfloat16* __restrict__ Thi, __nv_bfloat16* __restrict__ Tlo,
              const float* __restrict__ cbias) {
    extern __shared__ __align__(16) __nv_bfloat16 smem[];
    constexpr bool MSWAP = (EPI == 4) || (EPI == 5);

    const int tid = threadIdx.x;
    const int lane = tid & 31;
    const int wid = tid >> 5;
    const int wm = wid & 1;
    const int wn = wid >> 1;
    const int m0 = (MSWAP ? blockIdx.y : blockIdx.x) * 128;
    const int n0 = (MSWAP ? blockIdx.x : blockIdx.y) * 128;

    const int NK = K / 32;
    const __nv_bfloat16* A0 = Ahi + (long)m0 * K;
    const __nv_bfloat16* A1 = Alo + (long)m0 * K;

    float acc[4][4][4];
#pragma unroll
    for (int i = 0; i < 4; i++)
#pragma unroll
        for (int j = 0; j < 4; j++)
#pragma unroll
            for (int r = 0; r < 4; r++) acc[i][j][r] = 0.f;

    auto loadChunk = [&](int g, int stage) {
        long kc = (long)g * 32;
        __nv_bfloat16* st = smem + stage * ST;
#pragma unroll
        for (int i = 0; i < 2; i++) {
            int idx = tid + i * 256;
            int row = idx >> 2, seg = idx & 3;
            int off = swz(row, seg);
            long ga = (long)row * K + kc + seg * 8;
            long gb = (long)(n0 + row) * K + kc + seg * 8;
            cpa16u(smem_u32(st + off), A0 + ga);
            cpa16u(smem_u32(st + GTILE + off), Bhi + gb);
            cpa16u(smem_u32(st + 2 * GTILE + off), A1 + ga);
            cpa16u(smem_u32(st + 3 * GTILE + off), Blo + gb);
        }
    };

    loadChunk(0, 0); CPA_COMMIT();
    loadChunk(1, 1); CPA_COMMIT();

    int cs = 0, ls = 2;
    for (int g = 0; g < NK; g++) {
        if (g + 1 < NK) { CPA_WAIT(1); } else { CPA_WAIT(0); }
        __syncthreads();
        if (g + 2 < NK) {
            loadChunk(g + 2, ls);
            CPA_COMMIT();
            ls = (ls == 2) ? 0 : ls + 1;
        }
        const __nv_bfloat16* st = smem + cs * ST;
        cs = (cs == 2) ? 0 : cs + 1;

#pragma unroll
        for (int ks = 0; ks < 2; ks++) {
            const int aRow = wm * 64 + ((lane >> 3) & 1) * 8 + (lane & 7);
            const int aSeg = ks * 2 + (lane >> 4);
            const int bRow = wn * 32 + (lane >> 4) * 8 + (lane & 7);
            const int bSeg = ks * 2 + ((lane >> 3) & 1);

            uint32_t bh[2][4];
#pragma unroll
            for (int ni = 0; ni < 2; ni++)
                ldm_x4(bh[ni], smem_u32(st + GTILE + swz(bRow + ni * 16, bSeg)));
            uint32_t a[4][4];
#pragma unroll
            for (int mi = 0; mi < 4; mi++)
                ldm_x4(a[mi], smem_u32(st + swz(aRow + mi * 16, aSeg)));
#pragma unroll
            for (int mi = 0; mi < 4; mi++)
#pragma unroll
                for (int nj = 0; nj < 4; nj++)
                    mma16816(acc[mi][nj], a[mi],
                             bh[nj >> 1][(nj & 1) * 2], bh[nj >> 1][(nj & 1) * 2 + 1]);
            uint32_t bl[2][4];
#pragma unroll
            for (int ni = 0; ni < 2; ni++)
                ldm_x4(bl[ni], smem_u32(st + 3 * GTILE + swz(bRow + ni * 16, bSeg)));
#pragma unroll
            for (int mi = 0; mi < 4; mi++)
#pragma unroll
                for (int nj = 0; nj < 4; nj++)
                    mma16816(acc[mi][nj], a[mi],
                             bl[nj >> 1][(nj & 1) * 2], bl[nj >> 1][(nj & 1) * 2 + 1]);
#pragma unroll
            for (int mi = 0; mi < 4; mi++)
                ldm_x4(a[mi], smem_u32(st + 2 * GTILE + swz(aRow + mi * 16, aSeg)));
#pragma unroll
            for (int mi = 0; mi < 4; mi++)
#pragma unroll
                for (int nj = 0; nj < 4; nj++)
                    mma16816(acc[mi][nj], a[mi],
                             bh[nj >> 1][(nj & 1) * 2], bh[nj >> 1][(nj & 1) * 2 + 1]);
        }
    }

    const int mbase = m0 + wm * 64;
    const int nbase = n0 + wn * 32;
#pragma unroll
    for (int mi = 0; mi < 4; mi++) {
        int mr0 = mbase + mi * 16 + (lane >> 2);
        int mr1 = mr0 + 8;
        float es0 = 1.f, eh0 = 0.f, es1 = 1.f, eh1 = 0.f;
        if (EPI == 1) { eh0 = g_bstk[mr0]; eh1 = g_bstk[mr1]; }
        if (EPI == 2) {
            es0 = g_escale[mr0]; eh0 = g_eshift[mr0];
            es1 = g_escale[mr1]; eh1 = g_eshift[mr1];
        }
#pragma unroll
        for (int nj = 0; nj < 4; nj++) {
            int n = nbase + nj * 8 + (lane & 3) * 2;
            float2 v0 = make_float2(acc[mi][nj][0], acc[mi][nj][1]);
            float2 v1 = make_float2(acc[mi][nj][2], acc[mi][nj][3]);
            if (EPI == 1 || EPI == 2) {
                int bcol = n / NN;
                int nl = n - bcol * NN;
                float* Cb = Cp + (long)bcol * sC;
                if (EPI == 2) {
#pragma unroll
                    for (int e = 0; e < 2; e++) {
                        long rbase = (long)(n + e) * CC;
                        float r0 = __bfloat162float(g_xhT[rbase + mr0]) +
                                   __bfloat162float(g_xlT[rbase + mr0]);
                        float r1 = __bfloat162float(g_xhT[rbase + mr1]) +
                                   __bfloat162float(g_xlT[rbase + mr1]);
                        if (e == 0) { v0.x = v0.x * es0 + eh0 + r0; v1.x = v1.x * es1 + eh1 + r1; }
                        else        { v0.y = v0.y * es0 + eh0 + r0; v1.y = v1.y * es1 + eh1 + r1; }
                    }
                } else {
                    v0.x += eh0; v0.y += eh0; v1.x += eh1; v1.y += eh1;
                }
                *(float2*)(Cb + (long)mr0 * ldC + nl) = v0;
                *(float2*)(Cb + (long)mr1 * ldC + nl) = v1;
            } else {
                // column bias
                float b0 = cbias[n], b1 = cbias[n + 1];
                v0.x += b0; v0.y += b1; v1.x += b0; v1.y += b1;
                if (EPI == 5) {
                    *(float2*)(Cp + (long)mr0 * CI + n) = v0;
                    *(float2*)(Cp + (long)mr1 * CI + n) = v1;
                } else {   // EPI == 4: bf16 hi/lo split store
                    __nv_bfloat16 h;
                    h = __float2bfloat16(v0.x);
                    float l0x = v0.x - __bfloat162float(h); float h0x = __bfloat162float(h);
                    h = __float2bfloat16(v0.y);
                    float l0y = v0.y - __bfloat162float(h); float h0y = __bfloat162float(h);
                    h = __float2bfloat16(v1.x);
                    float l1x = v1.x - __bfloat162float(h); float h1x = __bfloat162float(h);
                    h = __float2bfloat16(v1.y);
                    float l1y = v1.y - __bfloat162float(h); float h1y = __bfloat162float(h);
                    *(uint32_t*)(Thi + (long)mr0 * CI + n) = pack_bf16x2(h0x, h0y);
                    *(uint32_t*)(Tlo + (long)mr0 * CI + n) = pack_bf16x2(l0x, l0y);
                    *(uint32_t*)(Thi + (long)mr1 * CI + n) = pack_bf16x2(h1x, h1y);
                    *(uint32_t*)(Tlo + (long)mr1 * CI + n) = pack_bf16x2(l1x, l1y);
                }
            }
        }
    }
}

// ---------------------------------------------------------------------------
// Fused attention kernel (unchanged from R13)
// ---------------------------------------------------------------------------
#define FA_SMEM 99328
#define NBLK 13

__global__ void __launch_bounds__(256, 2)
fused_attn_kernel() {
    extern __shared__ __align__(16) __nv_bfloat16 smem[];
    const int tid = threadIdx.x;
    const int lane = tid & 31;
    const int wid = tid >> 5;
    const int wm = wid & 1;
    const int wn = wid >> 1;
    const int n0 = blockIdx.x * 64;
    const int b = blockIdx.y;

    const __nv_bfloat16* Ah = g_thh + ((long)b * NN + n0) * CI;
    const __nv_bfloat16* Al = g_thl + ((long)b * NN + n0) * CI;
    const __nv_bfloat16* Bh = g_phh + (long)b * MM * CI;
    const __nv_bfloat16* Bl = g_phl + (long)b * MM * CI;

    float acc[2][8][4];
#pragma unroll
    for (int i = 0; i < 2; i++)
#pragma unroll
        for (int j = 0; j < 8; j++)
#pragma unroll
            for (int r = 0; r < 4; r++) acc[i][j][r] = 0.f;

    auto loadA = [&](int g, int buf) {
        long kc = (long)g * 32;
        __nv_bfloat16* st = smem + buf * 20480;
        {
            int row = tid >> 2, seg = tid & 3;
            int off = swz(row, seg);
            int ok = (n0 + row) < NN;
            long ga = (long)row * CI + kc + seg * 8;
            cpa16(smem_u32(st + off), Ah + ga, ok ? 16 : 0);
            cpa16(smem_u32(st + 10240 + off), Al + ga, ok ? 16 : 0);
        }
#pragma unroll
        for (int i = 0; i < 4; i++) {
            int idx = tid + i * 256;
            int row = idx >> 2, seg = idx & 3;
            int off = swz(row, seg);
            int ok = row < MM;
            long gb = (long)row * CI + kc + seg * 8;
            cpa16(smem_u32(st + 2048 + off), Bh + gb, ok ? 16 : 0);
            cpa16(smem_u32(st + 12288 + off), Bl + gb, ok ? 16 : 0);
        }
    };

    loadA(0, 0); CPA_COMMIT();
    const int NKA = CI / 32;
    for (int g = 0; g < NKA; g++) {
        int buf = g & 1;
        if (g + 1 < NKA) { loadA(g + 1, buf ^ 1); CPA_COMMIT(); CPA_WAIT(1); }
        else { CPA_WAIT(0); }
        __syncthreads();
        const __nv_bfloat16* st = smem + buf * 20480;
#pragma unroll
        for (int ks = 0; ks < 2; ks++) {
            const int aRow = wm * 32 + ((lane >> 3) & 1) * 8 + (lane & 7);
            const int aSeg = ks * 2 + (lane >> 4);
            const int bRow = wn * 64 + (lane >> 4) * 8 + (lane & 7);
            const int bSeg = ks * 2 + ((lane >> 3) & 1);

            uint32_t a[2][4], b4[4][4];
#pragma unroll
            for (int mi = 0; mi < 2; mi++)
                ldm_x4(a[mi], smem_u32(st + swz(aRow + mi * 16, aSeg)));
#pragma unroll
            for (int ng = 0; ng < 4; ng++)
                ldm_x4(b4[ng], smem_u32(st + 2048 + swz(bRow + ng * 16, bSeg)));
#pragma unroll
            for (int mi = 0; mi < 2; mi++)
#pragma unroll
                for (int nj = 0; nj < 8; nj++)
                    mma16816(acc[mi][nj], a[mi],
                             b4[nj >> 1][(nj & 1) * 2], b4[nj >> 1][(nj & 1) * 2 + 1]);
#pragma unroll
            for (int mi = 0; mi < 2; mi++)
                ldm_x4(a[mi], smem_u32(st + 10240 + swz(aRow + mi * 16, aSeg)));
#pragma unroll
            for (int mi = 0; mi < 2; mi++)
#pragma unroll
                for (int nj = 0; nj < 8; nj++)
                    mma16816(acc[mi][nj], a[mi],
                             b4[nj >> 1][(nj & 1) * 2], b4[nj >> 1][(nj & 1) * 2 + 1]);
#pragma unroll
            for (int mi = 0; mi < 2; mi++)
                ldm_x4(a[mi], smem_u32(st + swz(aRow + mi * 16, aSeg)));
#pragma unroll
            for (int ng = 0; ng < 4; ng++)
                ldm_x4(b4[ng], smem_u32(st + 12288 + swz(bRow + ng * 16, bSeg)));
#pragma unroll
            for (int mi = 0; mi < 2; mi++)
#pragma unroll
                for (int nj = 0; nj < 8; nj++)
                    mma16816(acc[mi][nj], a[mi],
                             b4[nj >> 1][(nj & 1) * 2], b4[nj >> 1][(nj & 1) * 2 + 1]);
        }
        __syncthreads();
    }

    __nv_bfloat16* attnHi = smem;
    __nv_bfloat16* attnLo = smem + 16384;
    __nv_bfloat16* pipeC  = smem + 32768;
    float* red = (float*)(smem + 49152);

    const __nv_bfloat16* Gh = g_gph + (long)b * CI * MMP;
    const __nv_bfloat16* Gl = g_gpl + (long)b * CI * MMP;

    auto loadC = [&](int q, int buf) {
        int nt = q / 7, k = q - nt * 7;
        __nv_bfloat16* st = pipeC + buf * 8192;
        long kc = (long)k * 32;
#pragma unroll
        for (int i = 0; i < 2; i++) {
            int idx = tid + i * 256;
            int row = idx >> 2, seg = idx & 3;
            int off = swz(row, seg);
            long gb = (long)(nt * 128 + row) * MMP + kc + seg * 8;
            cpa16u(smem_u32(st + off), Gh + gb);
            cpa16u(smem_u32(st + 4096 + off), Gl + gb);
        }
    };
    loadC(0, 0); CPA_COMMIT();

    float rowmax[2][2], rowinv[2][2];
#pragma unroll
    for (int mi = 0; mi < 2; mi++)
#pragma unroll
        for (int rh = 0; rh < 2; rh++) {
            int r = wm * 32 + mi * 16 + (lane >> 2) + rh * 8;
            float m = -1e30f;
#pragma unroll
            for (int nj = 0; nj < 8; nj++)
#pragma unroll
                for (int e = 0; e < 2; e++) {
                    int col = wn * 64 + nj * 8 + (lane & 3) * 2 + e;
                    float v = acc[mi][nj][rh * 2 + e];
                    if (col >= MM) { v = -1e30f; acc[mi][nj][rh * 2 + e] = v; }
                    m = fmaxf(m, v);
                }
            m = fmaxf(m, __shfl_xor_sync(0xffffffffu, m, 1));
            m = fmaxf(m, __shfl_xor_sync(0xffffffffu, m, 2));
            if ((lane & 3) == 0) red[r * 4 + wn] = m;
        }
    __syncthreads();
#pragma unroll
    for (int mi = 0; mi < 2; mi++)
#pragma unroll
        for (int rh = 0; rh < 2; rh++) {
            int r = wm * 32 + mi * 16 + (lane >> 2) + rh * 8;
            rowmax[mi][rh] = fmaxf(fmaxf(red[r * 4], red[r * 4 + 1]),
                                   fmaxf(red[r * 4 + 2], red[r * 4 + 3]));
        }
    __syncthreads();
#pragma unroll
    for (int mi = 0; mi < 2; mi++)
#pragma unroll
        for (int rh = 0; rh < 2; rh++) {
            int r = wm * 32 + mi * 16 + (lane >> 2) + rh * 8;
            float s = 0.f;
#pragma unroll
            for (int nj = 0; nj < 8; nj++)
#pragma unroll
                for (int e = 0; e < 2; e++) {
                    float v = __expf(acc[mi][nj][rh * 2 + e] - rowmax[mi][rh]);
                    acc[mi][nj][rh * 2 + e] = v;
                    s += v;
                }
            s += __shfl_xor_sync(0xffffffffu, s, 1);
            s += __shfl_xor_sync(0xffffffffu, s, 2);
            if ((lane & 3) == 0) red[r * 4 + wn] = s;
        }
    __syncthreads();
#pragma unroll
    for (int mi = 0; mi < 2; mi++)
#pragma unroll
        for (int rh = 0; rh < 2; rh++) {
            int r = wm * 32 + mi * 16 + (lane >> 2) + rh * 8;
            rowinv[mi][rh] = 1.f / (red[r * 4] + red[r * 4 + 1] +
                                    red[r * 4 + 2] + red[r * 4 + 3]);
        }
#pragma unroll
    for (int mi = 0; mi < 2; mi++)
#pragma unroll
        for (int rh = 0; rh < 2; rh++) {
            int r = wm * 32 + mi * 16 + (lane >> 2) + rh * 8;
#pragma unroll
            for (int nj = 0; nj < 8; nj++) {
                int col = wn * 64 + nj * 8 + (lane & 3) * 2;
                if (col >= MMP) continue;
                float v0 = acc[mi][nj][rh * 2] * rowinv[mi][rh];
                float v1 = acc[mi][nj][rh * 2 + 1] * rowinv[mi][rh];
                __nv_bfloat16 h0 = __float2bfloat16(v0);
                __nv_bfloat16 h1 = __float2bfloat16(v1);
                float l0 = v0 - __bfloat162float(h0);
                float l1 = v1 - __bfloat162float(h1);
                int k = col >> 5, kc = col & 31;
                int off = swz(r, kc >> 3) + (kc & 7);
                *(uint32_t*)(attnHi + k * 2048 + off) =
                    (uint32_t)(*(uint16_t*)&h0) | ((uint32_t)(*(uint16_t*)&h1) << 16);
                *(uint32_t*)(attnLo + k * 2048 + off) = pack_bf16x2(l0, l1);
            }
        }
    __syncthreads();

    float acc2[2][4][4];
    const int QT = 6 * 7;
    for (int q = 0; q < QT; q++) {
        int nt = q / 7, k = q - nt * 7;
        if (k == 0) {
#pragma unroll
            for (int i = 0; i < 2; i++)
#pragma unroll
                for (int j = 0; j < 4; j++)
#pragma unroll
                    for (int r = 0; r < 4; r++) acc2[i][j][r] = 0.f;
        }
        int buf = q & 1;
        if (q + 1 < QT) { loadC(q + 1, buf ^ 1); CPA_COMMIT(); CPA_WAIT(1); }
        else { CPA_WAIT(0); }
        __syncthreads();
        const __nv_bfloat16* st = pipeC + buf * 8192;
#pragma unroll
        for (int ks = 0; ks < 2; ks++) {
            const int aRow = wm * 32 + ((lane >> 3) & 1) * 8 + (lane & 7);
            const int aSeg = ks * 2 + (lane >> 4);
            const int bRow = wn * 32 + (lane >> 4) * 8 + (lane & 7);
            const int bSeg = ks * 2 + ((lane >> 3) & 1);

            uint32_t a[2][4], bb[2][4];
#pragma unroll
            for (int mi = 0; mi < 2; mi++)
                ldm_x4(a[mi], smem_u32(attnHi + k * 2048 + swz(aRow + mi * 16, aSeg)));
#pragma unroll
            for (int ni = 0; ni < 2; ni++)
                ldm_x4(bb[ni], smem_u32(st + swz(bRow + ni * 16, bSeg)));
#pragma unroll
            for (int mi = 0; mi < 2; mi++)
#pragma unroll
                for (int nj = 0; nj < 4; nj++)
                    mma16816(acc2[mi][nj], a[mi],
                             bb[nj >> 1][(nj & 1) * 2], bb[nj >> 1][(nj & 1) * 2 + 1]);
#pragma unroll
            for (int mi = 0; mi < 2; mi++)
                ldm_x4(a[mi], smem_u32(attnLo + k * 2048 + swz(aRow + mi * 16, aSeg)));
#pragma unroll
            for (int mi = 0; mi < 2; mi++)
#pragma unroll
                for (int nj = 0; nj < 4; nj++)
                    mma16816(acc2[mi][nj], a[mi],
                             bb[nj >> 1][(nj & 1) * 2], bb[nj >> 1][(nj & 1) * 2 + 1]);
#pragma unroll
            for (int mi = 0; mi < 2; mi++)
                ldm_x4(a[mi], smem_u32(attnHi + k * 2048 + swz(aRow + mi * 16, aSeg)));
#pragma unroll
            for (int ni = 0; ni < 2; ni++)
                ldm_x4(bb[ni], smem_u32(st + 4096 + swz(bRow + ni * 16, bSeg)));
#pragma unroll
            for (int mi = 0; mi < 2; mi++)
#pragma unroll
                for (int nj = 0; nj < 4; nj++)
                    mma16816(acc2[mi][nj], a[mi],
                             bb[nj >> 1][(nj & 1) * 2], bb[nj >> 1][(nj & 1) * 2 + 1]);
        }
        __syncthreads();
        if (k == 6) {
#pragma unroll
            for (int mi = 0; mi < 2; mi++) {
                int r0 = wm * 32 + mi * 16 + (lane >> 2);
                int r1 = r0 + 8;
                int nn0 = n0 + r0, nn1 = n0 + r1;
#pragma unroll
                for (int nj = 0; nj < 4; nj++) {
                    int c = nt * 128 + wn * 32 + nj * 8 + (lane & 3) * 2;
#pragma unroll
                    for (int half = 0; half < 2; half++) {
                        int nn = half ? nn1 : nn0;
                        if (nn >= NN) continue;
                        float v0 = acc2[mi][nj][half * 2];
                        float v1 = acc2[mi][nj][half * 2 + 1];
                        __nv_bfloat16 h0 = __float2bfloat16(v0);
                        __nv_bfloat16 h1 = __float2bfloat16(v1);
                        float l0 = v0 - __bfloat162float(h0);
                        float l1 = v1 - __bfloat162float(h1);
                        long obase = ((long)b * NN + nn) * CI + c;
                        *(uint32_t*)(g_yhT + obase) =
                            (uint32_t)(*(uint16_t*)&h0) | ((uint32_t)(*(uint16_t*)&h1) << 16);
                        *(uint32_t*)(g_ylT + obase) = pack_bf16x2(l0, l1);
                    }
                }
            }
        }
    }
}

// ---------------------------------------------------------------------------
// Launch
// ---------------------------------------------------------------------------
extern "C" void kernel_launch(void* const* d_in, const int* in_sizes, int n_in,
                              void* d_out, int out_size) {
    const float* x     = (const float*)d_in[0];
    const float* wt    = (const float*)d_in[1];
    const float* bt    = (const float*)d_in[2];
    const float* wp    = (const float*)d_in[3];
    const float* bp    = (const float*)d_in[4];
    const float* wg    = (const float*)d_in[5];
    const float* bg    = (const float*)d_in[6];
    const float* wW    = (const float*)d_in[7];
    const float* bW    = (const float*)d_in[8];
    const float* gamma = (const float*)d_in[9];
    const float* beta  = (const float*)d_in[10];
    const float* mean  = (const float*)d_in[11];
    const float* var   = (const float*)d_in[12];
    float* out = (float*)d_out;

    float *p_gconv, *p_phiN;
    __nv_bfloat16 *p_xhT, *p_xlT, *p_thh, *p_thl, *p_yhT, *p_ylT;
    __nv_bfloat16 *p_wthh, *p_wthl, *p_wphh, *p_wphl, *p_wghh, *p_wghl, *p_wWhi, *p_wWlo;
    cudaGetSymbolAddress((void**)&p_gconv, g_gconv);
    cudaGetSymbolAddress((void**)&p_phiN, g_phiN);
    cudaGetSymbolAddress((void**)&p_xhT, g_xhT);
    cudaGetSymbolAddress((void**)&p_xlT, g_xlT);
    cudaGetSymbolAddress((void**)&p_thh, g_thh);
    cudaGetSymbolAddress((void**)&p_thl, g_thl);
    cudaGetSymbolAddress((void**)&p_yhT, g_yhT);
    cudaGetSymbolAddress((void**)&p_ylT, g_ylT);
    cudaGetSymbolAddress((void**)&p_wthh, g_wthh);
    cudaGetSymbolAddress((void**)&p_wthl, g_wthl);
    cudaGetSymbolAddress((void**)&p_wphh, g_wphh);
    cudaGetSymbolAddress((void**)&p_wphl, g_wphl);
    cudaGetSymbolAddress((void**)&p_wghh, g_wghh);
    cudaGetSymbolAddress((void**)&p_wghl, g_wghl);
    cudaGetSymbolAddress((void**)&p_wWhi, g_wWhi);
    cudaGetSymbolAddress((void**)&p_wWlo, g_wWlo);

    cudaFuncSetAttribute((const void*)mma128_kernel<1>,
                         cudaFuncAttributeMaxDynamicSharedMemorySize, SMEM3);
    cudaFuncSetAttribute((const void*)mma128_kernel<2>,
                         cudaFuncAttributeMaxDynamicSharedMemorySize, SMEM3);
    cudaFuncSetAttribute((const void*)mma128_kernel<4>,
                         cudaFuncAttributeMaxDynamicSharedMemorySize, SMEM3);
    cudaFuncSetAttribute((const void*)mma128_kernel<5>,
                         cudaFuncAttributeMaxDynamicSharedMemorySize, SMEM3);
    cudaFuncSetAttribute((const void*)fused_attn_kernel,
                         cudaFuncAttributeMaxDynamicSharedMemorySize, FA_SMEM);

    // #1 weight split (theta/phi/g)
    wsplit3_kernel<<<(unsigned)(((long)CI * CC + 255) / 256), 256>>>(wt, wp, wg, bg);
    // #2 fused joint + transpose + split
    {
        dim3 grid((NN + 31) / 32, CC / 32, BSZ);
        tsplitX_kernel<<<grid, dim3(32, 8)>>>(x);
    }
    // #3 BN prep
    bnprep_kernel<<<(CC + 255) / 256, 256>>>(gamma, beta, mean, var, bW);
    // #4 theta conv (swapped): thetaT[gn][ci] bf16 hi/lo directly
    {
        mma128_kernel<4><<<dim3(CI / 128, GNTOT / 128, 1), 256, SMEM3>>>(
            p_xhT, p_xlT, p_wthh, p_wthl, nullptr, CC, 0, 0L, p_thh, p_thl, bt);
    }
    // #5 phi conv (swapped): phiN[gn][ci] fp32
    {
        mma128_kernel<5><<<dim3(CI / 128, GNTOT / 128, 1), 256, SMEM3>>>(
            p_xhT, p_xlT, p_wphh, p_wphl, p_phiN, CC, 0, 0L, nullptr, nullptr, bp);
    }
    // #6 g conv (classic): g_gconv[b][c][n] fp32 + bias
    {
        mma128_kernel<1><<<dim3(CI / 128, GNTOT / 128, 1), 256, SMEM3>>>(
            p_wghh, p_wghl, p_xhT, p_xlT, p_gconv, CC, NN, (long)CI * NN,
            nullptr, nullptr, nullptr);
    }
    // #7 W-conv weight split
    wsplitW_kernel<<<(unsigned)(((long)CC * CI + 255) / 256), 256>>>(wW);
    // #8 pool g -> bf16 hi/lo [c][224]
    {
        int tot = BSZ * CI * MMP;
        pool_g_kernel<<<(tot + 255) / 256, 256>>>();
    }
    // #9 pool phi -> phi^T bf16 hi/lo [m][ci] (coalesced)
    {
        int tot = BSZ * MM * CI;
        pool_phi_kernel<<<(tot + 255) / 256, 256>>>();
    }
    // #10 fused attention: f -> softmax -> yT hi/lo
    fused_attn_kernel<<<dim3(NBLK, BSZ, 1), 256, FA_SMEM>>>();
    // #11 W conv + BN + residual -> out
    {
        mma128_kernel<2><<<dim3(CC / 128, GNTOT / 128, 1), 256, SMEM3>>>(
            p_wWhi, p_wWlo, p_yhT, p_ylT, out, CI, NN, (long)CC * NN,
            nullptr, nullptr, nullptr);
    }
}

// round 15
// speedup vs baseline: 1.1757x; 1.0013x over previous
#include <cuda_runtime.h>
#include <cuda_bf16.h>
#include <cstdint>

// ---------------------------------------------------------------------------
// Problem constants
// ---------------------------------------------------------------------------
#define BSZ  32
#define CC   1536
#define CI   768
#define HH   14
#define WW   14
#define HJ   28
#define WJ   28
#define NN   784
#define MM   196
#define MMP  224
#define CTPG 2304
#define GNTOT (BSZ * NN)  // 25088 = 196 * 128

// ---------------------------------------------------------------------------
// Scratch (device globals)
// ---------------------------------------------------------------------------
__device__ __align__(16) __nv_bfloat16 g_xhT[(size_t)BSZ * NN * CC];
__device__ __align__(16) __nv_bfloat16 g_xlT[(size_t)BSZ * NN * CC];
__device__ float g_pg  [(size_t)GNTOT * (2 * CI)];          // [gn][phi(768)|g(768)]
__device__ __align__(16) __nv_bfloat16 g_thh[(size_t)BSZ * NN * CI];
__device__ __align__(16) __nv_bfloat16 g_thl[(size_t)BSZ * NN * CI];
__device__ __align__(16) __nv_bfloat16 g_phh[(size_t)BSZ * MM * CI];
__device__ __align__(16) __nv_bfloat16 g_phl[(size_t)BSZ * MM * CI];
__device__ __align__(16) __nv_bfloat16 g_gph[(size_t)BSZ * CI * MMP];
__device__ __align__(16) __nv_bfloat16 g_gpl[(size_t)BSZ * CI * MMP];
__device__ __align__(16) __nv_bfloat16 g_yhT[(size_t)BSZ * NN * CI];
__device__ __align__(16) __nv_bfloat16 g_ylT[(size_t)BSZ * NN * CI];
__device__ __align__(16) __nv_bfloat16 g_wstkh[(size_t)CTPG * CC];  // theta|phi|g
__device__ __align__(16) __nv_bfloat16 g_wstkl[(size_t)CTPG * CC];
__device__ __align__(16) __nv_bfloat16 g_wWhi[(size_t)CC * CI];
__device__ __align__(16) __nv_bfloat16 g_wWlo[(size_t)CC * CI];
__device__ float g_cbias[CTPG];
__device__ float g_escale[CC];
__device__ float g_eshift[CC];

// ---------------------------------------------------------------------------
// PTX helpers (base ISA only)
// ---------------------------------------------------------------------------
__device__ __forceinline__ uint32_t smem_u32(const void* p) {
    uint32_t a;
    asm("{ .reg .u64 t; cvta.to.shared.u64 t, %1; cvt.u32.u64 %0, t; }" : "=r"(a) : "l"(p));
    return a;
}
__device__ __forceinline__ void ldm_x4(uint32_t* r, uint32_t addr) {
    asm volatile("ldmatrix.sync.aligned.m8n8.x4.shared.b16 {%0,%1,%2,%3}, [%4];"
                 : "=r"(r[0]), "=r"(r[1]), "=r"(r[2]), "=r"(r[3]) : "r"(addr));
}
__device__ __forceinline__ void mma16816(float* d, const uint32_t* a, uint32_t b0, uint32_t b1) {
    asm volatile("mma.sync.aligned.m16n8k16.row.col.f32.bf16.bf16.f32 "
                 "{%0,%1,%2,%3}, {%4,%5,%6,%7}, {%8,%9}, {%0,%1,%2,%3};"
                 : "+f"(d[0]), "+f"(d[1]), "+f"(d[2]), "+f"(d[3])
                 : "r"(a[0]), "r"(a[1]), "r"(a[2]), "r"(a[3]), "r"(b0), "r"(b1));
}
__device__ __forceinline__ void cpa16(uint32_t dst, const void* src, int srcsz) {
    asm volatile("cp.async.cg.shared.global [%0], [%1], 16, %2;"
                 :: "r"(dst), "l"(src), "r"(srcsz));
}
__device__ __forceinline__ void cpa16u(uint32_t dst, const void* src) {
    asm volatile("cp.async.cg.shared.global [%0], [%1], 16;"
                 :: "r"(dst), "l"(src));
}
#define CPA_COMMIT()  asm volatile("cp.async.commit_group;" ::: "memory")
#define CPA_WAIT(n)   asm volatile("cp.async.wait_group %0;" :: "n"(n) : "memory")

__device__ __forceinline__ int swz(int row, int seg) {
    return row * 32 + ((seg ^ ((row >> 1) & 3)) << 3);
}
__device__ __forceinline__ uint32_t pack_bf16x2(float a, float b) {
    __nv_bfloat16 ha = __float2bfloat16(a), hb = __float2bfloat16(b);
    return (uint32_t)(*(uint16_t*)&ha) | ((uint32_t)(*(uint16_t*)&hb) << 16);
}

// ---------------------------------------------------------------------------
// fused joint-gather + transpose + bf16 hi/lo split: x -> xjT [b][n][c]
// ---------------------------------------------------------------------------
__global__ void tsplitX_kernel(const float* __restrict__ x) {
    __shared__ float t[32][33];
    int b = blockIdx.z;
    int c0 = blockIdx.y * 32, n0 = blockIdx.x * 32;
    int tx = threadIdx.x, ty = threadIdx.y;
#pragma unroll
    for (int s = 0; s < 32; s += 8) {
        int c = c0 + ty + s, n = n0 + tx;
        float v = 0.f;
        if (n < NN) {
            int hj = n / WJ, wj = n % WJ;
            int vv = ((hj >= HH) ? 2 : 0) + ((wj >= WW) ? 1 : 0);
            int hl = (hj >= HH) ? hj - HH : hj;
            int wl = (wj >= WW) ? wj - WW : wj;
            v = x[(((long)(b * 4 + vv) * CC + c) * HH + hl) * WW + wl];
        }
        t[ty + s][tx] = v;
    }
    __syncthreads();
    long ob = (long)b * NN * CC;
#pragma unroll
    for (int s = 0; s < 32; s += 8) {
        int n = n0 + ty + s, c = c0 + tx;
        if (n < NN) {
            float v = t[tx][ty + s];
            __nv_bfloat16 h = __float2bfloat16(v);
            g_xhT[ob + (long)n * CC + c] = h;
            g_xlT[ob + (long)n * CC + c] = __float2bfloat16(v - __bfloat162float(h));
        }
    }
}

// ---------------------------------------------------------------------------
// weight prep: stacked theta|phi|g split + bias
// ---------------------------------------------------------------------------
__global__ void wsplit_stack_kernel(const float* __restrict__ wt, const float* __restrict__ wp,
                                    const float* __restrict__ wg, const float* __restrict__ bt,
                                    const float* __restrict__ bp, const float* __restrict__ bg) {
    long idx = (long)blockIdx.x * blockDim.x + threadIdx.x;
    if (idx < (long)CTPG * CC) {
        int r = (int)(idx / CC), c = (int)(idx % CC);
        const float* src = (r < CI) ? wt : ((r < 2 * CI) ? wp : wg);
        int rr = (r < CI) ? r : ((r < 2 * CI) ? r - CI : r - 2 * CI);
        float v = src[(long)rr * CC + c];
        __nv_bfloat16 h = __float2bfloat16(v);
        g_wstkh[idx] = h;
        g_wstkl[idx] = __float2bfloat16(v - __bfloat162float(h));
    }
    if (idx < CTPG) {
        int r = (int)idx;
        g_cbias[r] = (r < CI) ? bt[r] : ((r < 2 * CI) ? bp[r - CI] : bg[r - 2 * CI]);
    }
}

__global__ void wsplitW_kernel(const float* __restrict__ wW) {
    long idx = (long)blockIdx.x * blockDim.x + threadIdx.x;
    if (idx >= (long)CC * CI) return;
    float v = wW[idx];
    __nv_bfloat16 h = __float2bfloat16(v);
    g_wWhi[idx] = h;
    g_wWlo[idx] = __float2bfloat16(v - __bfloat162float(h));
}

__global__ void bnprep_kernel(const float* __restrict__ gamma, const float* __restrict__ beta,
                              const float* __restrict__ mean, const float* __restrict__ var,
                              const float* __restrict__ bW) {
    int m = blockIdx.x * blockDim.x + threadIdx.x;
    if (m < CC) {
        float s = gamma[m] * rsqrtf(var[m] + 1e-5f);
        g_escale[m] = s;
        g_eshift[m] = beta[m] - mean[m] * s + bW[m] * s;
    }
}

// ---------------------------------------------------------------------------
// pool_phi: 2x2 maxpool on pg cols [0,768) -> phi^T bf16 hi/lo [b][m][c]
// ---------------------------------------------------------------------------
__global__ void pool_phi_kernel() {
    int idx = blockIdx.x * blockDim.x + threadIdx.x;
    const int tot = BSZ * MM * CI;
    if (idx >= tot) return;
    int c = idx % CI;
    int m = (idx / CI) % MM;
    int b = idx / (CI * MM);
    int hm = m / 14, wm = m % 14;
    int n = (2 * hm) * WJ + 2 * wm;
    long base = ((long)b * NN + n) * (2 * CI) + c;
    const int LD = 2 * CI;
    float v = fmaxf(fmaxf(g_pg[base], g_pg[base + LD]),
                    fmaxf(g_pg[base + WJ * LD], g_pg[base + (WJ + 1) * LD]));
    __nv_bfloat16 h = __float2bfloat16(v);
    g_phh[idx] = h;
    g_phl[idx] = __float2bfloat16(v - __bfloat162float(h));
}

// ---------------------------------------------------------------------------
// pool_g: 2x2 maxpool on pg cols [768,1536) + transpose -> [b][c][224] hi/lo
//   32x32 smem tile: coalesced reads (c fast) and writes (m fast)
// ---------------------------------------------------------------------------
__global__ void pool_g_kernel() {
    __shared__ float t[32][33];
    int b = blockIdx.z;
    int c0 = blockIdx.y * 32, j0 = blockIdx.x * 32;
    int tx = threadIdx.x, ty = threadIdx.y;
    const int LD = 2 * CI;
#pragma unroll
    for (int s = 0; s < 32; s += 8) {
        int j = j0 + ty + s, c = c0 + tx;
        float v = 0.f;
        if (j < MM) {
            int hm = j / 14, wm = j % 14;
            int n = (2 * hm) * WJ + 2 * wm;
            long base = ((long)b * NN + n) * LD + CI + c;
            v = fmaxf(fmaxf(g_pg[base], g_pg[base + LD]),
                      fmaxf(g_pg[base + WJ * LD], g_pg[base + (WJ + 1) * LD]));
        }
        t[ty + s][tx] = v;
    }
    __syncthreads();
#pragma unroll
    for (int s = 0; s < 32; s += 8) {
        int c = c0 + ty + s, j = j0 + tx;
        float v = t[tx][ty + s];
        __nv_bfloat16 h = __float2bfloat16(v);
        long o = ((long)b * CI + c) * MMP + j;
        g_gph[o] = h;
        g_gpl[o] = (j < MM) ? __float2bfloat16(v - __bfloat162float(h)) : __nv_bfloat16(0.f);
    }
}

// ---------------------------------------------------------------------------
// fused-pass bf16-split tensor GEMM (mma.sync m16n8k16), 128x128 tile,
// 256 thr, 2 CTA/SM, 3-stage cp.async, swizzled smem, 1 barrier/chunk.
//   EPI 2: W conv — BN-fold + residual(xhT+xlT); grid(x=M/128, y=N/128)
//   EPI 6: combined conv (swapped: A=xjT rows, B=wstk cols);
//          grid(x=col tiles 18, y=gn tiles 196); col tile uniform:
//          n0 < 768 -> theta bf16 hi/lo; else fp32 to g_pg[gn][n-768]
// ---------------------------------------------------------------------------
#define GTILE (128 * 32)
#define ST    (4 * GTILE)
#define SMEM3 (3 * ST * 2)          // 98304 B

template <int EPI>
__global__ void __launch_bounds__(256, 2)
mma128_kernel(const __nv_bfloat16* __restrict__ Ahi, const __nv_bfloat16* __restrict__ Alo,
              const __nv_bfloat16* __restrict__ Bhi, const __nv_bfloat16* __restrict__ Blo,
              float* __restrict__ Cp, int K, int ldC, long sC,
              __nv_bfloat16* __restrict__ Thi, __nv_bfloat16* __restrict__ Tlo) {
    extern __shared__ __align__(16) __nv_bfloat16 smem[];
    constexpr bool MSWAP = (EPI == 6);

    const int tid = threadIdx.x;
    const int lane = tid & 31;
    const int wid = tid >> 5;
    const int wm = wid & 1;
    const int wn = wid >> 1;
    const int m0 = (MSWAP ? blockIdx.y : blockIdx.x) * 128;
    const int n0 = (MSWAP ? blockIdx.x : blockIdx.y) * 128;

    const int NK = K / 32;
    const __nv_bfloat16* A0 = Ahi + (long)m0 * K;
    const __nv_bfloat16* A1 = Alo + (long)m0 * K;

    float acc[4][4][4];
#pragma unroll
    for (int i = 0; i < 4; i++)
#pragma unroll
        for (int j = 0; j < 4; j++)
#pragma unroll
            for (int r = 0; r < 4; r++) acc[i][j][r] = 0.f;

    auto loadChunk = [&](int g, int stage) {
        long kc = (long)g * 32;
        __nv_bfloat16* st = smem + stage * ST;
#pragma unroll
        for (int i = 0; i < 2; i++) {
            int idx = tid + i * 256;
            int row = idx >> 2, seg = idx & 3;
            int off = swz(row, seg);
            long ga = (long)row * K + kc + seg * 8;
            long gb = (long)(n0 + row) * K + kc + seg * 8;
            cpa16u(smem_u32(st + off), A0 + ga);
            cpa16u(smem_u32(st + GTILE + off), Bhi + gb);
            cpa16u(smem_u32(st + 2 * GTILE + off), A1 + ga);
            cpa16u(smem_u32(st + 3 * GTILE + off), Blo + gb);
        }
    };

    loadChunk(0, 0); CPA_COMMIT();
    loadChunk(1, 1); CPA_COMMIT();

    int cs = 0, ls = 2;
    for (int g = 0; g < NK; g++) {
        if (g + 1 < NK) { CPA_WAIT(1); } else { CPA_WAIT(0); }
        __syncthreads();
        if (g + 2 < NK) {
            loadChunk(g + 2, ls);
            CPA_COMMIT();
            ls = (ls == 2) ? 0 : ls + 1;
        }
        const __nv_bfloat16* st = smem + cs * ST;
        cs = (cs == 2) ? 0 : cs + 1;

#pragma unroll
        for (int ks = 0; ks < 2; ks++) {
            const int aRow = wm * 64 + ((lane >> 3) & 1) * 8 + (lane & 7);
            const int aSeg = ks * 2 + (lane >> 4);
            const int bRow = wn * 32 + (lane >> 4) * 8 + (lane & 7);
            const int bSeg = ks * 2 + ((lane >> 3) & 1);

            uint32_t bh[2][4];
#pragma unroll
            for (int ni = 0; ni < 2; ni++)
                ldm_x4(bh[ni], smem_u32(st + GTILE + swz(bRow + ni * 16, bSeg)));
            uint32_t a[4][4];
#pragma unroll
            for (int mi = 0; mi < 4; mi++)
                ldm_x4(a[mi], smem_u32(st + swz(aRow + mi * 16, aSeg)));
#pragma unroll
            for (int mi = 0; mi < 4; mi++)
#pragma unroll
                for (int nj = 0; nj < 4; nj++)
                    mma16816(acc[mi][nj], a[mi],
                             bh[nj >> 1][(nj & 1) * 2], bh[nj >> 1][(nj & 1) * 2 + 1]);
            uint32_t bl[2][4];
#pragma unroll
            for (int ni = 0; ni < 2; ni++)
                ldm_x4(bl[ni], smem_u32(st + 3 * GTILE + swz(bRow + ni * 16, bSeg)));
#pragma unroll
            for (int mi = 0; mi < 4; mi++)
#pragma unroll
                for (int nj = 0; nj < 4; nj++)
                    mma16816(acc[mi][nj], a[mi],
                             bl[nj >> 1][(nj & 1) * 2], bl[nj >> 1][(nj & 1) * 2 + 1]);
#pragma unroll
            for (int mi = 0; mi < 4; mi++)
                ldm_x4(a[mi], smem_u32(st + 2 * GTILE + swz(aRow + mi * 16, aSeg)));
#pragma unroll
            for (int mi = 0; mi < 4; mi++)
#pragma unroll
                for (int nj = 0; nj < 4; nj++)
                    mma16816(acc[mi][nj], a[mi],
                             bh[nj >> 1][(nj & 1) * 2], bh[nj >> 1][(nj & 1) * 2 + 1]);
        }
    }

    const int mbase = m0 + wm * 64;
    const int nbase = n0 + wn * 32;
#pragma unroll
    for (int mi = 0; mi < 4; mi++) {
        int mr0 = mbase + mi * 16 + (lane >> 2);
        int mr1 = mr0 + 8;
        float es0 = 1.f, eh0 = 0.f, es1 = 1.f, eh1 = 0.f;
        if (EPI == 2) {
            es0 = g_escale[mr0]; eh0 = g_eshift[mr0];
            es1 = g_escale[mr1]; eh1 = g_eshift[mr1];
        }
#pragma unroll
        for (int nj = 0; nj < 4; nj++) {
            int n = nbase + nj * 8 + (lane & 3) * 2;
            float2 v0 = make_float2(acc[mi][nj][0], acc[mi][nj][1]);
            float2 v1 = make_float2(acc[mi][nj][2], acc[mi][nj][3]);
            if (EPI == 2) {
                int bcol = n / NN;
                int nl = n - bcol * NN;
                float* Cb = Cp + (long)bcol * sC;
#pragma unroll
                for (int e = 0; e < 2; e++) {
                    long rbase = (long)(n + e) * CC;
                    float r0 = __bfloat162float(g_xhT[rbase + mr0]) +
                               __bfloat162float(g_xlT[rbase + mr0]);
                    float r1 = __bfloat162float(g_xhT[rbase + mr1]) +
                               __bfloat162float(g_xlT[rbase + mr1]);
                    if (e == 0) { v0.x = v0.x * es0 + eh0 + r0; v1.x = v1.x * es1 + eh1 + r1; }
                    else        { v0.y = v0.y * es0 + eh0 + r0; v1.y = v1.y * es1 + eh1 + r1; }
                }
                *(float2*)(Cb + (long)mr0 * ldC + nl) = v0;
                *(float2*)(Cb + (long)mr1 * ldC + nl) = v1;
            } else {   // EPI == 6
                float b0 = g_cbias[n], b1 = g_cbias[n + 1];
                v0.x += b0; v0.y += b1; v1.x += b0; v1.y += b1;
                if (n0 < CI) {   // CTA-uniform: theta tile -> bf16 hi/lo
                    __nv_bfloat16 h;
                    h = __float2bfloat16(v0.x);
                    float l0x = v0.x - __bfloat162float(h); float h0x = __bfloat162float(h);
                    h = __float2bfloat16(v0.y);
                    float l0y = v0.y - __bfloat162float(h); float h0y = __bfloat162float(h);
                    h = __float2bfloat16(v1.x);
                    float l1x = v1.x - __bfloat162float(h); float h1x = __bfloat162float(h);
                    h = __float2bfloat16(v1.y);
                    float l1y = v1.y - __bfloat162float(h); float h1y = __bfloat162float(h);
                    *(uint32_t*)(Thi + (long)mr0 * CI + n) = pack_bf16x2(h0x, h0y);
                    *(uint32_t*)(Tlo + (long)mr0 * CI + n) = pack_bf16x2(l0x, l0y);
                    *(uint32_t*)(Thi + (long)mr1 * CI + n) = pack_bf16x2(h1x, h1y);
                    *(uint32_t*)(Tlo + (long)mr1 * CI + n) = pack_bf16x2(l1x, l1y);
                } else {         // phi/g tile -> fp32 to pg[gn][n-768]
                    int pc = n - CI;
                    *(float2*)(Cp + (long)mr0 * (2 * CI) + pc) = v0;
                    *(float2*)(Cp + (long)mr1 * (2 * CI) + pc) = v1;
                }
            }
        }
    }
}

// ---------------------------------------------------------------------------
// Fused attention kernel (unchanged from R13/R14)
// ---------------------------------------------------------------------------
#define FA_SMEM 99328
#define NBLK 13

__global__ void __launch_bounds__(256, 2)
fused_attn_kernel() {
    extern __shared__ __align__(16) __nv_bfloat16 smem[];
    const int tid = threadIdx.x;
    const int lane = tid & 31;
    const int wid = tid >> 5;
    const int wm = wid & 1;
    const int wn = wid >> 1;
    const int n0 = blockIdx.x * 64;
    const int b = blockIdx.y;

    const __nv_bfloat16* Ah = g_thh + ((long)b * NN + n0) * CI;
    const __nv_bfloat16* Al = g_thl + ((long)b * NN + n0) * CI;
    const __nv_bfloat16* Bh = g_phh + (long)b * MM * CI;
    const __nv_bfloat16* Bl = g_phl + (long)b * MM * CI;

    float acc[2][8][4];
#pragma unroll
    for (int i = 0; i < 2; i++)
#pragma unroll
        for (int j = 0; j < 8; j++)
#pragma unroll
            for (int r = 0; r < 4; r++) acc[i][j][r] = 0.f;

    auto loadA = [&](int g, int buf) {
        long kc = (long)g * 32;
        __nv_bfloat16* st = smem + buf * 20480;
        {
            int row = tid >> 2, seg = tid & 3;
            int off = swz(row, seg);
            int ok = (n0 + row) < NN;
            long ga = (long)row * CI + kc + seg * 8;
            cpa16(smem_u32(st + off), Ah + ga, ok ? 16 : 0);
            cpa16(smem_u32(st + 10240 + off), Al + ga, ok ? 16 : 0);
        }
#pragma unroll
        for (int i = 0; i < 4; i++) {
            int idx = tid + i * 256;
            int row = idx >> 2, seg = idx & 3;
            int off = swz(row, seg);
            int ok = row < MM;
            long gb = (long)row * CI + kc + seg * 8;
            cpa16(smem_u32(st + 2048 + off), Bh + gb, ok ? 16 : 0);
            cpa16(smem_u32(st + 12288 + off), Bl + gb, ok ? 16 : 0);
        }
    };

    loadA(0, 0); CPA_COMMIT();
    const int NKA = CI / 32;
    for (int g = 0; g < NKA; g++) {
        int buf = g & 1;
        if (g + 1 < NKA) { loadA(g + 1, buf ^ 1); CPA_COMMIT(); CPA_WAIT(1); }
        else { CPA_WAIT(0); }
        __syncthreads();
        const __nv_bfloat16* st = smem + buf * 20480;
#pragma unroll
        for (int ks = 0; ks < 2; ks++) {
            const int aRow = wm * 32 + ((lane >> 3) & 1) * 8 + (lane & 7);
            const int aSeg = ks * 2 + (lane >> 4);
            const int bRow = wn * 64 + (lane >> 4) * 8 + (lane & 7);
            const int bSeg = ks * 2 + ((lane >> 3) & 1);

            uint32_t a[2][4], b4[4][4];
#pragma unroll
            for (int mi = 0; mi < 2; mi++)
                ldm_x4(a[mi], smem_u32(st + swz(aRow + mi * 16, aSeg)));
#pragma unroll
            for (int ng = 0; ng < 4; ng++)
                ldm_x4(b4[ng], smem_u32(st + 2048 + swz(bRow + ng * 16, bSeg)));
#pragma unroll
            for (int mi = 0; mi < 2; mi++)
#pragma unroll
                for (int nj = 0; nj < 8; nj++)
                    mma16816(acc[mi][nj], a[mi],
                             b4[nj >> 1][(nj & 1) * 2], b4[nj >> 1][(nj & 1) * 2 + 1]);
#pragma unroll
            for (int mi = 0; mi < 2; mi++)
                ldm_x4(a[mi], smem_u32(st + 10240 + swz(aRow + mi * 16, aSeg)));
#pragma unroll
            for (int mi = 0; mi < 2; mi++)
#pragma unroll
                for (int nj = 0; nj < 8; nj++)
                    mma16816(acc[mi][nj], a[mi],
                             b4[nj >> 1][(nj & 1) * 2], b4[nj >> 1][(nj & 1) * 2 + 1]);
#pragma unroll
            for (int mi = 0; mi < 2; mi++)
                ldm_x4(a[mi], smem_u32(st + swz(aRow + mi * 16, aSeg)));
#pragma unroll
            for (int ng = 0; ng < 4; ng++)
                ldm_x4(b4[ng], smem_u32(st + 12288 + swz(bRow + ng * 16, bSeg)));
#pragma unroll
            for (int mi = 0; mi < 2; mi++)
#pragma unroll
                for (int nj = 0; nj < 8; nj++)
                    mma16816(acc[mi][nj], a[mi],
                             b4[nj >> 1][(nj & 1) * 2], b4[nj >> 1][(nj & 1) * 2 + 1]);
        }
        __syncthreads();
    }

    __nv_bfloat16* attnHi = smem;
    __nv_bfloat16* attnLo = smem + 16384;
    __nv_bfloat16* pipeC  = smem + 32768;
    float* red = (float*)(smem + 49152);

    const __nv_bfloat16* Gh = g_gph + (long)b * CI * MMP;
    const __nv_bfloat16* Gl = g_gpl + (long)b * CI * MMP;

    auto loadC = [&](int q, int buf) {
        int nt = q / 7, k = q - nt * 7;
        __nv_bfloat16* st = pipeC + buf * 8192;
        long kc = (long)k * 32;
#pragma unroll
        for (int i = 0; i < 2; i++) {
            int idx = tid + i * 256;
            int row = idx >> 2, seg = idx & 3;
            int off = swz(row, seg);
            long gb = (long)(nt * 128 + row) * MMP + kc + seg * 8;
            cpa16u(smem_u32(st + off), Gh + gb);
            cpa16u(smem_u32(st + 4096 + off), Gl + gb);
        }
    };
    loadC(0, 0); CPA_COMMIT();

    float rowmax[2][2], rowinv[2][2];
#pragma unroll
    for (int mi = 0; mi < 2; mi++)
#pragma unroll
        for (int rh = 0; rh < 2; rh++) {
            int r = wm * 32 + mi * 16 + (lane >> 2) + rh * 8;
            float m = -1e30f;
#pragma unroll
            for (int nj = 0; nj < 8; nj++)
#pragma unroll
                for (int e = 0; e < 2; e++) {
                    int col = wn * 64 + nj * 8 + (lane & 3) * 2 + e;
                    float v = acc[mi][nj][rh * 2 + e];
                    if (col >= MM) { v = -1e30f; acc[mi][nj][rh * 2 + e] = v; }
                    m = fmaxf(m, v);
                }
            m = fmaxf(m, __shfl_xor_sync(0xffffffffu, m, 1));
            m = fmaxf(m, __shfl_xor_sync(0xffffffffu, m, 2));
            if ((lane & 3) == 0) red[r * 4 + wn] = m;
        }
    __syncthreads();
#pragma unroll
    for (int mi = 0; mi < 2; mi++)
#pragma unroll
        for (int rh = 0; rh < 2; rh++) {
            int r = wm * 32 + mi * 16 + (lane >> 2) + rh * 8;
            rowmax[mi][rh] = fmaxf(fmaxf(red[r * 4], red[r * 4 + 1]),
                                   fmaxf(red[r * 4 + 2], red[r * 4 + 3]));
        }
    __syncthreads();
#pragma unroll
    for (int mi = 0; mi < 2; mi++)
#pragma unroll
        for (int rh = 0; rh < 2; rh++) {
            int r = wm * 32 + mi * 16 + (lane >> 2) + rh * 8;
            float s = 0.f;
#pragma unroll
            for (int nj = 0; nj < 8; nj++)
#pragma unroll
                for (int e = 0; e < 2; e++) {
                    float v = __expf(acc[mi][nj][rh * 2 + e] - rowmax[mi][rh]);
                    acc[mi][nj][rh * 2 + e] = v;
                    s += v;
                }
            s += __shfl_xor_sync(0xffffffffu, s, 1);
            s += __shfl_xor_sync(0xffffffffu, s, 2);
            if ((lane & 3) == 0) red[r * 4 + wn] = s;
        }
    __syncthreads();
#pragma unroll
    for (int mi = 0; mi < 2; mi++)
#pragma unroll
        for (int rh = 0; rh < 2; rh++) {
            int r = wm * 32 + mi * 16 + (lane >> 2) + rh * 8;
            rowinv[mi][rh] = 1.f / (red[r * 4] + red[r * 4 + 1] +
                                    red[r * 4 + 2] + red[r * 4 + 3]);
        }
#pragma unroll
    for (int mi = 0; mi < 2; mi++)
#pragma unroll
        for (int rh = 0; rh < 2; rh++) {
            int r = wm * 32 + mi * 16 + (lane >> 2) + rh * 8;
#pragma unroll
            for (int nj = 0; nj < 8; nj++) {
                int col = wn * 64 + nj * 8 + (lane & 3) * 2;
                if (col >= MMP) continue;
                float v0 = acc[mi][nj][rh * 2] * rowinv[mi][rh];
                float v1 = acc[mi][nj][rh * 2 + 1] * rowinv[mi][rh];
                __nv_bfloat16 h0 = __float2bfloat16(v0);
                __nv_bfloat16 h1 = __float2bfloat16(v1);
                float l0 = v0 - __bfloat162float(h0);
                float l1 = v1 - __bfloat162float(h1);
                int k = col >> 5, kc = col & 31;
                int off = swz(r, kc >> 3) + (kc & 7);
                *(uint32_t*)(attnHi + k * 2048 + off) =
                    (uint32_t)(*(uint16_t*)&h0) | ((uint32_t)(*(uint16_t*)&h1) << 16);
                *(uint32_t*)(attnLo + k * 2048 + off) = pack_bf16x2(l0, l1);
            }
        }
    __syncthreads();

    float acc2[2][4][4];
    const int QT = 6 * 7;
    for (int q = 0; q < QT; q++) {
        int nt = q / 7, k = q - nt * 7;
        if (k == 0) {
#pragma unroll
            for (int i = 0; i < 2; i++)
#pragma unroll
                for (int j = 0; j < 4; j++)
#pragma unroll
                    for (int r = 0; r < 4; r++) acc2[i][j][r] = 0.f;
        }
        int buf = q & 1;
        if (q + 1 < QT) { loadC(q + 1, buf ^ 1); CPA_COMMIT(); CPA_WAIT(1); }
        else { CPA_WAIT(0); }
        __syncthreads();
        const __nv_bfloat16* st = pipeC + buf * 8192;
#pragma unroll
        for (int ks = 0; ks < 2; ks++) {
            const int aRow = wm * 32 + ((lane >> 3) & 1) * 8 + (lane & 7);
            const int aSeg = ks * 2 + (lane >> 4);
            const int bRow = wn * 32 + (lane >> 4) * 8 + (lane & 7);
            const int bSeg = ks * 2 + ((lane >> 3) & 1);

            uint32_t a[2][4], bb[2][4];
#pragma unroll
            for (int mi = 0; mi < 2; mi++)
                ldm_x4(a[mi], smem_u32(attnHi + k * 2048 + swz(aRow + mi * 16, aSeg)));
#pragma unroll
            for (int ni = 0; ni < 2; ni++)
                ldm_x4(bb[ni], smem_u32(st + swz(bRow + ni * 16, bSeg)));
#pragma unroll
            for (int mi = 0; mi < 2; mi++)
#pragma unroll
                for (int nj = 0; nj < 4; nj++)
                    mma16816(acc2[mi][nj], a[mi],
                             bb[nj >> 1][(nj & 1) * 2], bb[nj >> 1][(nj & 1) * 2 + 1]);
#pragma unroll
            for (int mi = 0; mi < 2; mi++)
                ldm_x4(a[mi], smem_u32(attnLo + k * 2048 + swz(aRow + mi * 16, aSeg)));
#pragma unroll
            for (int mi = 0; mi < 2; mi++)
#pragma unroll
                for (int nj = 0; nj < 4; nj++)
                    mma16816(acc2[mi][nj], a[mi],
                             bb[nj >> 1][(nj & 1) * 2], bb[nj >> 1][(nj & 1) * 2 + 1]);
#pragma unroll
            for (int mi = 0; mi < 2; mi++)
                ldm_x4(a[mi], smem_u32(attnHi + k * 2048 + swz(aRow + mi * 16, aSeg)));
#pragma unroll
            for (int ni = 0; ni < 2; ni++)
                ldm_x4(bb[ni], smem_u32(st + 4096 + swz(bRow + ni * 16, bSeg)));
#pragma unroll
            for (int mi = 0; mi < 2; mi++)
#pragma unroll
                for (int nj = 0; nj < 4; nj++)
                    mma16816(acc2[mi][nj], a[mi],
                             bb[nj >> 1][(nj & 1) * 2], bb[nj >> 1][(nj & 1) * 2 + 1]);
        }
        __syncthreads();
        if (k == 6) {
#pragma unroll
            for (int mi = 0; mi < 2; mi++) {
                int r0 = wm * 32 + mi * 16 + (lane >> 2);
                int r1 = r0 + 8;
                int nn0 = n0 + r0, nn1 = n0 + r1;
#pragma unroll
                for (int nj = 0; nj < 4; nj++) {
                    int c = nt * 128 + wn * 32 + nj * 8 + (lane & 3) * 2;
#pragma unroll
                    for (int half = 0; half < 2; half++) {
                        int nn = half ? nn1 : nn0;
                        if (nn >= NN) continue;
                        float v0 = acc2[mi][nj][half * 2];
                        float v1 = acc2[mi][nj][half * 2 + 1];
                        __nv_bfloat16 h0 = __float2bfloat16(v0);
                        __nv_bfloat16 h1 = __float2bfloat16(v1);
                        float l0 = v0 - __bfloat162float(h0);
                        float l1 = v1 - __bfloat162float(h1);
                        long obase = ((long)b * NN + nn) * CI + c;
                        *(uint32_t*)(g_yhT + obase) =
                            (uint32_t)(*(uint16_t*)&h0) | ((uint32_t)(*(uint16_t*)&h1) << 16);
                        *(uint32_t*)(g_ylT + obase) = pack_bf16x2(l0, l1);
                    }
                }
            }
        }
    }
}

// ---------------------------------------------------------------------------
// Launch
// ---------------------------------------------------------------------------
extern "C" void kernel_launch(void* const* d_in, const int* in_sizes, int n_in,
                              void* d_out, int out_size) {
    const float* x     = (const float*)d_in[0];
    const float* wt    = (const float*)d_in[1];
    const float* bt    = (const float*)d_in[2];
    const float* wp    = (const float*)d_in[3];
    const float* bp    = (const float*)d_in[4];
    const float* wg    = (const float*)d_in[5];
    const float* bg    = (const float*)d_in[6];
    const float* wW    = (const float*)d_in[7];
    const float* bW    = (const float*)d_in[8];
    const float* gamma = (const float*)d_in[9];
    const float* beta  = (const float*)d_in[10];
    const float* mean  = (const float*)d_in[11];
    const float* var   = (const float*)d_in[12];
    float* out = (float*)d_out;

    float *p_pg;
    __nv_bfloat16 *p_xhT, *p_xlT, *p_thh, *p_thl, *p_yhT, *p_ylT;
    __nv_bfloat16 *p_wstkh, *p_wstkl, *p_wWhi, *p_wWlo;
    cudaGetSymbolAddress((void**)&p_pg, g_pg);
    cudaGetSymbolAddress((void**)&p_xhT, g_xhT);
    cudaGetSymbolAddress((void**)&p_xlT, g_xlT);
    cudaGetSymbolAddress((void**)&p_thh, g_thh);
    cudaGetSymbolAddress((void**)&p_thl, g_thl);
    cudaGetSymbolAddress((void**)&p_yhT, g_yhT);
    cudaGetSymbolAddress((void**)&p_ylT, g_ylT);
    cudaGetSymbolAddress((void**)&p_wstkh, g_wstkh);
    cudaGetSymbolAddress((void**)&p_wstkl, g_wstkl);
    cudaGetSymbolAddress((void**)&p_wWhi, g_wWhi);
    cudaGetSymbolAddress((void**)&p_wWlo, g_wWlo);

    cudaFuncSetAttribute((const void*)mma128_kernel<2>,
                         cudaFuncAttributeMaxDynamicSharedMemorySize, SMEM3);
    cudaFuncSetAttribute((const void*)mma128_kernel<6>,
                         cudaFuncAttributeMaxDynamicSharedMemorySize, SMEM3);
    cudaFuncSetAttribute((const void*)fused_attn_kernel,
                         cudaFuncAttributeMaxDynamicSharedMemorySize, FA_SMEM);

    // #1 stacked weight split
    {
        long total = (long)CTPG * CC;
        wsplit_stack_kernel<<<(unsigned)((total + 255) / 256), 256>>>(wt, wp, wg, bt, bp, bg);
    }
    // #2 fused joint + transpose + split
    {
        dim3 grid((NN + 31) / 32, CC / 32, BSZ);
        tsplitX_kernel<<<grid, dim3(32, 8)>>>(x);
    }
    // #3 BN prep (keeps combined conv at launch #4 for ncu)
    bnprep_kernel<<<(CC + 255) / 256, 256>>>(gamma, beta, mean, var, bW);
    // #4 combined theta|phi|g conv (swapped): theta -> bf16 split, phi/g -> pg
    {
        mma128_kernel<6><<<dim3(CTPG / 128, GNTOT / 128, 1), 256, SMEM3>>>(
            p_xhT, p_xlT, p_wstkh, p_wstkl, p_pg, CC, 0, 0L, p_thh, p_thl);
    }
    // #5 W-conv weight split
    wsplitW_kernel<<<(unsigned)(((long)CC * CI + 255) / 256), 256>>>(wW);
    // #6 pool phi -> phi^T bf16 hi/lo [m][c]
    {
        int tot = BSZ * MM * CI;
        pool_phi_kernel<<<(tot + 255) / 256, 256>>>();
    }
    // #7 pool g (transpose) -> [c][224] bf16 hi/lo
    {
        dim3 grid(MMP / 32, CI / 32, BSZ);
        pool_g_kernel<<<grid, dim3(32, 8)>>>();
    }
    // #8 fused attention: f -> softmax -> yT hi/lo
    fused_attn_kernel<<<dim3(NBLK, BSZ, 1), 256, FA_SMEM>>>();
    // #9 W conv + BN + residual -> out
    {
        mma128_kernel<2><<<dim3(CC / 128, GNTOT / 128, 1), 256, SMEM3>>>(
            p_wWhi, p_wWlo, p_yhT, p_ylT, out, CI, NN, (long)CC * NN,
            nullptr, nullptr);
    }
}

// round 16
// speedup vs baseline: 1.1920x; 1.0139x over previous
#include <cuda_runtime.h>
#include <cuda_bf16.h>
#include <cstdint>

// ---------------------------------------------------------------------------
// Problem constants
// ---------------------------------------------------------------------------
#define BSZ  32
#define CC   1536
#define CI   768
#define HH   14
#define WW   14
#define HJ   28
#define WJ   28
#define NN   784
#define MM   196
#define MMP  224
#define CTPG 2304
#define GNTOT (BSZ * NN)  // 25088 = 196 * 128

// ---------------------------------------------------------------------------
// Scratch (device globals)
// ---------------------------------------------------------------------------
__device__ __align__(16) __nv_bfloat16 g_xhT[(size_t)BSZ * NN * CC];
__device__ __align__(16) __nv_bfloat16 g_xlT[(size_t)BSZ * NN * CC];
__device__ float g_pg  [(size_t)GNTOT * (2 * CI)];          // [gn][phi(768)|g(768)]
__device__ __align__(16) __nv_bfloat16 g_thh[(size_t)BSZ * NN * CI];
__device__ __align__(16) __nv_bfloat16 g_thl[(size_t)BSZ * NN * CI];
__device__ __align__(16) __nv_bfloat16 g_phh[(size_t)BSZ * MM * CI];
__device__ __align__(16) __nv_bfloat16 g_phl[(size_t)BSZ * MM * CI];
__device__ __align__(16) __nv_bfloat16 g_gph[(size_t)BSZ * CI * MMP];
__device__ __align__(16) __nv_bfloat16 g_gpl[(size_t)BSZ * CI * MMP];
__device__ __align__(16) __nv_bfloat16 g_yhT[(size_t)BSZ * NN * CI];
__device__ __align__(16) __nv_bfloat16 g_ylT[(size_t)BSZ * NN * CI];
__device__ __align__(16) __nv_bfloat16 g_wstkh[(size_t)CTPG * CC];
__device__ __align__(16) __nv_bfloat16 g_wstkl[(size_t)CTPG * CC];
__device__ __align__(16) __nv_bfloat16 g_wWhi[(size_t)CC * CI];
__device__ __align__(16) __nv_bfloat16 g_wWlo[(size_t)CC * CI];
__device__ float g_cbias[CTPG];
__device__ float g_escale[CC];
__device__ float g_eshift[CC];

// ---------------------------------------------------------------------------
// PTX helpers (base ISA only)
// ---------------------------------------------------------------------------
__device__ __forceinline__ uint32_t smem_u32(const void* p) {
    uint32_t a;
    asm("{ .reg .u64 t; cvta.to.shared.u64 t, %1; cvt.u32.u64 %0, t; }" : "=r"(a) : "l"(p));
    return a;
}
__device__ __forceinline__ void ldm_x4(uint32_t* r, uint32_t addr) {
    asm volatile("ldmatrix.sync.aligned.m8n8.x4.shared.b16 {%0,%1,%2,%3}, [%4];"
                 : "=r"(r[0]), "=r"(r[1]), "=r"(r[2]), "=r"(r[3]) : "r"(addr));
}
__device__ __forceinline__ void mma16816(float* d, const uint32_t* a, uint32_t b0, uint32_t b1) {
    asm volatile("mma.sync.aligned.m16n8k16.row.col.f32.bf16.bf16.f32 "
                 "{%0,%1,%2,%3}, {%4,%5,%6,%7}, {%8,%9}, {%0,%1,%2,%3};"
                 : "+f"(d[0]), "+f"(d[1]), "+f"(d[2]), "+f"(d[3])
                 : "r"(a[0]), "r"(a[1]), "r"(a[2]), "r"(a[3]), "r"(b0), "r"(b1));
}
__device__ __forceinline__ void cpa16(uint32_t dst, const void* src, int srcsz) {
    asm volatile("cp.async.cg.shared.global [%0], [%1], 16, %2;"
                 :: "r"(dst), "l"(src), "r"(srcsz));
}
__device__ __forceinline__ void cpa16u(uint32_t dst, const void* src) {
    asm volatile("cp.async.cg.shared.global [%0], [%1], 16;"
                 :: "r"(dst), "l"(src));
}
#define CPA_COMMIT()  asm volatile("cp.async.commit_group;" ::: "memory")
#define CPA_WAIT(n)   asm volatile("cp.async.wait_group %0;" :: "n"(n) : "memory")

__device__ __forceinline__ int swz(int row, int seg) {
    return row * 32 + ((seg ^ ((row >> 1) & 3)) << 3);
}
__device__ __forceinline__ uint32_t pack_bf16x2(float a, float b) {
    __nv_bfloat16 ha = __float2bfloat16(a), hb = __float2bfloat16(b);
    return (uint32_t)(*(uint16_t*)&ha) | ((uint32_t)(*(uint16_t*)&hb) << 16);
}

// ---------------------------------------------------------------------------
// tsplitX v2: joint-gather + transpose + split, hoisted index math,
// packed u32 bf16x2 stores (2 adjacent c per thread)
// ---------------------------------------------------------------------------
__global__ void tsplitX_kernel(const float* __restrict__ x) {
    __shared__ float t[32][33];        // [c_off][n_off]
    int b = blockIdx.z;
    int c0 = blockIdx.y * 32, n0 = blockIdx.x * 32;
    int tx = threadIdx.x, ty = threadIdx.y;

    int n = n0 + tx;
    long xbase = 0;
    bool okn = n < NN;
    if (okn) {
        int hj = n / WJ, wj = n - hj * WJ;
        int vv = ((hj >= HH) ? 2 : 0) + ((wj >= WW) ? 1 : 0);
        int hl = (hj >= HH) ? hj - HH : hj;
        int wl = (wj >= WW) ? wj - WW : wj;
        xbase = (((long)(b * 4 + vv) * CC) * HH + hl) * WW + wl;
    }
#pragma unroll
    for (int s = 0; s < 32; s += 8) {
        int c = c0 + ty + s;
        t[ty + s][tx] = okn ? x[xbase + (long)c * (HH * WW)] : 0.f;
    }
    __syncthreads();

    int lin = ty * 32 + tx;
    int cp = lin & 15;          // c-pair index (c = c0 + 2*cp)
    int nr = lin >> 4;          // n offset 0..15
    long ob = (long)b * NN * CC;
#pragma unroll
    for (int s = 0; s < 2; s++) {
        int nn = n0 + nr + s * 16;
        if (nn >= NN) continue;
        float v0 = t[cp * 2][nr + s * 16];
        float v1 = t[cp * 2 + 1][nr + s * 16];
        __nv_bfloat16 h0 = __float2bfloat16(v0);
        __nv_bfloat16 h1 = __float2bfloat16(v1);
        float l0 = v0 - __bfloat162float(h0);
        float l1 = v1 - __bfloat162float(h1);
        long o = ob + (long)nn * CC + c0 + cp * 2;
        *(uint32_t*)(g_xhT + o) =
            (uint32_t)(*(uint16_t*)&h0) | ((uint32_t)(*(uint16_t*)&h1) << 16);
        *(uint32_t*)(g_xlT + o) = pack_bf16x2(l0, l1);
    }
}

// ---------------------------------------------------------------------------
// merged weight prep: stacked theta|phi|g split + W split + biases
// ---------------------------------------------------------------------------
__global__ void prep_kernel(const float* __restrict__ wt, const float* __restrict__ wp,
                            const float* __restrict__ wg, const float* __restrict__ bt,
                            const float* __restrict__ bp, const float* __restrict__ bg,
                            const float* __restrict__ wW) {
    long idx = (long)blockIdx.x * blockDim.x + threadIdx.x;
    if (idx < (long)CTPG * CC) {
        int r = (int)(idx / CC), c = (int)(idx % CC);
        const float* src = (r < CI) ? wt : ((r < 2 * CI) ? wp : wg);
        int rr = (r < CI) ? r : ((r < 2 * CI) ? r - CI : r - 2 * CI);
        float v = src[(long)rr * CC + c];
        __nv_bfloat16 h = __float2bfloat16(v);
        g_wstkh[idx] = h;
        g_wstkl[idx] = __float2bfloat16(v - __bfloat162float(h));
    }
    if (idx < (long)CC * CI) {
        float v = wW[idx];
        __nv_bfloat16 h = __float2bfloat16(v);
        g_wWhi[idx] = h;
        g_wWlo[idx] = __float2bfloat16(v - __bfloat162float(h));
    }
    if (idx < CTPG) {
        int r = (int)idx;
        g_cbias[r] = (r < CI) ? bt[r] : ((r < 2 * CI) ? bp[r - CI] : bg[r - 2 * CI]);
    }
}

__global__ void bnprep_kernel(const float* __restrict__ gamma, const float* __restrict__ beta,
                              const float* __restrict__ mean, const float* __restrict__ var,
                              const float* __restrict__ bW) {
    int m = blockIdx.x * blockDim.x + threadIdx.x;
    if (m < CC) {
        float s = gamma[m] * rsqrtf(var[m] + 1e-5f);
        g_escale[m] = s;
        g_eshift[m] = beta[m] - mean[m] * s + bW[m] * s;
    }
}

// ---------------------------------------------------------------------------
// pool_phi v2: 2x2 maxpool on pg cols [0,768) -> phi^T bf16 hi/lo [b][m][c]
//   2 channels/thread: float2 loads + packed u32 stores
// ---------------------------------------------------------------------------
__global__ void pool_phi_kernel() {
    int idx = blockIdx.x * blockDim.x + threadIdx.x;
    const int CH = CI / 2;
    const int tot = BSZ * MM * CH;
    if (idx >= tot) return;
    int cp = idx % CH;
    int m = (idx / CH) % MM;
    int b = idx / (CH * MM);
    int c = cp * 2;
    int hm = m / 14, wm = m % 14;
    int n = (2 * hm) * WJ + 2 * wm;
    const int LD = 2 * CI;
    long base = ((long)b * NN + n) * LD + c;
    float2 a0 = *(const float2*)(g_pg + base);
    float2 a1 = *(const float2*)(g_pg + base + LD);
    float2 a2 = *(const float2*)(g_pg + base + WJ * LD);
    float2 a3 = *(const float2*)(g_pg + base + (WJ + 1) * LD);
    float v0 = fmaxf(fmaxf(a0.x, a1.x), fmaxf(a2.x, a3.x));
    float v1 = fmaxf(fmaxf(a0.y, a1.y), fmaxf(a2.y, a3.y));
    __nv_bfloat16 h0 = __float2bfloat16(v0), h1 = __float2bfloat16(v1);
    float l0 = v0 - __bfloat162float(h0), l1 = v1 - __bfloat162float(h1);
    long o = ((long)b * MM + m) * CI + c;
    *(uint32_t*)(g_phh + o) =
        (uint32_t)(*(uint16_t*)&h0) | ((uint32_t)(*(uint16_t*)&h1) << 16);
    *(uint32_t*)(g_phl + o) = pack_bf16x2(l0, l1);
}

// ---------------------------------------------------------------------------
// pool_g: 2x2 maxpool on pg cols [768,1536) + transpose -> [b][c][224] hi/lo
// ---------------------------------------------------------------------------
__global__ void pool_g_kernel() {
    __shared__ float t[32][33];
    int b = blockIdx.z;
    int c0 = blockIdx.y * 32, j0 = blockIdx.x * 32;
    int tx = threadIdx.x, ty = threadIdx.y;
    const int LD = 2 * CI;
#pragma unroll
    for (int s = 0; s < 32; s += 8) {
        int j = j0 + ty + s, c = c0 + tx;
        float v = 0.f;
        if (j < MM) {
            int hm = j / 14, wm = j % 14;
            int n = (2 * hm) * WJ + 2 * wm;
            long base = ((long)b * NN + n) * LD + CI + c;
            v = fmaxf(fmaxf(g_pg[base], g_pg[base + LD]),
                      fmaxf(g_pg[base + WJ * LD], g_pg[base + (WJ + 1) * LD]));
        }
        t[ty + s][tx] = v;
    }
    __syncthreads();
#pragma unroll
    for (int s = 0; s < 32; s += 8) {
        int c = c0 + ty + s, j = j0 + tx;
        float v = t[tx][ty + s];
        __nv_bfloat16 h = __float2bfloat16(v);
        long o = ((long)b * CI + c) * MMP + j;
        g_gph[o] = h;
        g_gpl[o] = (j < MM) ? __float2bfloat16(v - __bfloat162float(h)) : __nv_bfloat16(0.f);
    }
}

// ---------------------------------------------------------------------------
// fused-pass bf16-split tensor GEMM (unchanged core)
//   EPI 2: W conv — BN-fold + residual(xhT+xlT); grid(x=M/128, y=N/128)
//   EPI 6: combined conv (swapped); grid(x=col tiles 18, y=gn tiles 196)
// ---------------------------------------------------------------------------
#define GTILE (128 * 32)
#define ST    (4 * GTILE)
#define SMEM3 (3 * ST * 2)          // 98304 B

template <int EPI>
__global__ void __launch_bounds__(256, 2)
mma128_kernel(const __nv_bfloat16* __restrict__ Ahi, const __nv_bfloat16* __restrict__ Alo,
              const __nv_bfloat16* __restrict__ Bhi, const __nv_bfloat16* __restrict__ Blo,
              float* __restrict__ Cp, int K, int ldC, long sC,
              __nv_bfloat16* __restrict__ Thi, __nv_bfloat16* __restrict__ Tlo) {
    extern __shared__ __align__(16) __nv_bfloat16 smem[];
    constexpr bool MSWAP = (EPI == 6);

    const int tid = threadIdx.x;
    const int lane = tid & 31;
    const int wid = tid >> 5;
    const int wm = wid & 1;
    const int wn = wid >> 1;
    const int m0 = (MSWAP ? blockIdx.y : blockIdx.x) * 128;
    const int n0 = (MSWAP ? blockIdx.x : blockIdx.y) * 128;

    const int NK = K / 32;
    const __nv_bfloat16* A0 = Ahi + (long)m0 * K;
    const __nv_bfloat16* A1 = Alo + (long)m0 * K;

    float acc[4][4][4];
#pragma unroll
    for (int i = 0; i < 4; i++)
#pragma unroll
        for (int j = 0; j < 4; j++)
#pragma unroll
            for (int r = 0; r < 4; r++) acc[i][j][r] = 0.f;

    auto loadChunk = [&](int g, int stage) {
        long kc = (long)g * 32;
        __nv_bfloat16* st = smem + stage * ST;
#pragma unroll
        for (int i = 0; i < 2; i++) {
            int idx = tid + i * 256;
            int row = idx >> 2, seg = idx & 3;
            int off = swz(row, seg);
            long ga = (long)row * K + kc + seg * 8;
            long gb = (long)(n0 + row) * K + kc + seg * 8;
            cpa16u(smem_u32(st + off), A0 + ga);
            cpa16u(smem_u32(st + GTILE + off), Bhi + gb);
            cpa16u(smem_u32(st + 2 * GTILE + off), A1 + ga);
            cpa16u(smem_u32(st + 3 * GTILE + off), Blo + gb);
        }
    };

    loadChunk(0, 0); CPA_COMMIT();
    loadChunk(1, 1); CPA_COMMIT();

    int cs = 0, ls = 2;
    for (int g = 0; g < NK; g++) {
        if (g + 1 < NK) { CPA_WAIT(1); } else { CPA_WAIT(0); }
        __syncthreads();
        if (g + 2 < NK) {
            loadChunk(g + 2, ls);
            CPA_COMMIT();
            ls = (ls == 2) ? 0 : ls + 1;
        }
        const __nv_bfloat16* st = smem + cs * ST;
        cs = (cs == 2) ? 0 : cs + 1;

#pragma unroll
        for (int ks = 0; ks < 2; ks++) {
            const int aRow = wm * 64 + ((lane >> 3) & 1) * 8 + (lane & 7);
            const int aSeg = ks * 2 + (lane >> 4);
            const int bRow = wn * 32 + (lane >> 4) * 8 + (lane & 7);
            const int bSeg = ks * 2 + ((lane >> 3) & 1);

            uint32_t bh[2][4];
#pragma unroll
            for (int ni = 0; ni < 2; ni++)
                ldm_x4(bh[ni], smem_u32(st + GTILE + swz(bRow + ni * 16, bSeg)));
            uint32_t a[4][4];
#pragma unroll
            for (int mi = 0; mi < 4; mi++)
                ldm_x4(a[mi], smem_u32(st + swz(aRow + mi * 16, aSeg)));
#pragma unroll
            for (int mi = 0; mi < 4; mi++)
#pragma unroll
                for (int nj = 0; nj < 4; nj++)
                    mma16816(acc[mi][nj], a[mi],
                             bh[nj >> 1][(nj & 1) * 2], bh[nj >> 1][(nj & 1) * 2 + 1]);
            uint32_t bl[2][4];
#pragma unroll
            for (int ni = 0; ni < 2; ni++)
                ldm_x4(bl[ni], smem_u32(st + 3 * GTILE + swz(bRow + ni * 16, bSeg)));
#pragma unroll
            for (int mi = 0; mi < 4; mi++)
#pragma unroll
                for (int nj = 0; nj < 4; nj++)
                    mma16816(acc[mi][nj], a[mi],
                             bl[nj >> 1][(nj & 1) * 2], bl[nj >> 1][(nj & 1) * 2 + 1]);
#pragma unroll
            for (int mi = 0; mi < 4; mi++)
                ldm_x4(a[mi], smem_u32(st + 2 * GTILE + swz(aRow + mi * 16, aSeg)));
#pragma unroll
            for (int mi = 0; mi < 4; mi++)
#pragma unroll
                for (int nj = 0; nj < 4; nj++)
                    mma16816(acc[mi][nj], a[mi],
                             bh[nj >> 1][(nj & 1) * 2], bh[nj >> 1][(nj & 1) * 2 + 1]);
        }
    }

    const int mbase = m0 + wm * 64;
    const int nbase = n0 + wn * 32;
#pragma unroll
    for (int mi = 0; mi < 4; mi++) {
        int mr0 = mbase + mi * 16 + (lane >> 2);
        int mr1 = mr0 + 8;
        float es0 = 1.f, eh0 = 0.f, es1 = 1.f, eh1 = 0.f;
        if (EPI == 2) {
            es0 = g_escale[mr0]; eh0 = g_eshift[mr0];
            es1 = g_escale[mr1]; eh1 = g_eshift[mr1];
        }
#pragma unroll
        for (int nj = 0; nj < 4; nj++) {
            int n = nbase + nj * 8 + (lane & 3) * 2;
            float2 v0 = make_float2(acc[mi][nj][0], acc[mi][nj][1]);
            float2 v1 = make_float2(acc[mi][nj][2], acc[mi][nj][3]);
            if (EPI == 2) {
                int bcol = n / NN;
                int nl = n - bcol * NN;
                float* Cb = Cp + (long)bcol * sC;
#pragma unroll
                for (int e = 0; e < 2; e++) {
                    long rbase = (long)(n + e) * CC;
                    float r0 = __bfloat162float(g_xhT[rbase + mr0]) +
                               __bfloat162float(g_xlT[rbase + mr0]);
                    float r1 = __bfloat162float(g_xhT[rbase + mr1]) +
                               __bfloat162float(g_xlT[rbase + mr1]);
                    if (e == 0) { v0.x = v0.x * es0 + eh0 + r0; v1.x = v1.x * es1 + eh1 + r1; }
                    else        { v0.y = v0.y * es0 + eh0 + r0; v1.y = v1.y * es1 + eh1 + r1; }
                }
                *(float2*)(Cb + (long)mr0 * ldC + nl) = v0;
                *(float2*)(Cb + (long)mr1 * ldC + nl) = v1;
            } else {   // EPI == 6
                float b0 = g_cbias[n], b1 = g_cbias[n + 1];
                v0.x += b0; v0.y += b1; v1.x += b0; v1.y += b1;
                if (n0 < CI) {   // CTA-uniform: theta tile -> bf16 hi/lo
                    __nv_bfloat16 h;
                    h = __float2bfloat16(v0.x);
                    float l0x = v0.x - __bfloat162float(h); float h0x = __bfloat162float(h);
                    h = __float2bfloat16(v0.y);
                    float l0y = v0.y - __bfloat162float(h); float h0y = __bfloat162float(h);
                    h = __float2bfloat16(v1.x);
                    float l1x = v1.x - __bfloat162float(h); float h1x = __bfloat162float(h);
                    h = __float2bfloat16(v1.y);
                    float l1y = v1.y - __bfloat162float(h); float h1y = __bfloat162float(h);
                    *(uint32_t*)(Thi + (long)mr0 * CI + n) = pack_bf16x2(h0x, h0y);
                    *(uint32_t*)(Tlo + (long)mr0 * CI + n) = pack_bf16x2(l0x, l0y);
                    *(uint32_t*)(Thi + (long)mr1 * CI + n) = pack_bf16x2(h1x, h1y);
                    *(uint32_t*)(Tlo + (long)mr1 * CI + n) = pack_bf16x2(l1x, l1y);
                } else {         // phi/g tile -> fp32 to pg[gn][n-768]
                    int pc = n - CI;
                    *(float2*)(Cp + (long)mr0 * (2 * CI) + pc) = v0;
                    *(float2*)(Cp + (long)mr1 * (2 * CI) + pc) = v1;
                }
            }
        }
    }
}

// ---------------------------------------------------------------------------
// Fused attention kernel (unchanged)
// ---------------------------------------------------------------------------
#define FA_SMEM 99328
#define NBLK 13

__global__ void __launch_bounds__(256, 2)
fused_attn_kernel() {
    extern __shared__ __align__(16) __nv_bfloat16 smem[];
    const int tid = threadIdx.x;
    const int lane = tid & 31;
    const int wid = tid >> 5;
    const int wm = wid & 1;
    const int wn = wid >> 1;
    const int n0 = blockIdx.x * 64;
    const int b = blockIdx.y;

    const __nv_bfloat16* Ah = g_thh + ((long)b * NN + n0) * CI;
    const __nv_bfloat16* Al = g_thl + ((long)b * NN + n0) * CI;
    const __nv_bfloat16* Bh = g_phh + (long)b * MM * CI;
    const __nv_bfloat16* Bl = g_phl + (long)b * MM * CI;

    float acc[2][8][4];
#pragma unroll
    for (int i = 0; i < 2; i++)
#pragma unroll
        for (int j = 0; j < 8; j++)
#pragma unroll
            for (int r = 0; r < 4; r++) acc[i][j][r] = 0.f;

    auto loadA = [&](int g, int buf) {
        long kc = (long)g * 32;
        __nv_bfloat16* st = smem + buf * 20480;
        {
            int row = tid >> 2, seg = tid & 3;
            int off = swz(row, seg);
            int ok = (n0 + row) < NN;
            long ga = (long)row * CI + kc + seg * 8;
            cpa16(smem_u32(st + off), Ah + ga, ok ? 16 : 0);
            cpa16(smem_u32(st + 10240 + off), Al + ga, ok ? 16 : 0);
        }
#pragma unroll
        for (int i = 0; i < 4; i++) {
            int idx = tid + i * 256;
            int row = idx >> 2, seg = idx & 3;
            int off = swz(row, seg);
            int ok = row < MM;
            long gb = (long)row * CI + kc + seg * 8;
            cpa16(smem_u32(st + 2048 + off), Bh + gb, ok ? 16 : 0);
            cpa16(smem_u32(st + 12288 + off), Bl + gb, ok ? 16 : 0);
        }
    };

    loadA(0, 0); CPA_COMMIT();
    const int NKA = CI / 32;
    for (int g = 0; g < NKA; g++) {
        int buf = g & 1;
        if (g + 1 < NKA) { loadA(g + 1, buf ^ 1); CPA_COMMIT(); CPA_WAIT(1); }
        else { CPA_WAIT(0); }
        __syncthreads();
        const __nv_bfloat16* st = smem + buf * 20480;
#pragma unroll
        for (int ks = 0; ks < 2; ks++) {
            const int aRow = wm * 32 + ((lane >> 3) & 1) * 8 + (lane & 7);
            const int aSeg = ks * 2 + (lane >> 4);
            const int bRow = wn * 64 + (lane >> 4) * 8 + (lane & 7);
            const int bSeg = ks * 2 + ((lane >> 3) & 1);

            uint32_t a[2][4], b4[4][4];
#pragma unroll
            for (int mi = 0; mi < 2; mi++)
                ldm_x4(a[mi], smem_u32(st + swz(aRow + mi * 16, aSeg)));
#pragma unroll
            for (int ng = 0; ng < 4; ng++)
                ldm_x4(b4[ng], smem_u32(st + 2048 + swz(bRow + ng * 16, bSeg)));
#pragma unroll
            for (int mi = 0; mi < 2; mi++)
#pragma unroll
                for (int nj = 0; nj < 8; nj++)
                    mma16816(acc[mi][nj], a[mi],
                             b4[nj >> 1][(nj & 1) * 2], b4[nj >> 1][(nj & 1) * 2 + 1]);
#pragma unroll
            for (int mi = 0; mi < 2; mi++)
                ldm_x4(a[mi], smem_u32(st + 10240 + swz(aRow + mi * 16, aSeg)));
#pragma unroll
            for (int mi = 0; mi < 2; mi++)
#pragma unroll
                for (int nj = 0; nj < 8; nj++)
                    mma16816(acc[mi][nj], a[mi],
                             b4[nj >> 1][(nj & 1) * 2], b4[nj >> 1][(nj & 1) * 2 + 1]);
#pragma unroll
            for (int mi = 0; mi < 2; mi++)
                ldm_x4(a[mi], smem_u32(st + swz(aRow + mi * 16, aSeg)));
#pragma unroll
            for (int ng = 0; ng < 4; ng++)
                ldm_x4(b4[ng], smem_u32(st + 12288 + swz(bRow + ng * 16, bSeg)));
#pragma unroll
            for (int mi = 0; mi < 2; mi++)
#pragma unroll
                for (int nj = 0; nj < 8; nj++)
                    mma16816(acc[mi][nj], a[mi],
                             b4[nj >> 1][(nj & 1) * 2], b4[nj >> 1][(nj & 1) * 2 + 1]);
        }
        __syncthreads();
    }

    __nv_bfloat16* attnHi = smem;
    __nv_bfloat16* attnLo = smem + 16384;
    __nv_bfloat16* pipeC  = smem + 32768;
    float* red = (float*)(smem + 49152);

    const __nv_bfloat16* Gh = g_gph + (long)b * CI * MMP;
    const __nv_bfloat16* Gl = g_gpl + (long)b * CI * MMP;

    auto loadC = [&](int q, int buf) {
        int nt = q / 7, k = q - nt * 7;
        __nv_bfloat16* st = pipeC + buf * 8192;
        long kc = (long)k * 32;
#pragma unroll
        for (int i = 0; i < 2; i++) {
            int idx = tid + i * 256;
            int row = idx >> 2, seg = idx & 3;
            int off = swz(row, seg);
            long gb = (long)(nt * 128 + row) * MMP + kc + seg * 8;
            cpa16u(smem_u32(st + off), Gh + gb);
            cpa16u(smem_u32(st + 4096 + off), Gl + gb);
        }
    };
    loadC(0, 0); CPA_COMMIT();

    float rowmax[2][2], rowinv[2][2];
#pragma unroll
    for (int mi = 0; mi < 2; mi++)
#pragma unroll
        for (int rh = 0; rh < 2; rh++) {
            int r = wm * 32 + mi * 16 + (lane >> 2) + rh * 8;
            float m = -1e30f;
#pragma unroll
            for (int nj = 0; nj < 8; nj++)
#pragma unroll
                for (int e = 0; e < 2; e++) {
                    int col = wn * 64 + nj * 8 + (lane & 3) * 2 + e;
                    float v = acc[mi][nj][rh * 2 + e];
                    if (col >= MM) { v = -1e30f; acc[mi][nj][rh * 2 + e] = v; }
                    m = fmaxf(m, v);
                }
            m = fmaxf(m, __shfl_xor_sync(0xffffffffu, m, 1));
            m = fmaxf(m, __shfl_xor_sync(0xffffffffu, m, 2));
            if ((lane & 3) == 0) red[r * 4 + wn] = m;
        }
    __syncthreads();
#pragma unroll
    for (int mi = 0; mi < 2; mi++)
#pragma unroll
        for (int rh = 0; rh < 2; rh++) {
            int r = wm * 32 + mi * 16 + (lane >> 2) + rh * 8;
            rowmax[mi][rh] = fmaxf(fmaxf(red[r * 4], red[r * 4 + 1]),
                                   fmaxf(red[r * 4 + 2], red[r * 4 + 3]));
        }
    __syncthreads();
#pragma unroll
    for (int mi = 0; mi < 2; mi++)
#pragma unroll
        for (int rh = 0; rh < 2; rh++) {
            int r = wm * 32 + mi * 16 + (lane >> 2) + rh * 8;
            float s = 0.f;
#pragma unroll
            for (int nj = 0; nj < 8; nj++)
#pragma unroll
                for (int e = 0; e < 2; e++) {
                    float v = __expf(acc[mi][nj][rh * 2 + e] - rowmax[mi][rh]);
                    acc[mi][nj][rh * 2 + e] = v;
                    s += v;
                }
            s += __shfl_xor_sync(0xffffffffu, s, 1);
            s += __shfl_xor_sync(0xffffffffu, s, 2);
            if ((lane & 3) == 0) red[r * 4 + wn] = s;
        }
    __syncthreads();
#pragma unroll
    for (int mi = 0; mi < 2; mi++)
#pragma unroll
        for (int rh = 0; rh < 2; rh++) {
            int r = wm * 32 + mi * 16 + (lane >> 2) + rh * 8;
            rowinv[mi][rh] = 1.f / (red[r * 4] + red[r * 4 + 1] +
                                    red[r * 4 + 2] + red[r * 4 + 3]);
        }
#pragma unroll
    for (int mi = 0; mi < 2; mi++)
#pragma unroll
        for (int rh = 0; rh < 2; rh++) {
            int r = wm * 32 + mi * 16 + (lane >> 2) + rh * 8;
#pragma unroll
            for (int nj = 0; nj < 8; nj++) {
                int col = wn * 64 + nj * 8 + (lane & 3) * 2;
                if (col >= MMP) continue;
                float v0 = acc[mi][nj][rh * 2] * rowinv[mi][rh];
                float v1 = acc[mi][nj][rh * 2 + 1] * rowinv[mi][rh];
                __nv_bfloat16 h0 = __float2bfloat16(v0);
                __nv_bfloat16 h1 = __float2bfloat16(v1);
                float l0 = v0 - __bfloat162float(h0);
                float l1 = v1 - __bfloat162float(h1);
                int k = col >> 5, kc = col & 31;
                int off = swz(r, kc >> 3) + (kc & 7);
                *(uint32_t*)(attnHi + k * 2048 + off) =
                    (uint32_t)(*(uint16_t*)&h0) | ((uint32_t)(*(uint16_t*)&h1) << 16);
                *(uint32_t*)(attnLo + k * 2048 + off) = pack_bf16x2(l0, l1);
            }
        }
    __syncthreads();

    float acc2[2][4][4];
    const int QT = 6 * 7;
    for (int q = 0; q < QT; q++) {
        int nt = q / 7, k = q - nt * 7;
        if (k == 0) {
#pragma unroll
            for (int i = 0; i < 2; i++)
#pragma unroll
                for (int j = 0; j < 4; j++)
#pragma unroll
                    for (int r = 0; r < 4; r++) acc2[i][j][r] = 0.f;
        }
        int buf = q & 1;
        if (q + 1 < QT) { loadC(q + 1, buf ^ 1); CPA_COMMIT(); CPA_WAIT(1); }
        else { CPA_WAIT(0); }
        __syncthreads();
        const __nv_bfloat16* st = pipeC + buf * 8192;
#pragma unroll
        for (int ks = 0; ks < 2; ks++) {
            const int aRow = wm * 32 + ((lane >> 3) & 1) * 8 + (lane & 7);
            const int aSeg = ks * 2 + (lane >> 4);
            const int bRow = wn * 32 + (lane >> 4) * 8 + (lane & 7);
            const int bSeg = ks * 2 + ((lane >> 3) & 1);

            uint32_t a[2][4], bb[2][4];
#pragma unroll
            for (int mi = 0; mi < 2; mi++)
                ldm_x4(a[mi], smem_u32(attnHi + k * 2048 + swz(aRow + mi * 16, aSeg)));
#pragma unroll
            for (int ni = 0; ni < 2; ni++)
                ldm_x4(bb[ni], smem_u32(st + swz(bRow + ni * 16, bSeg)));
#pragma unroll
            for (int mi = 0; mi < 2; mi++)
#pragma unroll
                for (int nj = 0; nj < 4; nj++)
                    mma16816(acc2[mi][nj], a[mi],
                             bb[nj >> 1][(nj & 1) * 2], bb[nj >> 1][(nj & 1) * 2 + 1]);
#pragma unroll
            for (int mi = 0; mi < 2; mi++)
                ldm_x4(a[mi], smem_u32(attnLo + k * 2048 + swz(aRow + mi * 16, aSeg)));
#pragma unroll
            for (int mi = 0; mi < 2; mi++)
#pragma unroll
                for (int nj = 0; nj < 4; nj++)
                    mma16816(acc2[mi][nj], a[mi],
                             bb[nj >> 1][(nj & 1) * 2], bb[nj >> 1][(nj & 1) * 2 + 1]);
#pragma unroll
            for (int mi = 0; mi < 2; mi++)
                ldm_x4(a[mi], smem_u32(attnHi + k * 2048 + swz(aRow + mi * 16, aSeg)));
#pragma unroll
            for (int ni = 0; ni < 2; ni++)
                ldm_x4(bb[ni], smem_u32(st + 4096 + swz(bRow + ni * 16, bSeg)));
#pragma unroll
            for (int mi = 0; mi < 2; mi++)
#pragma unroll
                for (int nj = 0; nj < 4; nj++)
                    mma16816(acc2[mi][nj], a[mi],
                             bb[nj >> 1][(nj & 1) * 2], bb[nj >> 1][(nj & 1) * 2 + 1]);
        }
        __syncthreads();
        if (k == 6) {
#pragma unroll
            for (int mi = 0; mi < 2; mi++) {
                int r0 = wm * 32 + mi * 16 + (lane >> 2);
                int r1 = r0 + 8;
                int nn0 = n0 + r0, nn1 = n0 + r1;
#pragma unroll
                for (int nj = 0; nj < 4; nj++) {
                    int c = nt * 128 + wn * 32 + nj * 8 + (lane & 3) * 2;
#pragma unroll
                    for (int half = 0; half < 2; half++) {
                        int nn = half ? nn1 : nn0;
                        if (nn >= NN) continue;
                        float v0 = acc2[mi][nj][half * 2];
                        float v1 = acc2[mi][nj][half * 2 + 1];
                        __nv_bfloat16 h0 = __float2bfloat16(v0);
                        __nv_bfloat16 h1 = __float2bfloat16(v1);
                        float l0 = v0 - __bfloat162float(h0);
                        float l1 = v1 - __bfloat162float(h1);
                        long obase = ((long)b * NN + nn) * CI + c;
                        *(uint32_t*)(g_yhT + obase) =
                            (uint32_t)(*(uint16_t*)&h0) | ((uint32_t)(*(uint16_t*)&h1) << 16);
                        *(uint32_t*)(g_ylT + obase) = pack_bf16x2(l0, l1);
                    }
                }
            }
        }
    }
}

// ---------------------------------------------------------------------------
// Launch
// ---------------------------------------------------------------------------
extern "C" void kernel_launch(void* const* d_in, const int* in_sizes, int n_in,
                              void* d_out, int out_size) {
    const float* x     = (const float*)d_in[0];
    const float* wt    = (const float*)d_in[1];
    const float* bt    = (const float*)d_in[2];
    const float* wp    = (const float*)d_in[3];
    const float* bp    = (const float*)d_in[4];
    const float* wg    = (const float*)d_in[5];
    const float* bg    = (const float*)d_in[6];
    const float* wW    = (const float*)d_in[7];
    const float* bW    = (const float*)d_in[8];
    const float* gamma = (const float*)d_in[9];
    const float* beta  = (const float*)d_in[10];
    const float* mean  = (const float*)d_in[11];
    const float* var   = (const float*)d_in[12];
    float* out = (float*)d_out;

    float *p_pg;
    __nv_bfloat16 *p_xhT, *p_xlT, *p_thh, *p_thl, *p_yhT, *p_ylT;
    __nv_bfloat16 *p_wstkh, *p_wstkl, *p_wWhi, *p_wWlo;
    cudaGetSymbolAddress((void**)&p_pg, g_pg);
    cudaGetSymbolAddress((void**)&p_xhT, g_xhT);
    cudaGetSymbolAddress((void**)&p_xlT, g_xlT);
    cudaGetSymbolAddress((void**)&p_thh, g_thh);
    cudaGetSymbolAddress((void**)&p_thl, g_thl);
    cudaGetSymbolAddress((void**)&p_yhT, g_yhT);
    cudaGetSymbolAddress((void**)&p_ylT, g_ylT);
    cudaGetSymbolAddress((void**)&p_wstkh, g_wstkh);
    cudaGetSymbolAddress((void**)&p_wstkl, g_wstkl);
    cudaGetSymbolAddress((void**)&p_wWhi, g_wWhi);
    cudaGetSymbolAddress((void**)&p_wWlo, g_wWlo);

    cudaFuncSetAttribute((const void*)mma128_kernel<2>,
                         cudaFuncAttributeMaxDynamicSharedMemorySize, SMEM3);
    cudaFuncSetAttribute((const void*)mma128_kernel<6>,
                         cudaFuncAttributeMaxDynamicSharedMemorySize, SMEM3);
    cudaFuncSetAttribute((const void*)fused_attn_kernel,
                         cudaFuncAttributeMaxDynamicSharedMemorySize, FA_SMEM);

    // #1 merged weight prep (stacked split + W split + biases)
    {
        long total = (long)CTPG * CC;
        prep_kernel<<<(unsigned)((total + 255) / 256), 256>>>(wt, wp, wg, bt, bp, bg, wW);
    }
    // #2 fused joint + transpose + split (v2: packed stores)
    {
        dim3 grid((NN + 31) / 32, CC / 32, BSZ);
        tsplitX_kernel<<<grid, dim3(32, 8)>>>(x);
    }
    // #3 BN prep (keeps combined conv at launch #4 for ncu)
    bnprep_kernel<<<(CC + 255) / 256, 256>>>(gamma, beta, mean, var, bW);
    // #4 combined theta|phi|g conv (swapped): theta -> bf16 split, phi/g -> pg
    {
        mma128_kernel<6><<<dim3(CTPG / 128, GNTOT / 128, 1), 256, SMEM3>>>(
            p_xhT, p_xlT, p_wstkh, p_wstkl, p_pg, CC, 0, 0L, p_thh, p_thl);
    }
    // #5 pool phi (v2: vectorized) -> phi^T bf16 hi/lo [m][c]
    {
        int tot = BSZ * MM * (CI / 2);
        pool_phi_kernel<<<(tot + 255) / 256, 256>>>();
    }
    // #6 pool g (transpose) -> [c][224] bf16 hi/lo
    {
        dim3 grid(MMP / 32, CI / 32, BSZ);
        pool_g_kernel<<<grid, dim3(32, 8)>>>();
    }
    // #7 fused attention: f -> softmax -> yT hi/lo
    fused_attn_kernel<<<dim3(NBLK, BSZ, 1), 256, FA_SMEM>>>();
    // #8 W conv + BN + residual -> out
    {
        mma128_kernel<2><<<dim3(CC / 128, GNTOT / 128, 1), 256, SMEM3>>>(
            p_wWhi, p_wWlo, p_yhT, p_ylT, out, CI, NN, (long)CC * NN,
            nullptr, nullptr);
    }
}

// round 17
// speedup vs baseline: 1.1958x; 1.0031x over previous
#include <cuda_runtime.h>
#include <cuda_bf16.h>
#include <cstdint>

// ---------------------------------------------------------------------------
// Problem constants
// ---------------------------------------------------------------------------
#define BSZ  32
#define CC   1536
#define CI   768
#define HH   14
#define WW   14
#define HJ   28
#define WJ   28
#define NN   784
#define MM   196
#define MMP  224
#define CTPG 2304
#define GNTOT (BSZ * NN)  // 25088 = 196 * 128

// ---------------------------------------------------------------------------
// Scratch (device globals)
// ---------------------------------------------------------------------------
__device__ __align__(16) __nv_bfloat16 g_xhT[(size_t)BSZ * NN * CC];
__device__ __align__(16) __nv_bfloat16 g_xlT[(size_t)BSZ * NN * CC];
__device__ float g_pg  [(size_t)GNTOT * (2 * CI)];          // [gn][phi(768)|g(768)]
__device__ __align__(16) __nv_bfloat16 g_thh[(size_t)BSZ * NN * CI];
__device__ __align__(16) __nv_bfloat16 g_thl[(size_t)BSZ * NN * CI];
__device__ __align__(16) __nv_bfloat16 g_phh[(size_t)BSZ * MM * CI];
__device__ __align__(16) __nv_bfloat16 g_phl[(size_t)BSZ * MM * CI];
__device__ __align__(16) __nv_bfloat16 g_gph[(size_t)BSZ * CI * MMP];
__device__ __align__(16) __nv_bfloat16 g_gpl[(size_t)BSZ * CI * MMP];
__device__ __align__(16) __nv_bfloat16 g_yhT[(size_t)BSZ * NN * CI];
__device__ __align__(16) __nv_bfloat16 g_ylT[(size_t)BSZ * NN * CI];
__device__ __align__(16) __nv_bfloat16 g_wstkh[(size_t)CTPG * CC];
__device__ __align__(16) __nv_bfloat16 g_wstkl[(size_t)CTPG * CC];
__device__ __align__(16) __nv_bfloat16 g_wWhi[(size_t)CC * CI];
__device__ __align__(16) __nv_bfloat16 g_wWlo[(size_t)CC * CI];
__device__ float g_cbias[CTPG];
__device__ float g_escale[CC];
__device__ float g_eshift[CC];

// ---------------------------------------------------------------------------
// PTX helpers (base ISA only)
// ---------------------------------------------------------------------------
__device__ __forceinline__ uint32_t smem_u32(const void* p) {
    uint32_t a;
    asm("{ .reg .u64 t; cvta.to.shared.u64 t, %1; cvt.u32.u64 %0, t; }" : "=r"(a) : "l"(p));
    return a;
}
__device__ __forceinline__ void ldm_x4(uint32_t* r, uint32_t addr) {
    asm volatile("ldmatrix.sync.aligned.m8n8.x4.shared.b16 {%0,%1,%2,%3}, [%4];"
                 : "=r"(r[0]), "=r"(r[1]), "=r"(r[2]), "=r"(r[3]) : "r"(addr));
}
__device__ __forceinline__ void mma16816(float* d, const uint32_t* a, uint32_t b0, uint32_t b1) {
    asm volatile("mma.sync.aligned.m16n8k16.row.col.f32.bf16.bf16.f32 "
                 "{%0,%1,%2,%3}, {%4,%5,%6,%7}, {%8,%9}, {%0,%1,%2,%3};"
                 : "+f"(d[0]), "+f"(d[1]), "+f"(d[2]), "+f"(d[3])
                 : "r"(a[0]), "r"(a[1]), "r"(a[2]), "r"(a[3]), "r"(b0), "r"(b1));
}
__device__ __forceinline__ void cpa16(uint32_t dst, const void* src, int srcsz) {
    asm volatile("cp.async.cg.shared.global [%0], [%1], 16, %2;"
                 :: "r"(dst), "l"(src), "r"(srcsz));
}
__device__ __forceinline__ void cpa16u(uint32_t dst, const void* src) {
    asm volatile("cp.async.cg.shared.global [%0], [%1], 16;"
                 :: "r"(dst), "l"(src));
}
#define CPA_COMMIT()  asm volatile("cp.async.commit_group;" ::: "memory")
#define CPA_WAIT(n)   asm volatile("cp.async.wait_group %0;" :: "n"(n) : "memory")

__device__ __forceinline__ int swz(int row, int seg) {
    return row * 32 + ((seg ^ ((row >> 1) & 3)) << 3);
}
__device__ __forceinline__ uint32_t pack_bf16x2(float a, float b) {
    __nv_bfloat16 ha = __float2bfloat16(a), hb = __float2bfloat16(b);
    return (uint32_t)(*(uint16_t*)&ha) | ((uint32_t)(*(uint16_t*)&hb) << 16);
}

// ---------------------------------------------------------------------------
// tsplitX v2: joint-gather + transpose + split (packed bf16x2 stores)
// ---------------------------------------------------------------------------
__global__ void tsplitX_kernel(const float* __restrict__ x) {
    __shared__ float t[32][33];        // [c_off][n_off]
    int b = blockIdx.z;
    int c0 = blockIdx.y * 32, n0 = blockIdx.x * 32;
    int tx = threadIdx.x, ty = threadIdx.y;

    int n = n0 + tx;
    long xbase = 0;
    bool okn = n < NN;
    if (okn) {
        int hj = n / WJ, wj = n - hj * WJ;
        int vv = ((hj >= HH) ? 2 : 0) + ((wj >= WW) ? 1 : 0);
        int hl = (hj >= HH) ? hj - HH : hj;
        int wl = (wj >= WW) ? wj - WW : wj;
        xbase = (((long)(b * 4 + vv) * CC) * HH + hl) * WW + wl;
    }
#pragma unroll
    for (int s = 0; s < 32; s += 8) {
        int c = c0 + ty + s;
        t[ty + s][tx] = okn ? x[xbase + (long)c * (HH * WW)] : 0.f;
    }
    __syncthreads();

    int lin = ty * 32 + tx;
    int cp = lin & 15;
    int nr = lin >> 4;
    long ob = (long)b * NN * CC;
#pragma unroll
    for (int s = 0; s < 2; s++) {
        int nn = n0 + nr + s * 16;
        if (nn >= NN) continue;
        float v0 = t[cp * 2][nr + s * 16];
        float v1 = t[cp * 2 + 1][nr + s * 16];
        __nv_bfloat16 h0 = __float2bfloat16(v0);
        __nv_bfloat16 h1 = __float2bfloat16(v1);
        float l0 = v0 - __bfloat162float(h0);
        float l1 = v1 - __bfloat162float(h1);
        long o = ob + (long)nn * CC + c0 + cp * 2;
        *(uint32_t*)(g_xhT + o) =
            (uint32_t)(*(uint16_t*)&h0) | ((uint32_t)(*(uint16_t*)&h1) << 16);
        *(uint32_t*)(g_xlT + o) = pack_bf16x2(l0, l1);
    }
}

// ---------------------------------------------------------------------------
// merged prep: stacked theta|phi|g split + W split + biases + BN fold
// ---------------------------------------------------------------------------
__global__ void prep_kernel(const float* __restrict__ wt, const float* __restrict__ wp,
                            const float* __restrict__ wg, const float* __restrict__ bt,
                            const float* __restrict__ bp, const float* __restrict__ bg,
                            const float* __restrict__ wW,
                            const float* __restrict__ gamma, const float* __restrict__ beta,
                            const float* __restrict__ mean, const float* __restrict__ var,
                            const float* __restrict__ bW) {
    long idx = (long)blockIdx.x * blockDim.x + threadIdx.x;
    if (idx < (long)CTPG * CC) {
        int r = (int)(idx / CC), c = (int)(idx % CC);
        const float* src = (r < CI) ? wt : ((r < 2 * CI) ? wp : wg);
        int rr = (r < CI) ? r : ((r < 2 * CI) ? r - CI : r - 2 * CI);
        float v = src[(long)rr * CC + c];
        __nv_bfloat16 h = __float2bfloat16(v);
        g_wstkh[idx] = h;
        g_wstkl[idx] = __float2bfloat16(v - __bfloat162float(h));
    }
    if (idx < (long)CC * CI) {
        float v = wW[idx];
        __nv_bfloat16 h = __float2bfloat16(v);
        g_wWhi[idx] = h;
        g_wWlo[idx] = __float2bfloat16(v - __bfloat162float(h));
    }
    if (idx < CTPG) {
        int r = (int)idx;
        g_cbias[r] = (r < CI) ? bt[r] : ((r < 2 * CI) ? bp[r - CI] : bg[r - 2 * CI]);
    }
    if (idx < CC) {
        int m = (int)idx;
        float s = gamma[m] * rsqrtf(var[m] + 1e-5f);
        g_escale[m] = s;
        g_eshift[m] = beta[m] - mean[m] * s + bW[m] * s;
    }
}

// ---------------------------------------------------------------------------
// merged pool: blocks [0, POOLG_BLKS) do the g transpose-pool;
// remaining blocks do the flat vectorized phi pool.
// ---------------------------------------------------------------------------
#define POOLG_BLKS (7 * (CI / 32) * BSZ)                 // 5376
#define POOLPHI_BLKS ((BSZ * MM * (CI / 2) + 255) / 256) // 9408
__global__ void pool_kernel() {
    __shared__ float t[32][33];
    int bid = blockIdx.x;
    int tid = threadIdx.x;
    const int LD = 2 * CI;
    if (bid < POOLG_BLKS) {
        int jx = bid % 7;
        int cy = (bid / 7) % (CI / 32);
        int b = bid / (7 * (CI / 32));
        int c0 = cy * 32, j0 = jx * 32;
        int tx = tid & 31, ty = tid >> 5;
#pragma unroll
        for (int s = 0; s < 32; s += 8) {
            int j = j0 + ty + s, c = c0 + tx;
            float v = 0.f;
            if (j < MM) {
                int hm = j / 14, wm = j % 14;
                int n = (2 * hm) * WJ + 2 * wm;
                long base = ((long)b * NN + n) * LD + CI + c;
                v = fmaxf(fmaxf(g_pg[base], g_pg[base + LD]),
                          fmaxf(g_pg[base + WJ * LD], g_pg[base + (WJ + 1) * LD]));
            }
            t[ty + s][tx] = v;
        }
        __syncthreads();
#pragma unroll
        for (int s = 0; s < 32; s += 8) {
            int c = c0 + ty + s, j = j0 + tx;
            float v = t[tx][ty + s];
            __nv_bfloat16 h = __float2bfloat16(v);
            long o = ((long)b * CI + c) * MMP + j;
            g_gph[o] = h;
            g_gpl[o] = (j < MM) ? __float2bfloat16(v - __bfloat162float(h))
                                : __nv_bfloat16(0.f);
        }
    } else {
        int idx = (bid - POOLG_BLKS) * 256 + tid;
        const int CH = CI / 2;
        const int tot = BSZ * MM * CH;
        if (idx >= tot) return;
        int cp = idx % CH;
        int m = (idx / CH) % MM;
        int b = idx / (CH * MM);
        int c = cp * 2;
        int hm = m / 14, wm = m % 14;
        int n = (2 * hm) * WJ + 2 * wm;
        long base = ((long)b * NN + n) * LD + c;
        float2 a0 = *(const float2*)(g_pg + base);
        float2 a1 = *(const float2*)(g_pg + base + LD);
        float2 a2 = *(const float2*)(g_pg + base + WJ * LD);
        float2 a3 = *(const float2*)(g_pg + base + (WJ + 1) * LD);
        float v0 = fmaxf(fmaxf(a0.x, a1.x), fmaxf(a2.x, a3.x));
        float v1 = fmaxf(fmaxf(a0.y, a1.y), fmaxf(a2.y, a3.y));
        __nv_bfloat16 h0 = __float2bfloat16(v0), h1 = __float2bfloat16(v1);
        float l0 = v0 - __bfloat162float(h0), l1 = v1 - __bfloat162float(h1);
        long o = ((long)b * MM + m) * CI + c;
        *(uint32_t*)(g_phh + o) =
            (uint32_t)(*(uint16_t*)&h0) | ((uint32_t)(*(uint16_t*)&h1) << 16);
        *(uint32_t*)(g_phl + o) = pack_bf16x2(l0, l1);
    }
}

// ---------------------------------------------------------------------------
// fused-pass bf16-split tensor GEMM (unchanged core)
//   EPI 2: W conv — BN-fold + residual(xhT+xlT); grid(x=M/128, y=N/128)
//   EPI 6: combined conv (swapped); grid(x=col tiles 18, y=gn tiles 196)
// ---------------------------------------------------------------------------
#define GTILE (128 * 32)
#define ST    (4 * GTILE)
#define SMEM3 (3 * ST * 2)          // 98304 B

template <int EPI>
__global__ void __launch_bounds__(256, 2)
mma128_kernel(const __nv_bfloat16* __restrict__ Ahi, const __nv_bfloat16* __restrict__ Alo,
              const __nv_bfloat16* __restrict__ Bhi, const __nv_bfloat16* __restrict__ Blo,
              float* __restrict__ Cp, int K, int ldC, long sC,
              __nv_bfloat16* __restrict__ Thi, __nv_bfloat16* __restrict__ Tlo) {
    extern __shared__ __align__(16) __nv_bfloat16 smem[];
    constexpr bool MSWAP = (EPI == 6);

    const int tid = threadIdx.x;
    const int lane = tid & 31;
    const int wid = tid >> 5;
    const int wm = wid & 1;
    const int wn = wid >> 1;
    const int m0 = (MSWAP ? blockIdx.y : blockIdx.x) * 128;
    const int n0 = (MSWAP ? blockIdx.x : blockIdx.y) * 128;

    const int NK = K / 32;
    const __nv_bfloat16* A0 = Ahi + (long)m0 * K;
    const __nv_bfloat16* A1 = Alo + (long)m0 * K;

    float acc[4][4][4];
#pragma unroll
    for (int i = 0; i < 4; i++)
#pragma unroll
        for (int j = 0; j < 4; j++)
#pragma unroll
            for (int r = 0; r < 4; r++) acc[i][j][r] = 0.f;

    auto loadChunk = [&](int g, int stage) {
        long kc = (long)g * 32;
        __nv_bfloat16* st = smem + stage * ST;
#pragma unroll
        for (int i = 0; i < 2; i++) {
            int idx = tid + i * 256;
            int row = idx >> 2, seg = idx & 3;
            int off = swz(row, seg);
            long ga = (long)row * K + kc + seg * 8;
            long gb = (long)(n0 + row) * K + kc + seg * 8;
            cpa16u(smem_u32(st + off), A0 + ga);
            cpa16u(smem_u32(st + GTILE + off), Bhi + gb);
            cpa16u(smem_u32(st + 2 * GTILE + off), A1 + ga);
            cpa16u(smem_u32(st + 3 * GTILE + off), Blo + gb);
        }
    };

    loadChunk(0, 0); CPA_COMMIT();
    loadChunk(1, 1); CPA_COMMIT();

    int cs = 0, ls = 2;
    for (int g = 0; g < NK; g++) {
        if (g + 1 < NK) { CPA_WAIT(1); } else { CPA_WAIT(0); }
        __syncthreads();
        if (g + 2 < NK) {
            loadChunk(g + 2, ls);
            CPA_COMMIT();
            ls = (ls == 2) ? 0 : ls + 1;
        }
        const __nv_bfloat16* st = smem + cs * ST;
        cs = (cs == 2) ? 0 : cs + 1;

#pragma unroll
        for (int ks = 0; ks < 2; ks++) {
            const int aRow = wm * 64 + ((lane >> 3) & 1) * 8 + (lane & 7);
            const int aSeg = ks * 2 + (lane >> 4);
            const int bRow = wn * 32 + (lane >> 4) * 8 + (lane & 7);
            const int bSeg = ks * 2 + ((lane >> 3) & 1);

            uint32_t bh[2][4];
#pragma unroll
            for (int ni = 0; ni < 2; ni++)
                ldm_x4(bh[ni], smem_u32(st + GTILE + swz(bRow + ni * 16, bSeg)));
            uint32_t a[4][4];
#pragma unroll
            for (int mi = 0; mi < 4; mi++)
                ldm_x4(a[mi], smem_u32(st + swz(aRow + mi * 16, aSeg)));
#pragma unroll
            for (int mi = 0; mi < 4; mi++)
#pragma unroll
                for (int nj = 0; nj < 4; nj++)
                    mma16816(acc[mi][nj], a[mi],
                             bh[nj >> 1][(nj & 1) * 2], bh[nj >> 1][(nj & 1) * 2 + 1]);
            uint32_t bl[2][4];
#pragma unroll
            for (int ni = 0; ni < 2; ni++)
                ldm_x4(bl[ni], smem_u32(st + 3 * GTILE + swz(bRow + ni * 16, bSeg)));
#pragma unroll
            for (int mi = 0; mi < 4; mi++)
#pragma unroll
                for (int nj = 0; nj < 4; nj++)
                    mma16816(acc[mi][nj], a[mi],
                             bl[nj >> 1][(nj & 1) * 2], bl[nj >> 1][(nj & 1) * 2 + 1]);
#pragma unroll
            for (int mi = 0; mi < 4; mi++)
                ldm_x4(a[mi], smem_u32(st + 2 * GTILE + swz(aRow + mi * 16, aSeg)));
#pragma unroll
            for (int mi = 0; mi < 4; mi++)
#pragma unroll
                for (int nj = 0; nj < 4; nj++)
                    mma16816(acc[mi][nj], a[mi],
                             bh[nj >> 1][(nj & 1) * 2], bh[nj >> 1][(nj & 1) * 2 + 1]);
        }
    }

    const int mbase = m0 + wm * 64;
    const int nbase = n0 + wn * 32;
#pragma unroll
    for (int mi = 0; mi < 4; mi++) {
        int mr0 = mbase + mi * 16 + (lane >> 2);
        int mr1 = mr0 + 8;
        float es0 = 1.f, eh0 = 0.f, es1 = 1.f, eh1 = 0.f;
        if (EPI == 2) {
            es0 = g_escale[mr0]; eh0 = g_eshift[mr0];
            es1 = g_escale[mr1]; eh1 = g_eshift[mr1];
        }
#pragma unroll
        for (int nj = 0; nj < 4; nj++) {
            int n = nbase + nj * 8 + (lane & 3) * 2;
            float2 v0 = make_float2(acc[mi][nj][0], acc[mi][nj][1]);
            float2 v1 = make_float2(acc[mi][nj][2], acc[mi][nj][3]);
            if (EPI == 2) {
                int bcol = n / NN;
                int nl = n - bcol * NN;
                float* Cb = Cp + (long)bcol * sC;
#pragma unroll
                for (int e = 0; e < 2; e++) {
                    long rbase = (long)(n + e) * CC;
                    float r0 = __bfloat162float(g_xhT[rbase + mr0]) +
                               __bfloat162float(g_xlT[rbase + mr0]);
                    float r1 = __bfloat162float(g_xhT[rbase + mr1]) +
                               __bfloat162float(g_xlT[rbase + mr1]);
                    if (e == 0) { v0.x = v0.x * es0 + eh0 + r0; v1.x = v1.x * es1 + eh1 + r1; }
                    else        { v0.y = v0.y * es0 + eh0 + r0; v1.y = v1.y * es1 + eh1 + r1; }
                }
                *(float2*)(Cb + (long)mr0 * ldC + nl) = v0;
                *(float2*)(Cb + (long)mr1 * ldC + nl) = v1;
            } else {   // EPI == 6
                float b0 = g_cbias[n], b1 = g_cbias[n + 1];
                v0.x += b0; v0.y += b1; v1.x += b0; v1.y += b1;
                if (n0 < CI) {   // theta tile -> bf16 hi/lo
                    __nv_bfloat16 h;
                    h = __float2bfloat16(v0.x);
                    float l0x = v0.x - __bfloat162float(h); float h0x = __bfloat162float(h);
                    h = __float2bfloat16(v0.y);
                    float l0y = v0.y - __bfloat162float(h); float h0y = __bfloat162float(h);
                    h = __float2bfloat16(v1.x);
                    float l1x = v1.x - __bfloat162float(h); float h1x = __bfloat162float(h);
                    h = __float2bfloat16(v1.y);
                    float l1y = v1.y - __bfloat162float(h); float h1y = __bfloat162float(h);
                    *(uint32_t*)(Thi + (long)mr0 * CI + n) = pack_bf16x2(h0x, h0y);
                    *(uint32_t*)(Tlo + (long)mr0 * CI + n) = pack_bf16x2(l0x, l0y);
                    *(uint32_t*)(Thi + (long)mr1 * CI + n) = pack_bf16x2(h1x, h1y);
                    *(uint32_t*)(Tlo + (long)mr1 * CI + n) = pack_bf16x2(l1x, l1y);
                } else {         // phi/g tile -> fp32 to pg[gn][n-768]
                    int pc = n - CI;
                    *(float2*)(Cp + (long)mr0 * (2 * CI) + pc) = v0;
                    *(float2*)(Cp + (long)mr1 * (2 * CI) + pc) = v1;
                }
            }
        }
    }
}

// ---------------------------------------------------------------------------
// Fused attention kernel (stage-C prefetch reordered after the barrier:
// removes the cross-warp smem race present since R13)
// ---------------------------------------------------------------------------
#define FA_SMEM 99328
#define NBLK 13

__global__ void __launch_bounds__(256, 2)
fused_attn_kernel() {
    extern __shared__ __align__(16) __nv_bfloat16 smem[];
    const int tid = threadIdx.x;
    const int lane = tid & 31;
    const int wid = tid >> 5;
    const int wm = wid & 1;
    const int wn = wid >> 1;
    const int n0 = blockIdx.x * 64;
    const int b = blockIdx.y;

    const __nv_bfloat16* Ah = g_thh + ((long)b * NN + n0) * CI;
    const __nv_bfloat16* Al = g_thl + ((long)b * NN + n0) * CI;
    const __nv_bfloat16* Bh = g_phh + (long)b * MM * CI;
    const __nv_bfloat16* Bl = g_phl + (long)b * MM * CI;

    float acc[2][8][4];
#pragma unroll
    for (int i = 0; i < 2; i++)
#pragma unroll
        for (int j = 0; j < 8; j++)
#pragma unroll
            for (int r = 0; r < 4; r++) acc[i][j][r] = 0.f;

    auto loadA = [&](int g, int buf) {
        long kc = (long)g * 32;
        __nv_bfloat16* st = smem + buf * 20480;
        {
            int row = tid >> 2, seg = tid & 3;
            int off = swz(row, seg);
            int ok = (n0 + row) < NN;
            long ga = (long)row * CI + kc + seg * 8;
            cpa16(smem_u32(st + off), Ah + ga, ok ? 16 : 0);
            cpa16(smem_u32(st + 10240 + off), Al + ga, ok ? 16 : 0);
        }
#pragma unroll
        for (int i = 0; i < 4; i++) {
            int idx = tid + i * 256;
            int row = idx >> 2, seg = idx & 3;
            int off = swz(row, seg);
            int ok = row < MM;
            long gb = (long)row * CI + kc + seg * 8;
            cpa16(smem_u32(st + 2048 + off), Bh + gb, ok ? 16 : 0);
            cpa16(smem_u32(st + 12288 + off), Bl + gb, ok ? 16 : 0);
        }
    };

    loadA(0, 0); CPA_COMMIT();
    const int NKA = CI / 32;
    for (int g = 0; g < NKA; g++) {
        int buf = g & 1;
        if (g + 1 < NKA) { loadA(g + 1, buf ^ 1); CPA_COMMIT(); CPA_WAIT(1); }
        else { CPA_WAIT(0); }
        __syncthreads();
        const __nv_bfloat16* st = smem + buf * 20480;
#pragma unroll
        for (int ks = 0; ks < 2; ks++) {
            const int aRow = wm * 32 + ((lane >> 3) & 1) * 8 + (lane & 7);
            const int aSeg = ks * 2 + (lane >> 4);
            const int bRow = wn * 64 + (lane >> 4) * 8 + (lane & 7);
            const int bSeg = ks * 2 + ((lane >> 3) & 1);

            uint32_t a[2][4], b4[4][4];
#pragma unroll
            for (int mi = 0; mi < 2; mi++)
                ldm_x4(a[mi], smem_u32(st + swz(aRow + mi * 16, aSeg)));
#pragma unroll
            for (int ng = 0; ng < 4; ng++)
                ldm_x4(b4[ng], smem_u32(st + 2048 + swz(bRow + ng * 16, bSeg)));
#pragma unroll
            for (int mi = 0; mi < 2; mi++)
#pragma unroll
                for (int nj = 0; nj < 8; nj++)
                    mma16816(acc[mi][nj], a[mi],
                             b4[nj >> 1][(nj & 1) * 2], b4[nj >> 1][(nj & 1) * 2 + 1]);
#pragma unroll
            for (int mi = 0; mi < 2; mi++)
                ldm_x4(a[mi], smem_u32(st + 10240 + swz(aRow + mi * 16, aSeg)));
#pragma unroll
            for (int mi = 0; mi < 2; mi++)
#pragma unroll
                for (int nj = 0; nj < 8; nj++)
                    mma16816(acc[mi][nj], a[mi],
                             b4[nj >> 1][(nj & 1) * 2], b4[nj >> 1][(nj & 1) * 2 + 1]);
#pragma unroll
            for (int mi = 0; mi < 2; mi++)
                ldm_x4(a[mi], smem_u32(st + swz(aRow + mi * 16, aSeg)));
#pragma unroll
            for (int ng = 0; ng < 4; ng++)
                ldm_x4(b4[ng], smem_u32(st + 12288 + swz(bRow + ng * 16, bSeg)));
#pragma unroll
            for (int mi = 0; mi < 2; mi++)
#pragma unroll
                for (int nj = 0; nj < 8; nj++)
                    mma16816(acc[mi][nj], a[mi],
                             b4[nj >> 1][(nj & 1) * 2], b4[nj >> 1][(nj & 1) * 2 + 1]);
        }
        __syncthreads();
    }

    __nv_bfloat16* attnHi = smem;
    __nv_bfloat16* attnLo = smem + 16384;
    __nv_bfloat16* pipeC  = smem + 32768;
    float* red = (float*)(smem + 49152);

    const __nv_bfloat16* Gh = g_gph + (long)b * CI * MMP;
    const __nv_bfloat16* Gl = g_gpl + (long)b * CI * MMP;

    auto loadC = [&](int q, int buf) {
        int nt = q / 7, k = q - nt * 7;
        __nv_bfloat16* st = pipeC + buf * 8192;
        long kc = (long)k * 32;
#pragma unroll
        for (int i = 0; i < 2; i++) {
            int idx = tid + i * 256;
            int row = idx >> 2, seg = idx & 3;
            int off = swz(row, seg);
            long gb = (long)(nt * 128 + row) * MMP + kc + seg * 8;
            cpa16u(smem_u32(st + off), Gh + gb);
            cpa16u(smem_u32(st + 4096 + off), Gl + gb);
        }
    };
    loadC(0, 0); CPA_COMMIT();

    float rowmax[2][2], rowinv[2][2];
#pragma unroll
    for (int mi = 0; mi < 2; mi++)
#pragma unroll
        for (int rh = 0; rh < 2; rh++) {
            int r = wm * 32 + mi * 16 + (lane >> 2) + rh * 8;
            float m = -1e30f;
#pragma unroll
            for (int nj = 0; nj < 8; nj++)
#pragma unroll
                for (int e = 0; e < 2; e++) {
                    int col = wn * 64 + nj * 8 + (lane & 3) * 2 + e;
                    float v = acc[mi][nj][rh * 2 + e];
                    if (col >= MM) { v = -1e30f; acc[mi][nj][rh * 2 + e] = v; }
                    m = fmaxf(m, v);
                }
            m = fmaxf(m, __shfl_xor_sync(0xffffffffu, m, 1));
            m = fmaxf(m, __shfl_xor_sync(0xffffffffu, m, 2));
            if ((lane & 3) == 0) red[r * 4 + wn] = m;
        }
    __syncthreads();
#pragma unroll
    for (int mi = 0; mi < 2; mi++)
#pragma unroll
        for (int rh = 0; rh < 2; rh++) {
            int r = wm * 32 + mi * 16 + (lane >> 2) + rh * 8;
            rowmax[mi][rh] = fmaxf(fmaxf(red[r * 4], red[r * 4 + 1]),
                                   fmaxf(red[r * 4 + 2], red[r * 4 + 3]));
        }
    __syncthreads();
#pragma unroll
    for (int mi = 0; mi < 2; mi++)
#pragma unroll
        for (int rh = 0; rh < 2; rh++) {
            int r = wm * 32 + mi * 16 + (lane >> 2) + rh * 8;
            float s = 0.f;
#pragma unroll
            for (int nj = 0; nj < 8; nj++)
#pragma unroll
                for (int e = 0; e < 2; e++) {
                    float v = __expf(acc[mi][nj][rh * 2 + e] - rowmax[mi][rh]);
                    acc[mi][nj][rh * 2 + e] = v;
                    s += v;
                }
            s += __shfl_xor_sync(0xffffffffu, s, 1);
            s += __shfl_xor_sync(0xffffffffu, s, 2);
            if ((lane & 3) == 0) red[r * 4 + wn] = s;
        }
    __syncthreads();
#pragma unroll
    for (int mi = 0; mi < 2; mi++)
#pragma unroll
        for (int rh = 0; rh < 2; rh++) {
            int r = wm * 32 + mi * 16 + (lane >> 2) + rh * 8;
            rowinv[mi][rh] = 1.f / (red[r * 4] + red[r * 4 + 1] +
                                    red[r * 4 + 2] + red[r * 4 + 3]);
        }
#pragma unroll
    for (int mi = 0; mi < 2; mi++)
#pragma unroll
        for (int rh = 0; rh < 2; rh++) {
            int r = wm * 32 + mi * 16 + (lane >> 2) + rh * 8;
#pragma unroll
            for (int nj = 0; nj < 8; nj++) {
                int col = wn * 64 + nj * 8 + (lane & 3) * 2;
                if (col >= MMP) continue;
                float v0 = acc[mi][nj][rh * 2] * rowinv[mi][rh];
                float v1 = acc[mi][nj][rh * 2 + 1] * rowinv[mi][rh];
                __nv_bfloat16 h0 = __float2bfloat16(v0);
                __nv_bfloat16 h1 = __float2bfloat16(v1);
                float l0 = v0 - __bfloat162float(h0);
                float l1 = v1 - __bfloat162float(h1);
                int k = col >> 5, kc = col & 31;
                int off = swz(r, kc >> 3) + (kc & 7);
                *(uint32_t*)(attnHi + k * 2048 + off) =
                    (uint32_t)(*(uint16_t*)&h0) | ((uint32_t)(*(uint16_t*)&h1) << 16);
                *(uint32_t*)(attnLo + k * 2048 + off) = pack_bf16x2(l0, l1);
            }
        }
    __syncthreads();

    float acc2[2][4][4];
    const int QT = 6 * 7;
    for (int q = 0; q < QT; q++) {
        int nt = q / 7, k = q - nt * 7;
        if (k == 0) {
#pragma unroll
            for (int i = 0; i < 2; i++)
#pragma unroll
                for (int j = 0; j < 4; j++)
#pragma unroll
                    for (int r = 0; r < 4; r++) acc2[i][j][r] = 0.f;
        }
        int buf = q & 1;
        // wait for loadC(q), barrier, THEN issue loadC(q+1): no cross-warp race
        CPA_WAIT(0);
        __syncthreads();
        if (q + 1 < QT) { loadC(q + 1, buf ^ 1); CPA_COMMIT(); }
        const __nv_bfloat16* st = pipeC + buf * 8192;
#pragma unroll
        for (int ks = 0; ks < 2; ks++) {
            const int aRow = wm * 32 + ((lane >> 3) & 1) * 8 + (lane & 7);
            const int aSeg = ks * 2 + (lane >> 4);
            const int bRow = wn * 32 + (lane >> 4) * 8 + (lane & 7);
            const int bSeg = ks * 2 + ((lane >> 3) & 1);

            uint32_t a[2][4], bb[2][4];
#pragma unroll
            for (int mi = 0; mi < 2; mi++)
                ldm_x4(a[mi], smem_u32(attnHi + k * 2048 + swz(aRow + mi * 16, aSeg)));
#pragma unroll
            for (int ni = 0; ni < 2; ni++)
                ldm_x4(bb[ni], smem_u32(st + swz(bRow + ni * 16, bSeg)));
#pragma unroll
            for (int mi = 0; mi < 2; mi++)
#pragma unroll
                for (int nj = 0; nj < 4; nj++)
                    mma16816(acc2[mi][nj], a[mi],
                             bb[nj >> 1][(nj & 1) * 2], bb[nj >> 1][(nj & 1) * 2 + 1]);
#pragma unroll
            for (int mi = 0; mi < 2; mi++)
                ldm_x4(a[mi], smem_u32(attnLo + k * 2048 + swz(aRow + mi * 16, aSeg)));
#pragma unroll
            for (int mi = 0; mi < 2; mi++)
#pragma unroll
                for (int nj = 0; nj < 4; nj++)
                    mma16816(acc2[mi][nj], a[mi],
                             bb[nj >> 1][(nj & 1) * 2], bb[nj >> 1][(nj & 1) * 2 + 1]);
#pragma unroll
            for (int mi = 0; mi < 2; mi++)
                ldm_x4(a[mi], smem_u32(attnHi + k * 2048 + swz(aRow + mi * 16, aSeg)));
#pragma unroll
            for (int ni = 0; ni < 2; ni++)
                ldm_x4(bb[ni], smem_u32(st + 4096 + swz(bRow + ni * 16, bSeg)));
#pragma unroll
            for (int mi = 0; mi < 2; mi++)
#pragma unroll
                for (int nj = 0; nj < 4; nj++)
                    mma16816(acc2[mi][nj], a[mi],
                             bb[nj >> 1][(nj & 1) * 2], bb[nj >> 1][(nj & 1) * 2 + 1]);
        }
        if (k == 6) {
#pragma unroll
            for (int mi = 0; mi < 2; mi++) {
                int r0 = wm * 32 + mi * 16 + (lane >> 2);
                int r1 = r0 + 8;
                int nn0 = n0 + r0, nn1 = n0 + r1;
#pragma unroll
                for (int nj = 0; nj < 4; nj++) {
                    int c = nt * 128 + wn * 32 + nj * 8 + (lane & 3) * 2;
#pragma unroll
                    for (int half = 0; half < 2; half++) {
                        int nn = half ? nn1 : nn0;
                        if (nn >= NN) continue;
                        float v0 = acc2[mi][nj][half * 2];
                        float v1 = acc2[mi][nj][half * 2 + 1];
                        __nv_bfloat16 h0 = __float2bfloat16(v0);
                        __nv_bfloat16 h1 = __float2bfloat16(v1);
                        float l0 = v0 - __bfloat162float(h0);
                        float l1 = v1 - __bfloat162float(h1);
                        long obase = ((long)b * NN + nn) * CI + c;
                        *(uint32_t*)(g_yhT + obase) =
                            (uint32_t)(*(uint16_t*)&h0) | ((uint32_t)(*(uint16_t*)&h1) << 16);
                        *(uint32_t*)(g_ylT + obase) = pack_bf16x2(l0, l1);
                    }
                }
            }
        }
    }
}

// ---------------------------------------------------------------------------
// Launch
// ---------------------------------------------------------------------------
extern "C" void kernel_launch(void* const* d_in, const int* in_sizes, int n_in,
                              void* d_out, int out_size) {
    const float* x     = (const float*)d_in[0];
    const float* wt    = (const float*)d_in[1];
    const float* bt    = (const float*)d_in[2];
    const float* wp    = (const float*)d_in[3];
    const float* bp    = (const float*)d_in[4];
    const float* wg    = (const float*)d_in[5];
    const float* bg    = (const float*)d_in[6];
    const float* wW    = (const float*)d_in[7];
    const float* bW    = (const float*)d_in[8];
    const float* gamma = (const float*)d_in[9];
    const float* beta  = (const float*)d_in[10];
    const float* mean  = (const float*)d_in[11];
    const float* var   = (const float*)d_in[12];
    float* out = (float*)d_out;

    float *p_pg;
    __nv_bfloat16 *p_xhT, *p_xlT, *p_thh, *p_thl, *p_yhT, *p_ylT;
    __nv_bfloat16 *p_wstkh, *p_wstkl, *p_wWhi, *p_wWlo;
    cudaGetSymbolAddress((void**)&p_pg, g_pg);
    cudaGetSymbolAddress((void**)&p_xhT, g_xhT);
    cudaGetSymbolAddress((void**)&p_xlT, g_xlT);
    cudaGetSymbolAddress((void**)&p_thh, g_thh);
    cudaGetSymbolAddress((void**)&p_thl, g_thl);
    cudaGetSymbolAddress((void**)&p_yhT, g_yhT);
    cudaGetSymbolAddress((void**)&p_ylT, g_ylT);
    cudaGetSymbolAddress((void**)&p_wstkh, g_wstkh);
    cudaGetSymbolAddress((void**)&p_wstkl, g_wstkl);
    cudaGetSymbolAddress((void**)&p_wWhi, g_wWhi);
    cudaGetSymbolAddress((void**)&p_wWlo, g_wWlo);

    cudaFuncSetAttribute((const void*)mma128_kernel<2>,
                         cudaFuncAttributeMaxDynamicSharedMemorySize, SMEM3);
    cudaFuncSetAttribute((const void*)mma128_kernel<6>,
                         cudaFuncAttributeMaxDynamicSharedMemorySize, SMEM3);
    cudaFuncSetAttribute((const void*)fused_attn_kernel,
                         cudaFuncAttributeMaxDynamicSharedMemorySize, FA_SMEM);

    // #1 merged prep (stacked split + W split + biases + BN fold)
    {
        long total = (long)CTPG * CC;
        prep_kernel<<<(unsigned)((total + 255) / 256), 256>>>(
            wt, wp, wg, bt, bp, bg, wW, gamma, beta, mean, var, bW);
    }
    // #2 fused joint + transpose + split
    {
        dim3 grid((NN + 31) / 32, CC / 32, BSZ);
        tsplitX_kernel<<<grid, dim3(32, 8)>>>(x);
    }
    // #3 combined theta|phi|g conv (swapped): theta -> bf16 split, phi/g -> pg
    {
        mma128_kernel<6><<<dim3(CTPG / 128, GNTOT / 128, 1), 256, SMEM3>>>(
            p_xhT, p_xlT, p_wstkh, p_wstkl, p_pg, CC, 0, 0L, p_thh, p_thl);
    }
    // #4 merged pool (g transpose-pool + phi pool)
    {
        int blocks = POOLG_BLKS + POOLPHI_BLKS;
        pool_kernel<<<blocks, 256>>>();
    }
    // #5 fused attention: f -> softmax -> yT hi/lo
    fused_attn_kernel<<<dim3(NBLK, BSZ, 1), 256, FA_SMEM>>>();
    // #6 W conv + BN + residual -> out
    {
        mma128_kernel<2><<<dim3(CC / 128, GNTOT / 128, 1), 256, SMEM3>>>(
            p_wWhi, p_wWlo, p_yhT, p_ylT, out, CI, NN, (long)CC * NN,
            nullptr, nullptr);
    }
}